// round 1
// baseline (speedup 1.0000x reference)
#include <cuda_runtime.h>
#include <math.h>

#define BB 8
#define TT 24
#define NNODES 2048
#define CDIM 64
#define HH 8
#define HDIM 8
#define SWAV 4
#define BT (BB*TT)              // 192
#define ROWS ((long)BT*NNODES)  // 393216

// ---------------- scratch (static device globals; no allocation) ----------------
__device__ float g_sphi[SWAV*NNODES*NNODES];   // phi * diag_w
__device__ float g_msum[NNODES*NNODES];
__device__ float g_xk  [BT*NNODES*CDIM];
__device__ float g_qkv [BT*NNODES*3*CDIM];
__device__ float g_cat [BT*NNODES*2*CDIM];
__device__ float g_att0[BT*NNODES*CDIM];
__device__ float g_att1[BT*NNODES*CDIM];
__device__ float g_p0  [BT*NNODES*CDIM];
__device__ float g_p1  [BT*NNODES*CDIM];
__device__ float g_y   [BT*NNODES*CDIM];
__device__ float g_hid [BT*NNODES*2*CDIM];
__device__ float g_h2  [BT*NNODES*CDIM];

// ---------------- elementwise: scaledPhi[s,i,j] = phi[s,i,j]*diag_w[s,j] ----------------
__global__ void scale_phi_kernel(const float* __restrict__ phi,
                                 const float* __restrict__ diagw,
                                 float* __restrict__ out)
{
    long idx = (long)blockIdx.x * blockDim.x + threadIdx.x;
    long total = (long)SWAV * NNODES * NNODES;
    if (idx >= total) return;
    int s = (int)(idx / ((long)NNODES * NNODES));
    int j = (int)(idx % NNODES);
    out[idx] = phi[idx] * diagw[s * NNODES + j];
}

// ---------------- generic register-tiled fp32 GEMM ----------------
// C[m,n] = sum_k A[m,k] * B[k,n]   (B from W[n,k] when TRANSB)
// optional bias[n], optional accumulate into C, optional ReLU.
template<int BM,int BN,int BK,int TM,int TN,bool TRANSB,bool RELU>
__global__ __launch_bounds__((BM/TM)*(BN/TN))
void gemm_k(const float* __restrict__ A, const float* __restrict__ B,
            float* __restrict__ C, const float* __restrict__ bias,
            int K, int lda, int ldb, int ldc,
            long sA, long sB, long sC, int accumulate)
{
    constexpr int TX = BN / TN;
    constexpr int TY = BM / TM;
    constexpr int THREADS = TX * TY;
    __shared__ float As[BK][BM];
    __shared__ float Bs[BK][BN];

    const int tid = threadIdx.x;
    const int tx  = tid % TX;
    const int ty  = tid / TX;
    const long m0 = (long)blockIdx.y * BM;
    const int  n0 = blockIdx.x * BN;

    A += (long)blockIdx.z * sA;
    B += (long)blockIdx.z * sB;
    C += (long)blockIdx.z * sC;

    float acc[TM][TN];
#pragma unroll
    for (int i = 0; i < TM; i++)
#pragma unroll
        for (int j = 0; j < TN; j++) acc[i][j] = 0.f;

    for (int k0 = 0; k0 < K; k0 += BK) {
        // load A tile (BM x BK), store transposed As[k][m]
#pragma unroll
        for (int i = tid; i < BM * BK / 4; i += THREADS) {
            int r = i / (BK / 4);
            int c = i % (BK / 4);
            const float4 v = *(const float4*)&A[(m0 + r) * (long)lda + k0 + c * 4];
            As[c*4+0][r] = v.x; As[c*4+1][r] = v.y;
            As[c*4+2][r] = v.z; As[c*4+3][r] = v.w;
        }
        if (!TRANSB) {
#pragma unroll
            for (int i = tid; i < BK * BN / 4; i += THREADS) {
                int r = i / (BN / 4);
                int c = i % (BN / 4);
                *(float4*)&Bs[r][c*4] =
                    *(const float4*)&B[(long)(k0 + r) * ldb + n0 + c * 4];
            }
        } else {
#pragma unroll
            for (int i = tid; i < BN * BK / 4; i += THREADS) {
                int r = i / (BK / 4);      // n index
                int c = i % (BK / 4);
                const float4 v = *(const float4*)&B[(long)(n0 + r) * ldb + k0 + c * 4];
                Bs[c*4+0][r] = v.x; Bs[c*4+1][r] = v.y;
                Bs[c*4+2][r] = v.z; Bs[c*4+3][r] = v.w;
            }
        }
        __syncthreads();
#pragma unroll
        for (int k = 0; k < BK; k++) {
            float ra[TM], rb[TN];
#pragma unroll
            for (int i = 0; i < TM; i += 4)
                *(float4*)&ra[i] = *(const float4*)&As[k][ty * TM + i];
#pragma unroll
            for (int j = 0; j < TN; j += 4)
                *(float4*)&rb[j] = *(const float4*)&Bs[k][tx * TN + j];
#pragma unroll
            for (int i = 0; i < TM; i++)
#pragma unroll
                for (int j = 0; j < TN; j++)
                    acc[i][j] = fmaf(ra[i], rb[j], acc[i][j]);
        }
        __syncthreads();
    }
#pragma unroll
    for (int i = 0; i < TM; i++) {
#pragma unroll
        for (int j = 0; j < TN; j++) {
            int n = n0 + tx * TN + j;
            long idx = (m0 + ty * TM + i) * (long)ldc + n;
            float v = acc[i][j];
            if (bias) v += bias[n];
            if (accumulate) v += C[idx];
            if (RELU) v = fmaxf(v, 0.f);
            C[idx] = v;
        }
    }
}

// ---------------- linear attention, spatial (attend over N=2048) ----------------
// one block per (bt, head), 256 threads. qkv row layout: [q(64) k(64) v(64)].
__global__ __launch_bounds__(256)
void attn_spatial(const float* __restrict__ qkv, float* __restrict__ cat)
{
    const int bt = blockIdx.x;
    const int h  = blockIdx.y;
    const int tid = threadIdx.x;
    const int lane = tid & 31;
    const int warp = tid >> 5;
    const float* base = qkv + (long)bt * NNODES * 192;

    float kvs[HDIM][HDIM];
    float ksum[HDIM];
#pragma unroll
    for (int m = 0; m < HDIM; m++) {
        ksum[m] = 0.f;
#pragma unroll
        for (int d = 0; d < HDIM; d++) kvs[m][d] = 0.f;
    }

    for (int n = tid; n < NNODES; n += 256) {
        const float* pk = base + (long)n * 192 + 64 + h * 8;
        const float* pv = base + (long)n * 192 + 128 + h * 8;
        float kk[HDIM], vv[HDIM];
        float s = 0.f;
#pragma unroll
        for (int m = 0; m < HDIM; m++) { kk[m] = pk[m]; s += kk[m] * kk[m]; }
#pragma unroll
        for (int d = 0; d < HDIM; d++) vv[d] = pv[d];
        float inv = 1.f / fmaxf(sqrtf(s), 1e-12f);
#pragma unroll
        for (int m = 0; m < HDIM; m++) {
            float km = kk[m] * inv;
            ksum[m] += km;
#pragma unroll
            for (int d = 0; d < HDIM; d++) kvs[m][d] = fmaf(km, vv[d], kvs[m][d]);
        }
    }

    __shared__ float red[8][72];
    __shared__ float fin[72];
#pragma unroll
    for (int m = 0; m < HDIM; m++) {
#pragma unroll
        for (int d = 0; d < HDIM; d++) {
            float v = kvs[m][d];
#pragma unroll
            for (int o = 16; o; o >>= 1) v += __shfl_down_sync(0xffffffffu, v, o);
            if (lane == 0) red[warp][m * 8 + d] = v;
        }
        float v = ksum[m];
#pragma unroll
        for (int o = 16; o; o >>= 1) v += __shfl_down_sync(0xffffffffu, v, o);
        if (lane == 0) red[warp][64 + m] = v;
    }
    __syncthreads();
    if (tid < 72) {
        float s = 0.f;
#pragma unroll
        for (int w = 0; w < 8; w++) s += red[w][tid];
        fin[tid] = s;
    }
    __syncthreads();

    float fkvs[HDIM][HDIM], fksum[HDIM];
#pragma unroll
    for (int m = 0; m < HDIM; m++) {
        fksum[m] = fin[64 + m];
#pragma unroll
        for (int d = 0; d < HDIM; d++) fkvs[m][d] = fin[m * 8 + d];
    }

    for (int n = tid; n < NNODES; n += 256) {
        const float* pq = base + (long)n * 192 + h * 8;
        const float* pv = base + (long)n * 192 + 128 + h * 8;
        float qq[HDIM], vv[HDIM];
        float s = 0.f;
#pragma unroll
        for (int m = 0; m < HDIM; m++) { qq[m] = pq[m]; s += qq[m] * qq[m]; }
#pragma unroll
        for (int d = 0; d < HDIM; d++) vv[d] = pv[d];
        float inv = 1.f / fmaxf(sqrtf(s), 1e-12f);
        float den = (float)NNODES;
#pragma unroll
        for (int m = 0; m < HDIM; m++) { qq[m] *= inv; den = fmaf(qq[m], fksum[m], den); }
        float invden = 1.f / fmaxf(den, 1e-5f);
        float* out = cat + ((long)bt * NNODES + n) * 128 + h * 8;
#pragma unroll
        for (int d = 0; d < HDIM; d++) {
            float num = (float)NNODES * vv[d];
#pragma unroll
            for (int m = 0; m < HDIM; m++) num = fmaf(qq[m], fkvs[m][d], num);
            out[d] = num * invden;
        }
    }
}

// ---------------- linear attention, temporal (attend over T=24) ----------------
// one thread per (b, n, head): L=24 handled serially in registers.
__global__ __launch_bounds__(256)
void attn_temporal(const float* __restrict__ qkv, float* __restrict__ cat)
{
    int t = blockIdx.x * blockDim.x + threadIdx.x;
    if (t >= BB * NNODES * HH) return;
    const int h = t & 7;
    const int n = (t >> 3) & (NNODES - 1);
    const int b = t >> 14;  // /(8*2048)

    float kvs[HDIM][HDIM];
    float ksum[HDIM];
#pragma unroll
    for (int m = 0; m < HDIM; m++) {
        ksum[m] = 0.f;
#pragma unroll
        for (int d = 0; d < HDIM; d++) kvs[m][d] = 0.f;
    }

    for (int l = 0; l < TT; l++) {
        const float* p = qkv + (((long)(b * TT + l)) * NNODES + n) * 192;
        float kk[HDIM], vv[HDIM];
        float s = 0.f;
#pragma unroll
        for (int m = 0; m < HDIM; m++) { kk[m] = p[64 + h * 8 + m]; s += kk[m] * kk[m]; }
#pragma unroll
        for (int d = 0; d < HDIM; d++) vv[d] = p[128 + h * 8 + d];
        float inv = 1.f / fmaxf(sqrtf(s), 1e-12f);
#pragma unroll
        for (int m = 0; m < HDIM; m++) {
            float km = kk[m] * inv;
            ksum[m] += km;
#pragma unroll
            for (int d = 0; d < HDIM; d++) kvs[m][d] = fmaf(km, vv[d], kvs[m][d]);
        }
    }

    for (int l = 0; l < TT; l++) {
        const float* p = qkv + (((long)(b * TT + l)) * NNODES + n) * 192;
        float qq[HDIM], vv[HDIM];
        float s = 0.f;
#pragma unroll
        for (int m = 0; m < HDIM; m++) { qq[m] = p[h * 8 + m]; s += qq[m] * qq[m]; }
#pragma unroll
        for (int d = 0; d < HDIM; d++) vv[d] = p[128 + h * 8 + d];
        float inv = 1.f / fmaxf(sqrtf(s), 1e-12f);
        float den = (float)TT;
#pragma unroll
        for (int m = 0; m < HDIM; m++) { qq[m] *= inv; den = fmaf(qq[m], ksum[m], den); }
        float invden = 1.f / fmaxf(den, 1e-5f);
        float* out = cat + (((long)(b * TT + l)) * NNODES + n) * 128 + 64 + h * 8;
#pragma unroll
        for (int d = 0; d < HDIM; d++) {
            float num = (float)TT * vv[d];
#pragma unroll
            for (int m = 0; m < HDIM; m++) num = fmaf(qq[m], kvs[m][d], num);
            out[d] = num * invden;
        }
    }
}

// ---------------- fused x_glo + LayerNorm1 (warp per row of 64) ----------------
__global__ __launch_bounds__(256)
void glo_ln_kernel(const float* __restrict__ x,  const float* __restrict__ a0,
                   const float* __restrict__ a1, const float* __restrict__ p0,
                   const float* __restrict__ p1, const float* __restrict__ g,
                   const float* __restrict__ be, float* __restrict__ y)
{
    long row = ((long)blockIdx.x * blockDim.x + threadIdx.x) >> 5;
    int lane = threadIdx.x & 31;
    if (row >= ROWS) return;
    long base = row * 64;
    int c0 = lane, c1 = lane + 32;
    float v0 = 2.f * (x[base+c0] + a0[base+c0]*p0[base+c0] + a1[base+c0]*p1[base+c0]*0.01f);
    float v1 = 2.f * (x[base+c1] + a0[base+c1]*p0[base+c1] + a1[base+c1]*p1[base+c1]*0.01f);
    float s = v0 + v1;
#pragma unroll
    for (int o = 16; o; o >>= 1) s += __shfl_xor_sync(0xffffffffu, s, o);
    float mean = s * (1.f / 64.f);
    float d0 = v0 - mean, d1 = v1 - mean;
    float vs = d0 * d0 + d1 * d1;
#pragma unroll
    for (int o = 16; o; o >>= 1) vs += __shfl_xor_sync(0xffffffffu, vs, o);
    float r = rsqrtf(vs * (1.f / 64.f) + 1e-5f);
    y[base + c0] = d0 * r * g[c0] + be[c0];
    y[base + c1] = d1 * r * g[c1] + be[c1];
}

// ---------------- fused residual + LayerNorm2 -> output ----------------
__global__ __launch_bounds__(256)
void final_ln_kernel(const float* __restrict__ y, const float* __restrict__ h2,
                     const float* __restrict__ g, const float* __restrict__ be,
                     float* __restrict__ out)
{
    long row = ((long)blockIdx.x * blockDim.x + threadIdx.x) >> 5;
    int lane = threadIdx.x & 31;
    if (row >= ROWS) return;
    long base = row * 64;
    int c0 = lane, c1 = lane + 32;
    float v0 = y[base + c0] + h2[base + c0];
    float v1 = y[base + c1] + h2[base + c1];
    float s = v0 + v1;
#pragma unroll
    for (int o = 16; o; o >>= 1) s += __shfl_xor_sync(0xffffffffu, s, o);
    float mean = s * (1.f / 64.f);
    float d0 = v0 - mean, d1 = v1 - mean;
    float vs = d0 * d0 + d1 * d1;
#pragma unroll
    for (int o = 16; o; o >>= 1) vs += __shfl_xor_sync(0xffffffffu, vs, o);
    float r = rsqrtf(vs * (1.f / 64.f) + 1e-5f);
    out[base + c0] = d0 * r * g[c0] + be[c0];
    out[base + c1] = d1 * r * g[c1] + be[c1];
}

// ---------------- host launcher ----------------
extern "C" void kernel_launch(void* const* d_in, const int* in_sizes, int n_in,
                              void* d_out, int out_size)
{
    const float* x     = (const float*)d_in[0];
    const float* phi   = (const float*)d_in[1];
    const float* phinv = (const float*)d_in[2];
    const float* diagw = (const float*)d_in[3];
    const float* qkv0w = (const float*)d_in[4];
    const float* out0w = (const float*)d_in[5];
    const float* out0b = (const float*)d_in[6];
    const float* qkv1w = (const float*)d_in[7];
    const float* out1w = (const float*)d_in[8];
    const float* out1b = (const float*)d_in[9];
    const float* pw0w  = (const float*)d_in[10];
    const float* pw0b  = (const float*)d_in[11];
    const float* pw1w  = (const float*)d_in[12];
    const float* pw1b  = (const float*)d_in[13];
    const float* fc1w  = (const float*)d_in[14];
    const float* fc1b  = (const float*)d_in[15];
    const float* fc2w  = (const float*)d_in[16];
    const float* fc2b  = (const float*)d_in[17];
    const float* ln1g  = (const float*)d_in[18];
    const float* ln1b  = (const float*)d_in[19];
    const float* ln2g  = (const float*)d_in[20];
    const float* ln2b  = (const float*)d_in[21];

    float *sphi, *msum, *xk, *qkvb, *catb, *att0, *att1, *p0, *p1, *yb, *hid, *h2;
    cudaGetSymbolAddress((void**)&sphi, g_sphi);
    cudaGetSymbolAddress((void**)&msum, g_msum);
    cudaGetSymbolAddress((void**)&xk,   g_xk);
    cudaGetSymbolAddress((void**)&qkvb, g_qkv);
    cudaGetSymbolAddress((void**)&catb, g_cat);
    cudaGetSymbolAddress((void**)&att0, g_att0);
    cudaGetSymbolAddress((void**)&att1, g_att1);
    cudaGetSymbolAddress((void**)&p0,   g_p0);
    cudaGetSymbolAddress((void**)&p1,   g_p1);
    cudaGetSymbolAddress((void**)&yb,   g_y);
    cudaGetSymbolAddress((void**)&hid,  g_hid);
    cudaGetSymbolAddress((void**)&h2,   g_h2);

    const int MBLK = (int)(ROWS / 128);  // 3072

    // 1) scaledPhi = phi * diag_w (broadcast over j)
    {
        long total = (long)SWAV * NNODES * NNODES;
        scale_phi_kernel<<<(unsigned)((total + 255) / 256), 256>>>(phi, diagw, sphi);
    }

    // 2) Msum = sum_s scaledPhi_s @ phi_inv_s   (4 accumulating 2048^3 GEMMs)
    for (int s = 0; s < SWAV; s++) {
        gemm_k<128,128,16,8,8,false,false><<<dim3(16,16,1), 256>>>(
            sphi + (long)s * NNODES * NNODES, phinv + (long)s * NNODES * NNODES,
            msum, nullptr, NNODES, NNODES, NNODES, NNODES, 0, 0, 0, s > 0 ? 1 : 0);
    }

    // 3) x_k[bt] = Msum @ x[bt]   (batched, Msum shared -> L2-resident)
    gemm_k<128,64,16,8,4,false,false><<<dim3(1,16,BT), 256>>>(
        msum, x, xk, nullptr, NNODES, NNODES, CDIM, CDIM,
        0, (long)NNODES * CDIM, (long)NNODES * CDIM, 0);

    // 4) attention layer 0 on x
    gemm_k<128,64,16,8,4,true,false><<<dim3(3,MBLK,1), 256>>>(
        x, qkv0w, qkvb, nullptr, 64, 64, 64, 192, 0, 0, 0, 0);
    attn_spatial<<<dim3(BT, HH), 256>>>(qkvb, catb);
    attn_temporal<<<(BB * NNODES * HH + 255) / 256, 256>>>(qkvb, catb);
    gemm_k<128,64,16,8,4,true,false><<<dim3(1,MBLK,1), 256>>>(
        catb, out0w, att0, out0b, 128, 128, 128, 64, 0, 0, 0, 0);

    // 5) attention layer 1 on x_k
    gemm_k<128,64,16,8,4,true,false><<<dim3(3,MBLK,1), 256>>>(
        xk, qkv1w, qkvb, nullptr, 64, 64, 64, 192, 0, 0, 0, 0);
    attn_spatial<<<dim3(BT, HH), 256>>>(qkvb, catb);
    attn_temporal<<<(BB * NNODES * HH + 255) / 256, 256>>>(qkvb, catb);
    gemm_k<128,64,16,8,4,true,false><<<dim3(1,MBLK,1), 256>>>(
        catb, out1w, att1, out1b, 128, 128, 128, 64, 0, 0, 0, 0);

    // 6) pointwise gates
    gemm_k<128,64,16,8,4,true,false><<<dim3(1,MBLK,1), 256>>>(
        x, pw0w, p0, pw0b, 64, 64, 64, 64, 0, 0, 0, 0);
    gemm_k<128,64,16,8,4,true,false><<<dim3(1,MBLK,1), 256>>>(
        att0, pw1w, p1, pw1b, 64, 64, 64, 64, 0, 0, 0, 0);

    // 7) y = LN1(2 * (x + att0*p0 + 0.01*att1*p1))
    glo_ln_kernel<<<(unsigned)(ROWS / 8), 256>>>(x, att0, att1, p0, p1, ln1g, ln1b, yb);

    // 8) MLP
    gemm_k<128,64,16,8,4,true,true><<<dim3(2,MBLK,1), 256>>>(
        yb, fc1w, hid, fc1b, 64, 64, 64, 128, 0, 0, 0, 0);
    gemm_k<128,64,16,8,4,true,false><<<dim3(1,MBLK,1), 256>>>(
        hid, fc2w, h2, fc2b, 128, 128, 128, 64, 0, 0, 0, 0);

    // 9) out = LN2(y + h)
    final_ln_kernel<<<(unsigned)(ROWS / 8), 256>>>(yb, h2, ln2g, ln2b, (float*)d_out);
}

// round 3
// speedup vs baseline: 1.9820x; 1.9820x over previous
#include <cuda_runtime.h>
#include <cuda_bf16.h>
#include <math.h>
#include <stdint.h>

#define BB 8
#define TT 24
#define NNODES 2048
#define CDIM 64
#define HH 8
#define HDIM 8
#define SWAV 4
#define BT (BB*TT)              // 192
#define ROWS ((long)BT*NNODES)  // 393216
#define KBIG (SWAV*NNODES)      // 8192
#define NXK (BT*CDIM)           // 12288

// ---------------- scratch (static device globals; no allocation) ----------------
__device__ unsigned short g_a2[(long)NNODES*KBIG];      // bf16 [2048][8192] A for Msum
__device__ unsigned short g_b2[(long)NNODES*KBIG];      // bf16 [2048][8192] B^T for Msum
__device__ unsigned short g_msumbf[(long)NNODES*NNODES];// bf16 [2048][2048]
__device__ unsigned short g_xt[(long)NXK*NNODES];       // bf16 [12288][2048] x^T
__device__ float g_xk  [BT*NNODES*CDIM];
__device__ float g_qkv [BT*NNODES*3*CDIM];
__device__ float g_cat [BT*NNODES*2*CDIM];
__device__ float g_att0[BT*NNODES*CDIM];
__device__ float g_att1[BT*NNODES*CDIM];
__device__ float g_p0  [BT*NNODES*CDIM];
__device__ float g_p1  [BT*NNODES*CDIM];
__device__ float g_y   [BT*NNODES*CDIM];
__device__ float g_hid [BT*NNODES*2*CDIM];
__device__ float g_h2  [BT*NNODES*CDIM];

__device__ __forceinline__ uint32_t smem_u32(const void* p){
    uint32_t a;
    asm("{ .reg .u64 t; cvta.to.shared.u64 t, %1; cvt.u32.u64 %0, t; }" : "=r"(a) : "l"(p));
    return a;
}
__device__ __forceinline__ unsigned short f2bf(float v){
    __nv_bfloat16 h = __float2bfloat16(v);
    return *(unsigned short*)&h;
}

#define LDSM4(r, addr) \
    asm volatile("ldmatrix.sync.aligned.m8n8.x4.shared.b16 {%0,%1,%2,%3}, [%4];" \
        : "=r"((r)[0]), "=r"((r)[1]), "=r"((r)[2]), "=r"((r)[3]) : "r"(addr))

#define MMA16816(c, a, b0, b1) \
    asm volatile("mma.sync.aligned.m16n8k16.row.col.f32.bf16.bf16.f32 " \
        "{%0,%1,%2,%3}, {%4,%5,%6,%7}, {%8,%9}, {%0,%1,%2,%3};" \
        : "+f"((c)[0]), "+f"((c)[1]), "+f"((c)[2]), "+f"((c)[3]) \
        : "r"((a)[0]), "r"((a)[1]), "r"((a)[2]), "r"((a)[3]), "r"(b0), "r"(b1))

// ================ mma.sync bf16 GEMM: D[m,n] = sum_k A[m,k] * B[n,k] ================
// A: [Mtot][ldA] bf16 K-major, B: [Ntot][ldB] bf16 K-major. Block tile 128x128, K-tile 32.
// EPI 0: write bf16 to Cout (row-major ld 2048)  [Msum]
// EPI 1: scatter fp32 into x_k: col n = bt*64+c -> xk[(bt*2048 + m)*64 + c]
// smem per buffer: A 128 rows x 80B + B 128 rows x 80B (64B data + 16B pad -> conflict-free ldmatrix)
template<int EPI>
__global__ __launch_bounds__(256)
void mma_gemm(const unsigned short* __restrict__ A, const unsigned short* __restrict__ B,
              int K, int ldA, int ldB, void* __restrict__ Cout)
{
    __shared__ __align__(16) char smem[2 * 20480];
    const int tid  = threadIdx.x;
    const int lane = tid & 31;
    const int w    = tid >> 5;
    const int warp_m = w & 3;       // 4 warps over M (32 rows each)
    const int warp_n = w >> 2;      // 2 warps over N (64 cols each)
    const long m0 = (long)blockIdx.y * 128;
    const long n0 = (long)blockIdx.x * 128;
    const unsigned short* Ab = A + m0 * ldA;
    const unsigned short* Bb = B + n0 * ldB;

    const uint32_t sbase = smem_u32(smem);
    const int r0w = tid >> 2;       // 0..63 (+64 for second half)
    const int kc  = tid & 3;        // 16B chunk within 64B row

    // ldmatrix per-thread base offsets
    const uint32_t aoff = (uint32_t)(warp_m*32 + (lane & 15))*80 + (uint32_t)(lane >> 4)*16;
    const uint32_t boff = (uint32_t)(warp_n*64 + ((lane >> 4) << 3) + (lane & 7))*80
                        + (uint32_t)((lane >> 3) & 1)*16 + 10240;

    float acc[2][8][4];
#pragma unroll
    for (int mt = 0; mt < 2; mt++)
#pragma unroll
        for (int nt = 0; nt < 8; nt++)
#pragma unroll
            for (int i = 0; i < 4; i++) acc[mt][nt][i] = 0.f;

    // preload tile 0 into buffer 0
#pragma unroll
    for (int i = 0; i < 2; i++) {
        int row = r0w + i*64;
        uint4 va = *(const uint4*)(Ab + (long)row*ldA + kc*8);
        uint4 vb = *(const uint4*)(Bb + (long)row*ldB + kc*8);
        *(uint4*)(smem + row*80 + kc*16) = va;
        *(uint4*)(smem + 10240 + row*80 + kc*16) = vb;
    }
    __syncthreads();

    const int T = K >> 5;
    for (int t = 0; t < T; t++) {
        uint4 pa[2], pb[2];
        if (t + 1 < T) {
            const int kt = (t + 1) << 5;
#pragma unroll
            for (int i = 0; i < 2; i++) {
                int row = r0w + i*64;
                pa[i] = *(const uint4*)(Ab + (long)row*ldA + kt + kc*8);
                pb[i] = *(const uint4*)(Bb + (long)row*ldB + kt + kc*8);
            }
        }
        const uint32_t sA = sbase + (uint32_t)(t & 1)*20480;
#pragma unroll
        for (int k16 = 0; k16 < 2; k16++) {
            uint32_t a[2][4], b[4][4];
#pragma unroll
            for (int mt = 0; mt < 2; mt++)
                LDSM4(a[mt], sA + aoff + mt*1280 + k16*32);
#pragma unroll
            for (int nt2 = 0; nt2 < 4; nt2++)
                LDSM4(b[nt2], sA + boff + nt2*1280 + k16*32);
#pragma unroll
            for (int mt = 0; mt < 2; mt++)
#pragma unroll
                for (int nt = 0; nt < 8; nt++) {
                    const int nt2 = nt >> 1, hi = (nt & 1) * 2;
                    MMA16816(acc[mt][nt], a[mt], b[nt2][hi], b[nt2][hi+1]);
                }
        }
        if (t + 1 < T) {
            char* d = smem + ((t + 1) & 1)*20480;
#pragma unroll
            for (int i = 0; i < 2; i++) {
                int row = r0w + i*64;
                *(uint4*)(d + row*80 + kc*16) = pa[i];
                *(uint4*)(d + 10240 + row*80 + kc*16) = pb[i];
            }
        }
        __syncthreads();
    }

    const int group = lane >> 2, tig = lane & 3;
    if (EPI == 0) {
        unsigned short* C = (unsigned short*)Cout;
#pragma unroll
        for (int mt = 0; mt < 2; mt++) {
            long rbase = m0 + warp_m*32 + mt*16;
#pragma unroll
            for (int nt = 0; nt < 8; nt++) {
                long col = n0 + warp_n*64 + nt*8 + tig*2;
                __nv_bfloat162 h0 = __floats2bfloat162_rn(acc[mt][nt][0], acc[mt][nt][1]);
                __nv_bfloat162 h1 = __floats2bfloat162_rn(acc[mt][nt][2], acc[mt][nt][3]);
                *(uint32_t*)(C + (rbase + group)*2048 + col)     = *(uint32_t*)&h0;
                *(uint32_t*)(C + (rbase + 8 + group)*2048 + col) = *(uint32_t*)&h1;
            }
        }
    } else {
        float* Xk = (float*)Cout;
        const long bt = (n0 + warp_n*64) >> 6;
        float* obase = Xk + bt * (long)NNODES * 64;
#pragma unroll
        for (int mt = 0; mt < 2; mt++) {
            long r = m0 + warp_m*32 + mt*16 + group;
#pragma unroll
            for (int nt = 0; nt < 8; nt++) {
                int cin = nt*8 + tig*2;
                *(float2*)(obase + r*64 + cin)       = make_float2(acc[mt][nt][0], acc[mt][nt][1]);
                *(float2*)(obase + (r + 8)*64 + cin) = make_float2(acc[mt][nt][2], acc[mt][nt][3]);
            }
        }
    }
}

// ================ prep kernels (fp32 -> bf16 layouts) ================
__global__ void prep_phi(const float* __restrict__ phi, const float* __restrict__ dw,
                         unsigned short* __restrict__ A2)
{
    long idx4 = (long)blockIdx.x * blockDim.x + threadIdx.x;
    long total4 = (long)SWAV * NNODES * NNODES / 4;
    if (idx4 >= total4) return;
    long idx = idx4 * 4;
    int s = (int)(idx >> 22);
    int i = (int)((idx >> 11) & 2047);
    int j0 = (int)(idx & 2047);
    float4 p = *(const float4*)(phi + idx);
    float4 d = *(const float4*)(dw + (long)s * NNODES + j0);
    unsigned short res[4];
    res[0] = f2bf(p.x * d.x); res[1] = f2bf(p.y * d.y);
    res[2] = f2bf(p.z * d.z); res[3] = f2bf(p.w * d.w);
    *(uint2*)(A2 + (long)i * KBIG + (long)s * NNODES + j0) = *(uint2*)res;
}

__global__ void prep_phinv(const float* __restrict__ pin, unsigned short* __restrict__ B2)
{
    __shared__ float t[32][33];
    int s = blockIdx.z;
    int j0 = blockIdx.y * 32, n0 = blockIdx.x * 32;
    int tx = threadIdx.x, ty = threadIdx.y;
#pragma unroll
    for (int r = 0; r < 4; r++)
        t[ty + r*8][tx] = pin[((long)s << 22) + (long)(j0 + ty + r*8) * NNODES + n0 + tx];
    __syncthreads();
#pragma unroll
    for (int r = 0; r < 4; r++)
        B2[(long)(n0 + ty + r*8) * KBIG + (long)s * NNODES + j0 + tx] = f2bf(t[tx][ty + r*8]);
}

__global__ void prep_x(const float* __restrict__ x, unsigned short* __restrict__ XT)
{
    __shared__ float t[32][33];
    int bt = blockIdx.z;
    int j0 = blockIdx.x * 32, c0 = blockIdx.y * 32;
    int tx = threadIdx.x, ty = threadIdx.y;
#pragma unroll
    for (int r = 0; r < 4; r++)
        t[ty + r*8][tx] = x[((long)bt * NNODES + j0 + ty + r*8) * CDIM + c0 + tx];
    __syncthreads();
#pragma unroll
    for (int r = 0; r < 4; r++)
        XT[(long)(bt * 64 + c0 + ty + r*8) * NNODES + j0 + tx] = f2bf(t[tx][ty + r*8]);
}

// ---------------- generic register-tiled fp32 GEMM (skinny ops) ----------------
template<int BM,int BN,int BK,int TM,int TN,bool TRANSB,bool RELU>
__global__ __launch_bounds__((BM/TM)*(BN/TN))
void gemm_k(const float* __restrict__ A, const float* __restrict__ B,
            float* __restrict__ C, const float* __restrict__ bias,
            int K, int lda, int ldb, int ldc,
            long sA, long sB, long sC, int accumulate)
{
    constexpr int TX = BN / TN;
    constexpr int TY = BM / TM;
    constexpr int THREADS = TX * TY;
    __shared__ float As[BK][BM];
    __shared__ float Bs[BK][BN];

    const int tid = threadIdx.x;
    const int tx  = tid % TX;
    const int ty  = tid / TX;
    const long m0 = (long)blockIdx.y * BM;
    const int  n0 = blockIdx.x * BN;

    A += (long)blockIdx.z * sA;
    B += (long)blockIdx.z * sB;
    C += (long)blockIdx.z * sC;

    float acc[TM][TN];
#pragma unroll
    for (int i = 0; i < TM; i++)
#pragma unroll
        for (int j = 0; j < TN; j++) acc[i][j] = 0.f;

    for (int k0 = 0; k0 < K; k0 += BK) {
#pragma unroll
        for (int i = tid; i < BM * BK / 4; i += THREADS) {
            int r = i / (BK / 4);
            int c = i % (BK / 4);
            const float4 v = *(const float4*)&A[(m0 + r) * (long)lda + k0 + c * 4];
            As[c*4+0][r] = v.x; As[c*4+1][r] = v.y;
            As[c*4+2][r] = v.z; As[c*4+3][r] = v.w;
        }
        if (!TRANSB) {
#pragma unroll
            for (int i = tid; i < BK * BN / 4; i += THREADS) {
                int r = i / (BN / 4);
                int c = i % (BN / 4);
                *(float4*)&Bs[r][c*4] =
                    *(const float4*)&B[(long)(k0 + r) * ldb + n0 + c * 4];
            }
        } else {
#pragma unroll
            for (int i = tid; i < BN * BK / 4; i += THREADS) {
                int r = i / (BK / 4);
                int c = i % (BK / 4);
                const float4 v = *(const float4*)&B[(long)(n0 + r) * ldb + k0 + c * 4];
                Bs[c*4+0][r] = v.x; Bs[c*4+1][r] = v.y;
                Bs[c*4+2][r] = v.z; Bs[c*4+3][r] = v.w;
            }
        }
        __syncthreads();
#pragma unroll
        for (int k = 0; k < BK; k++) {
            float ra[TM], rb[TN];
#pragma unroll
            for (int i = 0; i < TM; i += 4)
                *(float4*)&ra[i] = *(const float4*)&As[k][ty * TM + i];
#pragma unroll
            for (int j = 0; j < TN; j += 4)
                *(float4*)&rb[j] = *(const float4*)&Bs[k][tx * TN + j];
#pragma unroll
            for (int i = 0; i < TM; i++)
#pragma unroll
                for (int j = 0; j < TN; j++)
                    acc[i][j] = fmaf(ra[i], rb[j], acc[i][j]);
        }
        __syncthreads();
    }
#pragma unroll
    for (int i = 0; i < TM; i++) {
#pragma unroll
        for (int j = 0; j < TN; j++) {
            int n = n0 + tx * TN + j;
            long idx = (m0 + ty * TM + i) * (long)ldc + n;
            float v = acc[i][j];
            if (bias) v += bias[n];
            if (accumulate) v += C[idx];
            if (RELU) v = fmaxf(v, 0.f);
            C[idx] = v;
        }
    }
}

// ---------------- linear attention, spatial (attend over N=2048) ----------------
__global__ __launch_bounds__(256)
void attn_spatial(const float* __restrict__ qkv, float* __restrict__ cat)
{
    const int bt = blockIdx.x;
    const int h  = blockIdx.y;
    const int tid = threadIdx.x;
    const int lane = tid & 31;
    const int warp = tid >> 5;
    const float* base = qkv + (long)bt * NNODES * 192;

    float kvs[HDIM][HDIM];
    float ksum[HDIM];
#pragma unroll
    for (int m = 0; m < HDIM; m++) {
        ksum[m] = 0.f;
#pragma unroll
        for (int d = 0; d < HDIM; d++) kvs[m][d] = 0.f;
    }

    for (int n = tid; n < NNODES; n += 256) {
        const float* pk = base + (long)n * 192 + 64 + h * 8;
        const float* pv = base + (long)n * 192 + 128 + h * 8;
        float kk[HDIM], vv[HDIM];
        float s = 0.f;
#pragma unroll
        for (int m = 0; m < HDIM; m++) { kk[m] = pk[m]; s += kk[m] * kk[m]; }
#pragma unroll
        for (int d = 0; d < HDIM; d++) vv[d] = pv[d];
        float inv = 1.f / fmaxf(sqrtf(s), 1e-12f);
#pragma unroll
        for (int m = 0; m < HDIM; m++) {
            float km = kk[m] * inv;
            ksum[m] += km;
#pragma unroll
            for (int d = 0; d < HDIM; d++) kvs[m][d] = fmaf(km, vv[d], kvs[m][d]);
        }
    }

    __shared__ float red[8][72];
    __shared__ float fin[72];
#pragma unroll
    for (int m = 0; m < HDIM; m++) {
#pragma unroll
        for (int d = 0; d < HDIM; d++) {
            float v = kvs[m][d];
#pragma unroll
            for (int o = 16; o; o >>= 1) v += __shfl_down_sync(0xffffffffu, v, o);
            if (lane == 0) red[warp][m * 8 + d] = v;
        }
        float v = ksum[m];
#pragma unroll
        for (int o = 16; o; o >>= 1) v += __shfl_down_sync(0xffffffffu, v, o);
        if (lane == 0) red[warp][64 + m] = v;
    }
    __syncthreads();
    if (tid < 72) {
        float s = 0.f;
#pragma unroll
        for (int w = 0; w < 8; w++) s += red[w][tid];
        fin[tid] = s;
    }
    __syncthreads();

    float fkvs[HDIM][HDIM], fksum[HDIM];
#pragma unroll
    for (int m = 0; m < HDIM; m++) {
        fksum[m] = fin[64 + m];
#pragma unroll
        for (int d = 0; d < HDIM; d++) fkvs[m][d] = fin[m * 8 + d];
    }

    for (int n = tid; n < NNODES; n += 256) {
        const float* pq = base + (long)n * 192 + h * 8;
        const float* pv = base + (long)n * 192 + 128 + h * 8;
        float qq[HDIM], vv[HDIM];
        float s = 0.f;
#pragma unroll
        for (int m = 0; m < HDIM; m++) { qq[m] = pq[m]; s += qq[m] * qq[m]; }
#pragma unroll
        for (int d = 0; d < HDIM; d++) vv[d] = pv[d];
        float inv = 1.f / fmaxf(sqrtf(s), 1e-12f);
        float den = (float)NNODES;
#pragma unroll
        for (int m = 0; m < HDIM; m++) { qq[m] *= inv; den = fmaf(qq[m], fksum[m], den); }
        float invden = 1.f / fmaxf(den, 1e-5f);
        float* out = cat + ((long)bt * NNODES + n) * 128 + h * 8;
#pragma unroll
        for (int d = 0; d < HDIM; d++) {
            float num = (float)NNODES * vv[d];
#pragma unroll
            for (int m = 0; m < HDIM; m++) num = fmaf(qq[m], fkvs[m][d], num);
            out[d] = num * invden;
        }
    }
}

// ---------------- linear attention, temporal (attend over T=24) ----------------
__global__ __launch_bounds__(256)
void attn_temporal(const float* __restrict__ qkv, float* __restrict__ cat)
{
    int t = blockIdx.x * blockDim.x + threadIdx.x;
    if (t >= BB * NNODES * HH) return;
    const int h = t & 7;
    const int n = (t >> 3) & (NNODES - 1);
    const int b = t >> 14;

    float kvs[HDIM][HDIM];
    float ksum[HDIM];
#pragma unroll
    for (int m = 0; m < HDIM; m++) {
        ksum[m] = 0.f;
#pragma unroll
        for (int d = 0; d < HDIM; d++) kvs[m][d] = 0.f;
    }

    for (int l = 0; l < TT; l++) {
        const float* p = qkv + (((long)(b * TT + l)) * NNODES + n) * 192;
        float kk[HDIM], vv[HDIM];
        float s = 0.f;
#pragma unroll
        for (int m = 0; m < HDIM; m++) { kk[m] = p[64 + h * 8 + m]; s += kk[m] * kk[m]; }
#pragma unroll
        for (int d = 0; d < HDIM; d++) vv[d] = p[128 + h * 8 + d];
        float inv = 1.f / fmaxf(sqrtf(s), 1e-12f);
#pragma unroll
        for (int m = 0; m < HDIM; m++) {
            float km = kk[m] * inv;
            ksum[m] += km;
#pragma unroll
            for (int d = 0; d < HDIM; d++) kvs[m][d] = fmaf(km, vv[d], kvs[m][d]);
        }
    }

    for (int l = 0; l < TT; l++) {
        const float* p = qkv + (((long)(b * TT + l)) * NNODES + n) * 192;
        float qq[HDIM], vv[HDIM];
        float s = 0.f;
#pragma unroll
        for (int m = 0; m < HDIM; m++) { qq[m] = p[h * 8 + m]; s += qq[m] * qq[m]; }
#pragma unroll
        for (int d = 0; d < HDIM; d++) vv[d] = p[128 + h * 8 + d];
        float inv = 1.f / fmaxf(sqrtf(s), 1e-12f);
        float den = (float)TT;
#pragma unroll
        for (int m = 0; m < HDIM; m++) { qq[m] *= inv; den = fmaf(qq[m], ksum[m], den); }
        float invden = 1.f / fmaxf(den, 1e-5f);
        float* out = cat + (((long)(b * TT + l)) * NNODES + n) * 128 + 64 + h * 8;
#pragma unroll
        for (int d = 0; d < HDIM; d++) {
            float num = (float)TT * vv[d];
#pragma unroll
            for (int m = 0; m < HDIM; m++) num = fmaf(qq[m], kvs[m][d], num);
            out[d] = num * invden;
        }
    }
}

// ---------------- fused x_glo + LayerNorm1 ----------------
__global__ __launch_bounds__(256)
void glo_ln_kernel(const float* __restrict__ x,  const float* __restrict__ a0,
                   const float* __restrict__ a1, const float* __restrict__ p0,
                   const float* __restrict__ p1, const float* __restrict__ g,
                   const float* __restrict__ be, float* __restrict__ y)
{
    long row = ((long)blockIdx.x * blockDim.x + threadIdx.x) >> 5;
    int lane = threadIdx.x & 31;
    if (row >= ROWS) return;
    long base = row * 64;
    int c0 = lane, c1 = lane + 32;
    float v0 = 2.f * (x[base+c0] + a0[base+c0]*p0[base+c0] + a1[base+c0]*p1[base+c0]*0.01f);
    float v1 = 2.f * (x[base+c1] + a0[base+c1]*p0[base+c1] + a1[base+c1]*p1[base+c1]*0.01f);
    float s = v0 + v1;
#pragma unroll
    for (int o = 16; o; o >>= 1) s += __shfl_xor_sync(0xffffffffu, s, o);
    float mean = s * (1.f / 64.f);
    float d0 = v0 - mean, d1 = v1 - mean;
    float vs = d0 * d0 + d1 * d1;
#pragma unroll
    for (int o = 16; o; o >>= 1) vs += __shfl_xor_sync(0xffffffffu, vs, o);
    float r = rsqrtf(vs * (1.f / 64.f) + 1e-5f);
    y[base + c0] = d0 * r * g[c0] + be[c0];
    y[base + c1] = d1 * r * g[c1] + be[c1];
}

// ---------------- fused residual + LayerNorm2 -> output ----------------
__global__ __launch_bounds__(256)
void final_ln_kernel(const float* __restrict__ y, const float* __restrict__ h2,
                     const float* __restrict__ g, const float* __restrict__ be,
                     float* __restrict__ out)
{
    long row = ((long)blockIdx.x * blockDim.x + threadIdx.x) >> 5;
    int lane = threadIdx.x & 31;
    if (row >= ROWS) return;
    long base = row * 64;
    int c0 = lane, c1 = lane + 32;
    float v0 = y[base + c0] + h2[base + c0];
    float v1 = y[base + c1] + h2[base + c1];
    float s = v0 + v1;
#pragma unroll
    for (int o = 16; o; o >>= 1) s += __shfl_xor_sync(0xffffffffu, s, o);
    float mean = s * (1.f / 64.f);
    float d0 = v0 - mean, d1 = v1 - mean;
    float vs = d0 * d0 + d1 * d1;
#pragma unroll
    for (int o = 16; o; o >>= 1) vs += __shfl_xor_sync(0xffffffffu, vs, o);
    float r = rsqrtf(vs * (1.f / 64.f) + 1e-5f);
    out[base + c0] = d0 * r * g[c0] + be[c0];
    out[base + c1] = d1 * r * g[c1] + be[c1];
}

// ---------------- host launcher ----------------
extern "C" void kernel_launch(void* const* d_in, const int* in_sizes, int n_in,
                              void* d_out, int out_size)
{
    const float* x     = (const float*)d_in[0];
    const float* phi   = (const float*)d_in[1];
    const float* phinv = (const float*)d_in[2];
    const float* diagw = (const float*)d_in[3];
    const float* qkv0w = (const float*)d_in[4];
    const float* out0w = (const float*)d_in[5];
    const float* out0b = (const float*)d_in[6];
    const float* qkv1w = (const float*)d_in[7];
    const float* out1w = (const float*)d_in[8];
    const float* out1b = (const float*)d_in[9];
    const float* pw0w  = (const float*)d_in[10];
    const float* pw0b  = (const float*)d_in[11];
    const float* pw1w  = (const float*)d_in[12];
    const float* pw1b  = (const float*)d_in[13];
    const float* fc1w  = (const float*)d_in[14];
    const float* fc1b  = (const float*)d_in[15];
    const float* fc2w  = (const float*)d_in[16];
    const float* fc2b  = (const float*)d_in[17];
    const float* ln1g  = (const float*)d_in[18];
    const float* ln1b  = (const float*)d_in[19];
    const float* ln2g  = (const float*)d_in[20];
    const float* ln2b  = (const float*)d_in[21];

    unsigned short *a2, *b2, *msumbf, *xt;
    float *xk, *qkvb, *catb, *att0, *att1, *p0, *p1, *yb, *hid, *h2;
    cudaGetSymbolAddress((void**)&a2,     g_a2);
    cudaGetSymbolAddress((void**)&b2,     g_b2);
    cudaGetSymbolAddress((void**)&msumbf, g_msumbf);
    cudaGetSymbolAddress((void**)&xt,     g_xt);
    cudaGetSymbolAddress((void**)&xk,   g_xk);
    cudaGetSymbolAddress((void**)&qkvb, g_qkv);
    cudaGetSymbolAddress((void**)&catb, g_cat);
    cudaGetSymbolAddress((void**)&att0, g_att0);
    cudaGetSymbolAddress((void**)&att1, g_att1);
    cudaGetSymbolAddress((void**)&p0,   g_p0);
    cudaGetSymbolAddress((void**)&p1,   g_p1);
    cudaGetSymbolAddress((void**)&yb,   g_y);
    cudaGetSymbolAddress((void**)&hid,  g_hid);
    cudaGetSymbolAddress((void**)&h2,   g_h2);

    const int MBLK = (int)(ROWS / 128);  // 3072

    // 1) bf16 layout prep
    {
        long total4 = (long)SWAV * NNODES * NNODES / 4;
        prep_phi<<<(unsigned)((total4 + 255) / 256), 256>>>(phi, diagw, a2);
    }
    prep_phinv<<<dim3(NNODES/32, NNODES/32, SWAV), dim3(32, 8)>>>(phinv, b2);
    prep_x<<<dim3(NNODES/32, CDIM/32, BT), dim3(32, 8)>>>(x, xt);

    // 2) Msum = A2 @ B2^T : 2048 x 2048 x 8192 bf16 HMMA GEMM -> bf16
    mma_gemm<0><<<dim3(16, 16), 256>>>(a2, b2, KBIG, KBIG, KBIG, msumbf);

    // 3) x_k = Msum @ x (batches folded into N): 2048 x 12288 x 2048 -> fp32 scatter
    mma_gemm<1><<<dim3(NXK/128, 16), 256>>>(msumbf, xt, NNODES, NNODES, NNODES, xk);

    // 4) attention layer 0 on x
    gemm_k<128,64,16,8,4,true,false><<<dim3(3,MBLK,1), 256>>>(
        x, qkv0w, qkvb, nullptr, 64, 64, 64, 192, 0, 0, 0, 0);
    attn_spatial<<<dim3(BT, HH), 256>>>(qkvb, catb);
    attn_temporal<<<(BB * NNODES * HH + 255) / 256, 256>>>(qkvb, catb);
    gemm_k<128,64,16,8,4,true,false><<<dim3(1,MBLK,1), 256>>>(
        catb, out0w, att0, out0b, 128, 128, 128, 64, 0, 0, 0, 0);

    // 5) attention layer 1 on x_k
    gemm_k<128,64,16,8,4,true,false><<<dim3(3,MBLK,1), 256>>>(
        xk, qkv1w, qkvb, nullptr, 64, 64, 64, 192, 0, 0, 0, 0);
    attn_spatial<<<dim3(BT, HH), 256>>>(qkvb, catb);
    attn_temporal<<<(BB * NNODES * HH + 255) / 256, 256>>>(qkvb, catb);
    gemm_k<128,64,16,8,4,true,false><<<dim3(1,MBLK,1), 256>>>(
        catb, out1w, att1, out1b, 128, 128, 128, 64, 0, 0, 0, 0);

    // 6) pointwise gates
    gemm_k<128,64,16,8,4,true,false><<<dim3(1,MBLK,1), 256>>>(
        x, pw0w, p0, pw0b, 64, 64, 64, 64, 0, 0, 0, 0);
    gemm_k<128,64,16,8,4,true,false><<<dim3(1,MBLK,1), 256>>>(
        att0, pw1w, p1, pw1b, 64, 64, 64, 64, 0, 0, 0, 0);

    // 7) y = LN1(2 * (x + att0*p0 + 0.01*att1*p1))
    glo_ln_kernel<<<(unsigned)(ROWS / 8), 256>>>(x, att0, att1, p0, p1, ln1g, ln1b, yb);

    // 8) MLP
    gemm_k<128,64,16,8,4,true,true><<<dim3(2,MBLK,1), 256>>>(
        yb, fc1w, hid, fc1b, 64, 64, 64, 128, 0, 0, 0, 0);
    gemm_k<128,64,16,8,4,true,false><<<dim3(1,MBLK,1), 256>>>(
        hid, fc2w, h2, fc2b, 128, 128, 128, 64, 0, 0, 0, 0);

    // 9) out = LN2(y + h)
    final_ln_kernel<<<(unsigned)(ROWS / 8), 256>>>(yb, h2, ln2g, ln2b, (float*)d_out);
}

// round 4
// speedup vs baseline: 3.4182x; 1.7246x over previous
#include <cuda_runtime.h>
#include <cuda_bf16.h>
#include <math.h>
#include <stdint.h>

#define BB 8
#define TT 24
#define NNODES 2048
#define CDIM 64
#define HH 8
#define HDIM 8
#define SWAV 4
#define BT (BB*TT)              // 192
#define ROWS ((long)BT*NNODES)  // 393216
#define KBIG (SWAV*NNODES)      // 8192
#define NXK (BT*CDIM)           // 12288

typedef unsigned short u16;

// ---------------- scratch (static device globals; no allocation) ----------------
__device__ u16 g_a2[(long)NNODES*KBIG];       // bf16 A for Msum
__device__ u16 g_b2[(long)NNODES*KBIG];       // bf16 B^T for Msum
__device__ u16 g_msumbf[(long)NNODES*NNODES]; // bf16 Msum
__device__ u16 g_xt[(long)NXK*NNODES];        // bf16 x^T for x_k GEMM
__device__ u16 g_xb  [ROWS*CDIM];             // bf16 x
__device__ u16 g_xk  [ROWS*CDIM];             // bf16 x_k
__device__ u16 g_qkv [ROWS*3*CDIM];           // bf16 qkv
__device__ u16 g_cat [ROWS*2*CDIM];           // bf16 concat attention out
__device__ u16 g_att0[ROWS*CDIM];
__device__ u16 g_att1[ROWS*CDIM];
__device__ u16 g_p0  [ROWS*CDIM];
__device__ u16 g_p1  [ROWS*CDIM];
__device__ u16 g_hid [ROWS*2*CDIM];
__device__ u16 g_h2  [ROWS*CDIM];
__device__ float g_y [ROWS*CDIM];             // fp32 y (dominates output)
// bf16 weights
__device__ u16 g_wqkv0[3*CDIM*CDIM];
__device__ u16 g_wout0[CDIM*2*CDIM];
__device__ u16 g_wqkv1[3*CDIM*CDIM];
__device__ u16 g_wout1[CDIM*2*CDIM];
__device__ u16 g_wpw0 [CDIM*CDIM];
__device__ u16 g_wpw1 [CDIM*CDIM];
__device__ u16 g_wfc1 [2*CDIM*CDIM];
__device__ u16 g_wfc2 [CDIM*2*CDIM];

__device__ __forceinline__ uint32_t smem_u32(const void* p){
    uint32_t a;
    asm("{ .reg .u64 t; cvta.to.shared.u64 t, %1; cvt.u32.u64 %0, t; }" : "=r"(a) : "l"(p));
    return a;
}
__device__ __forceinline__ u16 f2bf(float v){
    __nv_bfloat16 h = __float2bfloat16(v);
    return *(u16*)&h;
}
__device__ __forceinline__ void ld8bf(float* f, const u16* p){
    uint4 u = *(const uint4*)p;
    const __nv_bfloat162* h = (const __nv_bfloat162*)&u;
#pragma unroll
    for (int i = 0; i < 4; i++) { float2 t = __bfloat1622float2(h[i]); f[2*i] = t.x; f[2*i+1] = t.y; }
}
__device__ __forceinline__ void st8bf(u16* p, const float* f){
    __nv_bfloat162 h[4];
#pragma unroll
    for (int i = 0; i < 4; i++) h[i] = __floats2bfloat162_rn(f[2*i], f[2*i+1]);
    *(uint4*)p = *(uint4*)h;
}

#define LDSM4(r, addr) \
    asm volatile("ldmatrix.sync.aligned.m8n8.x4.shared.b16 {%0,%1,%2,%3}, [%4];" \
        : "=r"((r)[0]), "=r"((r)[1]), "=r"((r)[2]), "=r"((r)[3]) : "r"(addr))

#define MMA16816(c, a, b0, b1) \
    asm volatile("mma.sync.aligned.m16n8k16.row.col.f32.bf16.bf16.f32 " \
        "{%0,%1,%2,%3}, {%4,%5,%6,%7}, {%8,%9}, {%0,%1,%2,%3};" \
        : "+f"((c)[0]), "+f"((c)[1]), "+f"((c)[2]), "+f"((c)[3]) \
        : "r"((a)[0]), "r"((a)[1]), "r"((a)[2]), "r"((a)[3]), "r"(b0), "r"(b1))

// ================ big mma GEMM: D[m,n] = sum_k A[m,k] * B[n,k] (bf16 in) ================
// EPI 0: bf16 out row-major ld 2048 [Msum];  EPI 1: bf16 out at row (n>>6)*2048+m, col n&63 [x_k]
template<int EPI>
__global__ __launch_bounds__(256)
void mma_gemm(const u16* __restrict__ A, const u16* __restrict__ B,
              int K, int ldA, int ldB, void* __restrict__ Cout)
{
    __shared__ __align__(16) char smem[2 * 20480];
    const int tid  = threadIdx.x;
    const int lane = tid & 31;
    const int w    = tid >> 5;
    const int warp_m = w & 3;
    const int warp_n = w >> 2;
    const long m0 = (long)blockIdx.y * 128;
    const long n0 = (long)blockIdx.x * 128;
    const u16* Ab = A + m0 * ldA;
    const u16* Bb = B + n0 * ldB;

    const uint32_t sbase = smem_u32(smem);
    const int r0w = tid >> 2;
    const int kc  = tid & 3;

    const uint32_t aoff = (uint32_t)(warp_m*32 + (lane & 15))*80 + (uint32_t)(lane >> 4)*16;
    const uint32_t boff = (uint32_t)(warp_n*64 + ((lane >> 4) << 3) + (lane & 7))*80
                        + (uint32_t)((lane >> 3) & 1)*16 + 10240;

    float acc[2][8][4];
#pragma unroll
    for (int mt = 0; mt < 2; mt++)
#pragma unroll
        for (int nt = 0; nt < 8; nt++)
#pragma unroll
            for (int i = 0; i < 4; i++) acc[mt][nt][i] = 0.f;

#pragma unroll
    for (int i = 0; i < 2; i++) {
        int row = r0w + i*64;
        uint4 va = *(const uint4*)(Ab + (long)row*ldA + kc*8);
        uint4 vb = *(const uint4*)(Bb + (long)row*ldB + kc*8);
        *(uint4*)(smem + row*80 + kc*16) = va;
        *(uint4*)(smem + 10240 + row*80 + kc*16) = vb;
    }
    __syncthreads();

    const int T = K >> 5;
    for (int t = 0; t < T; t++) {
        uint4 pa[2], pb[2];
        if (t + 1 < T) {
            const int kt = (t + 1) << 5;
#pragma unroll
            for (int i = 0; i < 2; i++) {
                int row = r0w + i*64;
                pa[i] = *(const uint4*)(Ab + (long)row*ldA + kt + kc*8);
                pb[i] = *(const uint4*)(Bb + (long)row*ldB + kt + kc*8);
            }
        }
        const uint32_t sA = sbase + (uint32_t)(t & 1)*20480;
#pragma unroll
        for (int k16 = 0; k16 < 2; k16++) {
            uint32_t a[2][4], b[4][4];
#pragma unroll
            for (int mt = 0; mt < 2; mt++)
                LDSM4(a[mt], sA + aoff + mt*1280 + k16*32);
#pragma unroll
            for (int nt2 = 0; nt2 < 4; nt2++)
                LDSM4(b[nt2], sA + boff + nt2*1280 + k16*32);
#pragma unroll
            for (int mt = 0; mt < 2; mt++)
#pragma unroll
                for (int nt = 0; nt < 8; nt++) {
                    const int nt2 = nt >> 1, hi = (nt & 1) * 2;
                    MMA16816(acc[mt][nt], a[mt], b[nt2][hi], b[nt2][hi+1]);
                }
        }
        if (t + 1 < T) {
            char* d = smem + ((t + 1) & 1)*20480;
#pragma unroll
            for (int i = 0; i < 2; i++) {
                int row = r0w + i*64;
                *(uint4*)(d + row*80 + kc*16) = pa[i];
                *(uint4*)(d + 10240 + row*80 + kc*16) = pb[i];
            }
        }
        __syncthreads();
    }

    const int group = lane >> 2, tig = lane & 3;
    if (EPI == 0) {
        u16* C = (u16*)Cout;
#pragma unroll
        for (int mt = 0; mt < 2; mt++) {
            long rbase = m0 + warp_m*32 + mt*16;
#pragma unroll
            for (int nt = 0; nt < 8; nt++) {
                long col = n0 + warp_n*64 + nt*8 + tig*2;
                __nv_bfloat162 h0 = __floats2bfloat162_rn(acc[mt][nt][0], acc[mt][nt][1]);
                __nv_bfloat162 h1 = __floats2bfloat162_rn(acc[mt][nt][2], acc[mt][nt][3]);
                *(uint32_t*)(C + (rbase + group)*2048 + col)     = *(uint32_t*)&h0;
                *(uint32_t*)(C + (rbase + 8 + group)*2048 + col) = *(uint32_t*)&h1;
            }
        }
    } else {
        u16* Xk = (u16*)Cout;
        const long bt = (n0 + warp_n*64) >> 6;
        u16* obase = Xk + bt * (long)NNODES * 64;
#pragma unroll
        for (int mt = 0; mt < 2; mt++) {
            long r = m0 + warp_m*32 + mt*16 + group;
#pragma unroll
            for (int nt = 0; nt < 8; nt++) {
                int cin = nt*8 + tig*2;
                __nv_bfloat162 h0 = __floats2bfloat162_rn(acc[mt][nt][0], acc[mt][nt][1]);
                __nv_bfloat162 h1 = __floats2bfloat162_rn(acc[mt][nt][2], acc[mt][nt][3]);
                *(uint32_t*)(obase + r*64 + cin)       = *(uint32_t*)&h0;
                *(uint32_t*)(obase + (r + 8)*64 + cin) = *(uint32_t*)&h1;
            }
        }
    }
}

// ================ rowgemm: per-row skinny GEMM, tensor cores, W resident in smem ========
// Out[r, n] = sum_k X[r,k] * W[n,k] (+bias) (+relu). 128 rows per block, 8 warps.
template<int NT, int KT, bool RELU, bool OUTBF, bool INF32>
__global__ __launch_bounds__(256)
void rowgemm(const void* __restrict__ Xin, const u16* __restrict__ Wb,
             const float* __restrict__ bias, void* __restrict__ Out)
{
    constexpr int SX  = KT*2 + 16;
    constexpr int CPR = (KT*2)/16;
    constexpr int NF  = NT/16;     // n8-frags per warp (half of NT per warp / 8)
    extern __shared__ __align__(16) char smem[];
    const int tid = threadIdx.x, lane = tid & 31, w = tid >> 5;
    const int warp_m = w & 3, warp_n = w >> 2;
    const long r0 = (long)blockIdx.x * 128;

    if (!INF32) {
        const u16* X = (const u16*)Xin + r0*KT;
        for (int l = tid; l < 128*CPR; l += 256) {
            int row = l / CPR, c = l % CPR;
            *(uint4*)(smem + row*SX + c*16) = *(const uint4*)(X + (long)row*KT + c*8);
        }
    } else {
        const float* X = (const float*)Xin + r0*KT;
        for (int l = tid; l < 128*CPR; l += 256) {
            int row = l / CPR, c = l % CPR;
            float4 f0 = *(const float4*)(X + (long)row*KT + c*8);
            float4 f1 = *(const float4*)(X + (long)row*KT + c*8 + 4);
            __nv_bfloat162 h[4];
            h[0] = __floats2bfloat162_rn(f0.x, f0.y);
            h[1] = __floats2bfloat162_rn(f0.z, f0.w);
            h[2] = __floats2bfloat162_rn(f1.x, f1.y);
            h[3] = __floats2bfloat162_rn(f1.z, f1.w);
            *(uint4*)(smem + row*SX + c*16) = *(uint4*)h;
        }
    }
    char* wsm = smem + 128*SX;
    for (int l = tid; l < NT*CPR; l += 256) {
        int row = l / CPR, c = l % CPR;
        *(uint4*)(wsm + row*SX + c*16) = *(const uint4*)(Wb + (long)row*KT + c*8);
    }
    __syncthreads();

    float acc[2][NF][4];
#pragma unroll
    for (int mt = 0; mt < 2; mt++)
#pragma unroll
        for (int nf = 0; nf < NF; nf++)
#pragma unroll
            for (int i = 0; i < 4; i++) acc[mt][nf][i] = 0.f;

    const uint32_t sb = smem_u32(smem);
    const uint32_t aoff = sb + (uint32_t)(warp_m*32 + (lane & 15))*SX + (uint32_t)(lane >> 4)*16;
    const uint32_t boff = sb + 128u*SX
        + (uint32_t)(warp_n*(NT/2) + ((lane >> 4) << 3) + (lane & 7))*SX
        + (uint32_t)((lane >> 3) & 1)*16;

#pragma unroll
    for (int k16 = 0; k16 < KT/16; k16++) {
        uint32_t a[2][4], b[NF/2][4];
#pragma unroll
        for (int mt = 0; mt < 2; mt++)
            LDSM4(a[mt], aoff + mt*16*SX + k16*32);
#pragma unroll
        for (int nf2 = 0; nf2 < NF/2; nf2++)
            LDSM4(b[nf2], boff + nf2*16*SX + k16*32);
#pragma unroll
        for (int mt = 0; mt < 2; mt++)
#pragma unroll
            for (int nf = 0; nf < NF; nf++) {
                const int nf2 = nf >> 1, hi = (nf & 1) * 2;
                MMA16816(acc[mt][nf], a[mt], b[nf2][hi], b[nf2][hi+1]);
            }
    }

    const int group = lane >> 2, tig = lane & 3;
#pragma unroll
    for (int mt = 0; mt < 2; mt++) {
        long r = r0 + warp_m*32 + mt*16 + group;
#pragma unroll
        for (int nf = 0; nf < NF; nf++) {
            int col = warp_n*(NT/2) + nf*8 + tig*2;
            float b0 = 0.f, b1 = 0.f;
            if (bias) { b0 = bias[col]; b1 = bias[col+1]; }
            float v00 = acc[mt][nf][0] + b0, v01 = acc[mt][nf][1] + b1;
            float v10 = acc[mt][nf][2] + b0, v11 = acc[mt][nf][3] + b1;
            if (RELU) {
                v00 = fmaxf(v00, 0.f); v01 = fmaxf(v01, 0.f);
                v10 = fmaxf(v10, 0.f); v11 = fmaxf(v11, 0.f);
            }
            if (OUTBF) {
                u16* O = (u16*)Out;
                __nv_bfloat162 h0 = __floats2bfloat162_rn(v00, v01);
                __nv_bfloat162 h1 = __floats2bfloat162_rn(v10, v11);
                *(uint32_t*)(O + r*NT + col)       = *(uint32_t*)&h0;
                *(uint32_t*)(O + (r + 8)*NT + col) = *(uint32_t*)&h1;
            } else {
                float* O = (float*)Out;
                *(float2*)(O + r*NT + col)       = make_float2(v00, v01);
                *(float2*)(O + (r + 8)*NT + col) = make_float2(v10, v11);
            }
        }
    }
}

// ================ prep kernels ================
__global__ void prep_phi(const float* __restrict__ phi, const float* __restrict__ dw,
                         u16* __restrict__ A2)
{
    long idx4 = (long)blockIdx.x * blockDim.x + threadIdx.x;
    long total4 = (long)SWAV * NNODES * NNODES / 4;
    if (idx4 >= total4) return;
    long idx = idx4 * 4;
    int s = (int)(idx >> 22);
    int i = (int)((idx >> 11) & 2047);
    int j0 = (int)(idx & 2047);
    float4 p = *(const float4*)(phi + idx);
    float4 d = *(const float4*)(dw + (long)s * NNODES + j0);
    u16 res[4];
    res[0] = f2bf(p.x * d.x); res[1] = f2bf(p.y * d.y);
    res[2] = f2bf(p.z * d.z); res[3] = f2bf(p.w * d.w);
    *(uint2*)(A2 + (long)i * KBIG + (long)s * NNODES + j0) = *(uint2*)res;
}

__global__ void prep_phinv(const float* __restrict__ pin, u16* __restrict__ B2)
{
    __shared__ float t[32][33];
    int s = blockIdx.z;
    int j0 = blockIdx.y * 32, n0 = blockIdx.x * 32;
    int tx = threadIdx.x, ty = threadIdx.y;
#pragma unroll
    for (int r = 0; r < 4; r++)
        t[ty + r*8][tx] = pin[((long)s << 22) + (long)(j0 + ty + r*8) * NNODES + n0 + tx];
    __syncthreads();
#pragma unroll
    for (int r = 0; r < 4; r++)
        B2[(long)(n0 + ty + r*8) * KBIG + (long)s * NNODES + j0 + tx] = f2bf(t[tx][ty + r*8]);
}

__global__ void prep_x(const float* __restrict__ x, u16* __restrict__ XT)
{
    __shared__ float t[32][33];
    int bt = blockIdx.z;
    int j0 = blockIdx.x * 32, c0 = blockIdx.y * 32;
    int tx = threadIdx.x, ty = threadIdx.y;
#pragma unroll
    for (int r = 0; r < 4; r++)
        t[ty + r*8][tx] = x[((long)bt * NNODES + j0 + ty + r*8) * CDIM + c0 + tx];
    __syncthreads();
#pragma unroll
    for (int r = 0; r < 4; r++)
        XT[(long)(bt * 64 + c0 + ty + r*8) * NNODES + j0 + tx] = f2bf(t[tx][ty + r*8]);
}

// flat fp32 -> bf16 conversion (vector of 4)
__global__ void conv_bf(const float* __restrict__ src, u16* __restrict__ dst, long n4)
{
    long i = (long)blockIdx.x * blockDim.x + threadIdx.x;
    if (i >= n4) return;
    float4 f = *(const float4*)(src + i*4);
    u16 r[4];
    r[0] = f2bf(f.x); r[1] = f2bf(f.y); r[2] = f2bf(f.z); r[3] = f2bf(f.w);
    *(uint2*)(dst + i*4) = *(uint2*)r;
}

// ---------------- linear attention, spatial (bf16 I/O) ----------------
__global__ __launch_bounds__(256)
void attn_spatial(const u16* __restrict__ qkv, u16* __restrict__ cat)
{
    const int bt = blockIdx.x;
    const int h  = blockIdx.y;
    const int tid = threadIdx.x;
    const int lane = tid & 31;
    const int warp = tid >> 5;
    const u16* base = qkv + (long)bt * NNODES * 192;

    float kvs[HDIM][HDIM];
    float ksum[HDIM];
#pragma unroll
    for (int m = 0; m < HDIM; m++) {
        ksum[m] = 0.f;
#pragma unroll
        for (int d = 0; d < HDIM; d++) kvs[m][d] = 0.f;
    }

    for (int n = tid; n < NNODES; n += 256) {
        float kk[HDIM], vv[HDIM];
        ld8bf(kk, base + (long)n * 192 + 64 + h * 8);
        ld8bf(vv, base + (long)n * 192 + 128 + h * 8);
        float s = 0.f;
#pragma unroll
        for (int m = 0; m < HDIM; m++) s += kk[m] * kk[m];
        float inv = 1.f / fmaxf(sqrtf(s), 1e-12f);
#pragma unroll
        for (int m = 0; m < HDIM; m++) {
            float km = kk[m] * inv;
            ksum[m] += km;
#pragma unroll
            for (int d = 0; d < HDIM; d++) kvs[m][d] = fmaf(km, vv[d], kvs[m][d]);
        }
    }

    __shared__ float red[8][72];
    __shared__ float fin[72];
#pragma unroll
    for (int m = 0; m < HDIM; m++) {
#pragma unroll
        for (int d = 0; d < HDIM; d++) {
            float v = kvs[m][d];
#pragma unroll
            for (int o = 16; o; o >>= 1) v += __shfl_down_sync(0xffffffffu, v, o);
            if (lane == 0) red[warp][m * 8 + d] = v;
        }
        float v = ksum[m];
#pragma unroll
        for (int o = 16; o; o >>= 1) v += __shfl_down_sync(0xffffffffu, v, o);
        if (lane == 0) red[warp][64 + m] = v;
    }
    __syncthreads();
    if (tid < 72) {
        float s = 0.f;
#pragma unroll
        for (int w = 0; w < 8; w++) s += red[w][tid];
        fin[tid] = s;
    }
    __syncthreads();

    float fkvs[HDIM][HDIM], fksum[HDIM];
#pragma unroll
    for (int m = 0; m < HDIM; m++) {
        fksum[m] = fin[64 + m];
#pragma unroll
        for (int d = 0; d < HDIM; d++) fkvs[m][d] = fin[m * 8 + d];
    }

    for (int n = tid; n < NNODES; n += 256) {
        float qq[HDIM], vv[HDIM];
        ld8bf(qq, base + (long)n * 192 + h * 8);
        ld8bf(vv, base + (long)n * 192 + 128 + h * 8);
        float s = 0.f;
#pragma unroll
        for (int m = 0; m < HDIM; m++) s += qq[m] * qq[m];
        float inv = 1.f / fmaxf(sqrtf(s), 1e-12f);
        float den = (float)NNODES;
#pragma unroll
        for (int m = 0; m < HDIM; m++) { qq[m] *= inv; den = fmaf(qq[m], fksum[m], den); }
        float invden = 1.f / fmaxf(den, 1e-5f);
        float o[HDIM];
#pragma unroll
        for (int d = 0; d < HDIM; d++) {
            float num = (float)NNODES * vv[d];
#pragma unroll
            for (int m = 0; m < HDIM; m++) num = fmaf(qq[m], fkvs[m][d], num);
            o[d] = num * invden;
        }
        st8bf(cat + ((long)bt * NNODES + n) * 128 + h * 8, o);
    }
}

// ---------------- linear attention, temporal (bf16 I/O) ----------------
__global__ __launch_bounds__(256)
void attn_temporal(const u16* __restrict__ qkv, u16* __restrict__ cat)
{
    int t = blockIdx.x * blockDim.x + threadIdx.x;
    if (t >= BB * NNODES * HH) return;
    const int h = t & 7;
    const int n = (t >> 3) & (NNODES - 1);
    const int b = t >> 14;

    float kvs[HDIM][HDIM];
    float ksum[HDIM];
#pragma unroll
    for (int m = 0; m < HDIM; m++) {
        ksum[m] = 0.f;
#pragma unroll
        for (int d = 0; d < HDIM; d++) kvs[m][d] = 0.f;
    }

    for (int l = 0; l < TT; l++) {
        const u16* p = qkv + (((long)(b * TT + l)) * NNODES + n) * 192;
        float kk[HDIM], vv[HDIM];
        ld8bf(kk, p + 64 + h * 8);
        ld8bf(vv, p + 128 + h * 8);
        float s = 0.f;
#pragma unroll
        for (int m = 0; m < HDIM; m++) s += kk[m] * kk[m];
        float inv = 1.f / fmaxf(sqrtf(s), 1e-12f);
#pragma unroll
        for (int m = 0; m < HDIM; m++) {
            float km = kk[m] * inv;
            ksum[m] += km;
#pragma unroll
            for (int d = 0; d < HDIM; d++) kvs[m][d] = fmaf(km, vv[d], kvs[m][d]);
        }
    }

    for (int l = 0; l < TT; l++) {
        const u16* p = qkv + (((long)(b * TT + l)) * NNODES + n) * 192;
        float qq[HDIM], vv[HDIM];
        ld8bf(qq, p + h * 8);
        ld8bf(vv, p + 128 + h * 8);
        float s = 0.f;
#pragma unroll
        for (int m = 0; m < HDIM; m++) s += qq[m] * qq[m];
        float inv = 1.f / fmaxf(sqrtf(s), 1e-12f);
        float den = (float)TT;
#pragma unroll
        for (int m = 0; m < HDIM; m++) { qq[m] *= inv; den = fmaf(qq[m], ksum[m], den); }
        float invden = 1.f / fmaxf(den, 1e-5f);
        float o[HDIM];
#pragma unroll
        for (int d = 0; d < HDIM; d++) {
            float num = (float)TT * vv[d];
#pragma unroll
            for (int m = 0; m < HDIM; m++) num = fmaf(qq[m], kvs[m][d], num);
            o[d] = num * invden;
        }
        st8bf(cat + (((long)(b * TT + l)) * NNODES + n) * 128 + 64 + h * 8, o);
    }
}

// ---------------- fused x_glo + LayerNorm1 (paired columns) ----------------
__global__ __launch_bounds__(256)
void glo_ln_kernel(const float* __restrict__ x,  const u16* __restrict__ a0,
                   const u16* __restrict__ a1, const u16* __restrict__ p0,
                   const u16* __restrict__ p1, const float* __restrict__ g,
                   const float* __restrict__ be, float* __restrict__ y)
{
    long row = ((long)blockIdx.x * blockDim.x + threadIdx.x) >> 5;
    int lane = threadIdx.x & 31;
    if (row >= ROWS) return;
    long base = row * 64;
    int c = 2 * lane;
    float2 xv = *(const float2*)(x + base + c);
    float2 a0v = __bfloat1622float2(*(const __nv_bfloat162*)(a0 + base + c));
    float2 a1v = __bfloat1622float2(*(const __nv_bfloat162*)(a1 + base + c));
    float2 p0v = __bfloat1622float2(*(const __nv_bfloat162*)(p0 + base + c));
    float2 p1v = __bfloat1622float2(*(const __nv_bfloat162*)(p1 + base + c));
    float v0 = 2.f * (xv.x + a0v.x*p0v.x + a1v.x*p1v.x*0.01f);
    float v1 = 2.f * (xv.y + a0v.y*p0v.y + a1v.y*p1v.y*0.01f);
    float s = v0 + v1;
#pragma unroll
    for (int o = 16; o; o >>= 1) s += __shfl_xor_sync(0xffffffffu, s, o);
    float mean = s * (1.f / 64.f);
    float d0 = v0 - mean, d1 = v1 - mean;
    float vs = d0 * d0 + d1 * d1;
#pragma unroll
    for (int o = 16; o; o >>= 1) vs += __shfl_xor_sync(0xffffffffu, vs, o);
    float r = rsqrtf(vs * (1.f / 64.f) + 1e-5f);
    float2 out = make_float2(d0 * r * g[c] + be[c], d1 * r * g[c+1] + be[c+1]);
    *(float2*)(y + base + c) = out;
}

// ---------------- fused residual + LayerNorm2 -> output ----------------
__global__ __launch_bounds__(256)
void final_ln_kernel(const float* __restrict__ y, const u16* __restrict__ h2,
                     const float* __restrict__ g, const float* __restrict__ be,
                     float* __restrict__ out)
{
    long row = ((long)blockIdx.x * blockDim.x + threadIdx.x) >> 5;
    int lane = threadIdx.x & 31;
    if (row >= ROWS) return;
    long base = row * 64;
    int c = 2 * lane;
    float2 yv = *(const float2*)(y + base + c);
    float2 hv = __bfloat1622float2(*(const __nv_bfloat162*)(h2 + base + c));
    float v0 = yv.x + hv.x;
    float v1 = yv.y + hv.y;
    float s = v0 + v1;
#pragma unroll
    for (int o = 16; o; o >>= 1) s += __shfl_xor_sync(0xffffffffu, s, o);
    float mean = s * (1.f / 64.f);
    float d0 = v0 - mean, d1 = v1 - mean;
    float vs = d0 * d0 + d1 * d1;
#pragma unroll
    for (int o = 16; o; o >>= 1) vs += __shfl_xor_sync(0xffffffffu, vs, o);
    float r = rsqrtf(vs * (1.f / 64.f) + 1e-5f);
    *(float2*)(out + base + c) = make_float2(d0 * r * g[c] + be[c], d1 * r * g[c+1] + be[c+1]);
}

// ---------------- host launcher ----------------
extern "C" void kernel_launch(void* const* d_in, const int* in_sizes, int n_in,
                              void* d_out, int out_size)
{
    const float* x     = (const float*)d_in[0];
    const float* phi   = (const float*)d_in[1];
    const float* phinv = (const float*)d_in[2];
    const float* diagw = (const float*)d_in[3];
    const float* qkv0w = (const float*)d_in[4];
    const float* out0w = (const float*)d_in[5];
    const float* out0b = (const float*)d_in[6];
    const float* qkv1w = (const float*)d_in[7];
    const float* out1w = (const float*)d_in[8];
    const float* out1b = (const float*)d_in[9];
    const float* pw0w  = (const float*)d_in[10];
    const float* pw0b  = (const float*)d_in[11];
    const float* pw1w  = (const float*)d_in[12];
    const float* pw1b  = (const float*)d_in[13];
    const float* fc1w  = (const float*)d_in[14];
    const float* fc1b  = (const float*)d_in[15];
    const float* fc2w  = (const float*)d_in[16];
    const float* fc2b  = (const float*)d_in[17];
    const float* ln1g  = (const float*)d_in[18];
    const float* ln1b  = (const float*)d_in[19];
    const float* ln2g  = (const float*)d_in[20];
    const float* ln2b  = (const float*)d_in[21];

    u16 *a2, *b2, *msumbf, *xt, *xb, *xk, *qkvb, *catb, *att0, *att1, *p0, *p1, *hid, *h2;
    u16 *wqkv0, *wout0, *wqkv1, *wout1, *wpw0, *wpw1, *wfc1, *wfc2;
    float *yb;
    cudaGetSymbolAddress((void**)&a2,     g_a2);
    cudaGetSymbolAddress((void**)&b2,     g_b2);
    cudaGetSymbolAddress((void**)&msumbf, g_msumbf);
    cudaGetSymbolAddress((void**)&xt,     g_xt);
    cudaGetSymbolAddress((void**)&xb,     g_xb);
    cudaGetSymbolAddress((void**)&xk,     g_xk);
    cudaGetSymbolAddress((void**)&qkvb,   g_qkv);
    cudaGetSymbolAddress((void**)&catb,   g_cat);
    cudaGetSymbolAddress((void**)&att0,   g_att0);
    cudaGetSymbolAddress((void**)&att1,   g_att1);
    cudaGetSymbolAddress((void**)&p0,     g_p0);
    cudaGetSymbolAddress((void**)&p1,     g_p1);
    cudaGetSymbolAddress((void**)&hid,    g_hid);
    cudaGetSymbolAddress((void**)&h2,     g_h2);
    cudaGetSymbolAddress((void**)&yb,     g_y);
    cudaGetSymbolAddress((void**)&wqkv0,  g_wqkv0);
    cudaGetSymbolAddress((void**)&wout0,  g_wout0);
    cudaGetSymbolAddress((void**)&wqkv1,  g_wqkv1);
    cudaGetSymbolAddress((void**)&wout1,  g_wout1);
    cudaGetSymbolAddress((void**)&wpw0,   g_wpw0);
    cudaGetSymbolAddress((void**)&wpw1,   g_wpw1);
    cudaGetSymbolAddress((void**)&wfc1,   g_wfc1);
    cudaGetSymbolAddress((void**)&wfc2,   g_wfc2);

    // rowgemm variants + dynamic smem sizes
    auto rg_qkv = rowgemm<192, 64, false, true,  false>;
    auto rg_out = rowgemm<64, 128, false, true,  false>;
    auto rg_pw  = rowgemm<64,  64, false, true,  false>;
    auto rg_fc1 = rowgemm<128, 64, true,  true,  true >;
    const int SM_QKV = (128+192)*(64*2+16);   // 46080
    const int SM_OUT = (128+64)*(128*2+16);   // 52224
    const int SM_PW  = (128+64)*(64*2+16);    // 27648
    const int SM_FC1 = (128+128)*(64*2+16);   // 36864
    cudaFuncSetAttribute(rg_qkv, cudaFuncAttributeMaxDynamicSharedMemorySize, SM_QKV);
    cudaFuncSetAttribute(rg_out, cudaFuncAttributeMaxDynamicSharedMemorySize, SM_OUT);
    cudaFuncSetAttribute(rg_pw,  cudaFuncAttributeMaxDynamicSharedMemorySize, SM_PW);
    cudaFuncSetAttribute(rg_fc1, cudaFuncAttributeMaxDynamicSharedMemorySize, SM_FC1);

    const unsigned RB = (unsigned)(ROWS / 128);  // 3072

    // 1) weight + x conversions, bf16 layout prep
    conv_bf<<<(unsigned)((ROWS*64/4 + 255)/256), 256>>>(x, xb, ROWS*64/4);
    conv_bf<<<12, 256>>>(qkv0w, wqkv0, 12288/4);
    conv_bf<<<8,  256>>>(out0w, wout0, 8192/4);
    conv_bf<<<12, 256>>>(qkv1w, wqkv1, 12288/4);
    conv_bf<<<8,  256>>>(out1w, wout1, 8192/4);
    conv_bf<<<4,  256>>>(pw0w,  wpw0,  4096/4);
    conv_bf<<<4,  256>>>(pw1w,  wpw1,  4096/4);
    conv_bf<<<8,  256>>>(fc1w,  wfc1,  8192/4);
    conv_bf<<<8,  256>>>(fc2w,  wfc2,  8192/4);
    {
        long total4 = (long)SWAV * NNODES * NNODES / 4;
        prep_phi<<<(unsigned)((total4 + 255) / 256), 256>>>(phi, diagw, a2);
    }
    prep_phinv<<<dim3(NNODES/32, NNODES/32, SWAV), dim3(32, 8)>>>(phinv, b2);
    prep_x<<<dim3(NNODES/32, CDIM/32, BT), dim3(32, 8)>>>(x, xt);

    // 2) Msum (2048x2048x8192) and x_k (2048x12288x2048), bf16 tensor cores
    mma_gemm<0><<<dim3(16, 16), 256>>>(a2, b2, KBIG, KBIG, KBIG, msumbf);
    mma_gemm<1><<<dim3(NXK/128, 16), 256>>>(msumbf, xt, NNODES, NNODES, NNODES, xk);

    // 3) attention layer 0 on x
    rg_qkv<<<RB, 256, SM_QKV>>>(xb, wqkv0, nullptr, qkvb);
    attn_spatial<<<dim3(BT, HH), 256>>>(qkvb, catb);
    attn_temporal<<<(BB * NNODES * HH + 255) / 256, 256>>>(qkvb, catb);
    rg_out<<<RB, 256, SM_OUT>>>(catb, wout0, out0b, att0);

    // 4) attention layer 1 on x_k
    rg_qkv<<<RB, 256, SM_QKV>>>(xk, wqkv1, nullptr, qkvb);
    attn_spatial<<<dim3(BT, HH), 256>>>(qkvb, catb);
    attn_temporal<<<(BB * NNODES * HH + 255) / 256, 256>>>(qkvb, catb);
    rg_out<<<RB, 256, SM_OUT>>>(catb, wout1, out1b, att1);

    // 5) pointwise gates
    rg_pw<<<RB, 256, SM_PW>>>(xb,   wpw0, pw0b, p0);
    rg_pw<<<RB, 256, SM_PW>>>(att0, wpw1, pw1b, p1);

    // 6) y = LN1(2 * (x + att0*p0 + 0.01*att1*p1))
    glo_ln_kernel<<<(unsigned)(ROWS / 8), 256>>>(x, att0, att1, p0, p1, ln1g, ln1b, yb);

    // 7) MLP
    rg_fc1<<<RB, 256, SM_FC1>>>(yb, wfc1, fc1b, hid);
    rg_out<<<RB, 256, SM_OUT>>>(hid, wfc2, fc2b, h2);

    // 8) out = LN2(y + h)
    final_ln_kernel<<<(unsigned)(ROWS / 8), 256>>>(yb, h2, ln2g, ln2b, (float*)d_out);
}

// round 7
// speedup vs baseline: 3.4705x; 1.0153x over previous
#include <cuda_runtime.h>
#include <cuda_bf16.h>
#include <math.h>
#include <stdint.h>

#define BB 8
#define TT 24
#define NNODES 2048
#define CDIM 64
#define HH 8
#define HDIM 8
#define SWAV 4
#define BT (BB*TT)              // 192
#define ROWS ((long)BT*NNODES)  // 393216
#define KBIG (SWAV*NNODES)      // 8192
#define NXK (BT*CDIM)           // 12288

typedef unsigned short u16;

// ---------------- scratch ----------------
__device__ u16 g_a2[(long)NNODES*KBIG];
__device__ u16 g_b2[(long)NNODES*KBIG];
__device__ u16 g_msumbf[(long)NNODES*NNODES];
__device__ u16 g_xt[(long)NXK*NNODES];
__device__ u16 g_xb  [ROWS*CDIM];
__device__ u16 g_xk  [ROWS*CDIM];
__device__ u16 g_qkv [ROWS*3*CDIM];
__device__ u16 g_cat [ROWS*2*CDIM];
__device__ u16 g_att0[ROWS*CDIM];
__device__ u16 g_p0  [ROWS*CDIM];
__device__ u16 g_p1  [ROWS*CDIM];
__device__ float g_y [ROWS*CDIM];
__device__ u16 g_wqkv0[3*CDIM*CDIM];
__device__ u16 g_wout0[CDIM*2*CDIM];
__device__ u16 g_wqkv1[3*CDIM*CDIM];
__device__ u16 g_wout1[CDIM*2*CDIM];
__device__ u16 g_wpw0 [CDIM*CDIM];
__device__ u16 g_wpw1 [CDIM*CDIM];
__device__ u16 g_wfc1 [2*CDIM*CDIM];
__device__ u16 g_wfc2 [CDIM*2*CDIM];

__device__ __forceinline__ uint32_t smem_u32(const void* p){
    uint32_t a;
    asm("{ .reg .u64 t; cvta.to.shared.u64 t, %1; cvt.u32.u64 %0, t; }" : "=r"(a) : "l"(p));
    return a;
}
__device__ __forceinline__ u16 f2bf(float v){
    __nv_bfloat16 h = __float2bfloat16(v);
    return *(u16*)&h;
}
__device__ __forceinline__ void ld8bf(float* f, const u16* p){
    uint4 u = *(const uint4*)p;
    const __nv_bfloat162* h = (const __nv_bfloat162*)&u;
#pragma unroll
    for (int i = 0; i < 4; i++) { float2 t = __bfloat1622float2(h[i]); f[2*i] = t.x; f[2*i+1] = t.y; }
}
__device__ __forceinline__ void st8bf(u16* p, const float* f){
    __nv_bfloat162 h[4];
#pragma unroll
    for (int i = 0; i < 4; i++) h[i] = __floats2bfloat162_rn(f[2*i], f[2*i+1]);
    *(uint4*)p = *(uint4*)h;
}

#define LDSM4(r, addr) \
    asm volatile("ldmatrix.sync.aligned.m8n8.x4.shared.b16 {%0,%1,%2,%3}, [%4];" \
        : "=r"((r)[0]), "=r"((r)[1]), "=r"((r)[2]), "=r"((r)[3]) : "r"(addr))

#define MMA16816(c, a, b0, b1) \
    asm volatile("mma.sync.aligned.m16n8k16.row.col.f32.bf16.bf16.f32 " \
        "{%0,%1,%2,%3}, {%4,%5,%6,%7}, {%8,%9}, {%0,%1,%2,%3};" \
        : "+f"((c)[0]), "+f"((c)[1]), "+f"((c)[2]), "+f"((c)[3]) \
        : "r"((a)[0]), "r"((a)[1]), "r"((a)[2]), "r"((a)[3]), "r"(b0), "r"(b1))

// generic smem-resident MMA stage: acc[mt*NF+nf] += Atile(128xKT) * Btile(NTxKT)^T
template<int NT, int KT, int SXA, int SXB>
__device__ __forceinline__ void mma_stage(uint32_t sa, uint32_t sbm, int lane,
                                          int warp_m, int warp_n, float (*acc)[4])
{
    constexpr int NF = NT/16;
    const uint32_t aoff = sa + (uint32_t)(warp_m*32 + (lane & 15))*SXA + (uint32_t)(lane >> 4)*16;
    const uint32_t boff = sbm + (uint32_t)(warp_n*(NT/2) + ((lane >> 4) << 3) + (lane & 7))*SXB
                        + (uint32_t)((lane >> 3) & 1)*16;
#pragma unroll
    for (int k16 = 0; k16 < KT/16; k16++) {
        uint32_t a[2][4], b[NF/2][4];
#pragma unroll
        for (int mt = 0; mt < 2; mt++)
            LDSM4(a[mt], aoff + mt*16*SXA + k16*32);
#pragma unroll
        for (int nf2 = 0; nf2 < NF/2; nf2++)
            LDSM4(b[nf2], boff + nf2*16*SXB + k16*32);
#pragma unroll
        for (int mt = 0; mt < 2; mt++)
#pragma unroll
            for (int nf = 0; nf < NF; nf++) {
                const int nf2 = nf >> 1, hi = (nf & 1) * 2;
                MMA16816(acc[mt*NF+nf], a[mt], b[nf2][hi], b[nf2][hi+1]);
            }
    }
}

// ================ big mma GEMM (unchanged from R4) ================
template<int EPI>
__global__ __launch_bounds__(256)
void mma_gemm(const u16* __restrict__ A, const u16* __restrict__ B,
              int K, int ldA, int ldB, void* __restrict__ Cout)
{
    __shared__ __align__(16) char smem[2 * 20480];
    const int tid  = threadIdx.x;
    const int lane = tid & 31;
    const int w    = tid >> 5;
    const int warp_m = w & 3;
    const int warp_n = w >> 2;
    const long m0 = (long)blockIdx.y * 128;
    const long n0 = (long)blockIdx.x * 128;
    const u16* Ab = A + m0 * ldA;
    const u16* Bb = B + n0 * ldB;

    const uint32_t sbase = smem_u32(smem);
    const int r0w = tid >> 2;
    const int kc  = tid & 3;

    const uint32_t aoff = (uint32_t)(warp_m*32 + (lane & 15))*80 + (uint32_t)(lane >> 4)*16;
    const uint32_t boff = (uint32_t)(warp_n*64 + ((lane >> 4) << 3) + (lane & 7))*80
                        + (uint32_t)((lane >> 3) & 1)*16 + 10240;

    float acc[2][8][4];
#pragma unroll
    for (int mt = 0; mt < 2; mt++)
#pragma unroll
        for (int nt = 0; nt < 8; nt++)
#pragma unroll
            for (int i = 0; i < 4; i++) acc[mt][nt][i] = 0.f;

#pragma unroll
    for (int i = 0; i < 2; i++) {
        int row = r0w + i*64;
        uint4 va = *(const uint4*)(Ab + (long)row*ldA + kc*8);
        uint4 vb = *(const uint4*)(Bb + (long)row*ldB + kc*8);
        *(uint4*)(smem + row*80 + kc*16) = va;
        *(uint4*)(smem + 10240 + row*80 + kc*16) = vb;
    }
    __syncthreads();

    const int T = K >> 5;
    for (int t = 0; t < T; t++) {
        uint4 pa[2], pb[2];
        if (t + 1 < T) {
            const int kt = (t + 1) << 5;
#pragma unroll
            for (int i = 0; i < 2; i++) {
                int row = r0w + i*64;
                pa[i] = *(const uint4*)(Ab + (long)row*ldA + kt + kc*8);
                pb[i] = *(const uint4*)(Bb + (long)row*ldB + kt + kc*8);
            }
        }
        const uint32_t sA = sbase + (uint32_t)(t & 1)*20480;
#pragma unroll
        for (int k16 = 0; k16 < 2; k16++) {
            uint32_t a[2][4], b[4][4];
#pragma unroll
            for (int mt = 0; mt < 2; mt++)
                LDSM4(a[mt], sA + aoff + mt*1280 + k16*32);
#pragma unroll
            for (int nt2 = 0; nt2 < 4; nt2++)
                LDSM4(b[nt2], sA + boff + nt2*1280 + k16*32);
#pragma unroll
            for (int mt = 0; mt < 2; mt++)
#pragma unroll
                for (int nt = 0; nt < 8; nt++) {
                    const int nt2 = nt >> 1, hi = (nt & 1) * 2;
                    MMA16816(acc[mt][nt], a[mt], b[nt2][hi], b[nt2][hi+1]);
                }
        }
        if (t + 1 < T) {
            char* d = smem + ((t + 1) & 1)*20480;
#pragma unroll
            for (int i = 0; i < 2; i++) {
                int row = r0w + i*64;
                *(uint4*)(d + row*80 + kc*16) = pa[i];
                *(uint4*)(d + 10240 + row*80 + kc*16) = pb[i];
            }
        }
        __syncthreads();
    }

    const int group = lane >> 2, tig = lane & 3;
    if (EPI == 0) {
        u16* C = (u16*)Cout;
#pragma unroll
        for (int mt = 0; mt < 2; mt++) {
            long rbase = m0 + warp_m*32 + mt*16;
#pragma unroll
            for (int nt = 0; nt < 8; nt++) {
                long col = n0 + warp_n*64 + nt*8 + tig*2;
                __nv_bfloat162 h0 = __floats2bfloat162_rn(acc[mt][nt][0], acc[mt][nt][1]);
                __nv_bfloat162 h1 = __floats2bfloat162_rn(acc[mt][nt][2], acc[mt][nt][3]);
                *(uint32_t*)(C + (rbase + group)*2048 + col)     = *(uint32_t*)&h0;
                *(uint32_t*)(C + (rbase + 8 + group)*2048 + col) = *(uint32_t*)&h1;
            }
        }
    } else {
        u16* Xk = (u16*)Cout;
        const long bt = (n0 + warp_n*64) >> 6;
        u16* obase = Xk + bt * (long)NNODES * 64;
#pragma unroll
        for (int mt = 0; mt < 2; mt++) {
            long r = m0 + warp_m*32 + mt*16 + group;
#pragma unroll
            for (int nt = 0; nt < 8; nt++) {
                int cin = nt*8 + tig*2;
                __nv_bfloat162 h0 = __floats2bfloat162_rn(acc[mt][nt][0], acc[mt][nt][1]);
                __nv_bfloat162 h1 = __floats2bfloat162_rn(acc[mt][nt][2], acc[mt][nt][3]);
                *(uint32_t*)(obase + r*64 + cin)       = *(uint32_t*)&h0;
                *(uint32_t*)(obase + (r + 8)*64 + cin) = *(uint32_t*)&h1;
            }
        }
    }
}

// ================ rowgemm (qkv + pw0) ================
template<int NT, int KT, bool RELU, bool OUTBF, bool INF32>
__global__ __launch_bounds__(256)
void rowgemm(const void* __restrict__ Xin, const u16* __restrict__ Wb,
             const float* __restrict__ bias, void* __restrict__ Out)
{
    constexpr int SX  = KT*2 + 16;
    constexpr int CPR = (KT*2)/16;
    constexpr int NF  = NT/16;
    extern __shared__ __align__(16) char smem[];
    const int tid = threadIdx.x, lane = tid & 31, w = tid >> 5;
    const int warp_m = w & 3, warp_n = w >> 2;
    const long r0 = (long)blockIdx.x * 128;

    {
        const u16* X = (const u16*)Xin + r0*KT;
        for (int l = tid; l < 128*CPR; l += 256) {
            int row = l / CPR, c = l % CPR;
            *(uint4*)(smem + row*SX + c*16) = *(const uint4*)(X + (long)row*KT + c*8);
        }
    }
    char* wsm = smem + 128*SX;
    for (int l = tid; l < NT*CPR; l += 256) {
        int row = l / CPR, c = l % CPR;
        *(uint4*)(wsm + row*SX + c*16) = *(const uint4*)(Wb + (long)row*KT + c*8);
    }
    __syncthreads();

    float acc[2*NF][4];
#pragma unroll
    for (int i = 0; i < 2*NF; i++)
#pragma unroll
        for (int j = 0; j < 4; j++) acc[i][j] = 0.f;

    const uint32_t sb = smem_u32(smem);
    mma_stage<NT, KT, SX, SX>(sb, sb + 128u*SX, lane, warp_m, warp_n, acc);

    const int group = lane >> 2, tig = lane & 3;
#pragma unroll
    for (int mt = 0; mt < 2; mt++) {
        long r = r0 + warp_m*32 + mt*16 + group;
#pragma unroll
        for (int nf = 0; nf < NF; nf++) {
            int col = warp_n*(NT/2) + nf*8 + tig*2;
            float b0 = 0.f, b1 = 0.f;
            if (bias) { b0 = bias[col]; b1 = bias[col+1]; }
            float v00 = acc[mt*NF+nf][0] + b0, v01 = acc[mt*NF+nf][1] + b1;
            float v10 = acc[mt*NF+nf][2] + b0, v11 = acc[mt*NF+nf][3] + b1;
            if (RELU) {
                v00 = fmaxf(v00, 0.f); v01 = fmaxf(v01, 0.f);
                v10 = fmaxf(v10, 0.f); v11 = fmaxf(v11, 0.f);
            }
            u16* O = (u16*)Out;
            __nv_bfloat162 h0 = __floats2bfloat162_rn(v00, v01);
            __nv_bfloat162 h1 = __floats2bfloat162_rn(v10, v11);
            *(uint32_t*)(O + r*NT + col)       = *(uint32_t*)&h0;
            *(uint32_t*)(O + (r + 8)*NT + col) = *(uint32_t*)&h1;
        }
    }
}

// ================ fused out-proj0 + pw1 ================
// att0 = cat @ Wout0^T + b1 (write global + smem); p1 = att0 @ Wpw1^T + b2 (write global)
__global__ __launch_bounds__(256)
void fused_out_pw(const u16* __restrict__ cat, const u16* __restrict__ w1,
                  const float* __restrict__ b1, const u16* __restrict__ w2,
                  const float* __restrict__ b2, u16* __restrict__ att0,
                  u16* __restrict__ p1)
{
    constexpr int SX1 = 272;   // 128 bf16 + pad
    constexpr int SX2 = 144;   // 64 bf16 + pad
    extern __shared__ __align__(16) char smem[];
    char* Xs = smem;                         // 128*272 = 34816
    char* W1 = Xs + 128*SX1;                 // 64*272 = 17408
    char* As = W1 + 64*SX1;                  // 128*144 = 18432
    char* W2 = As + 128*SX2;                 // 64*144 = 9216
    const int tid = threadIdx.x, lane = tid & 31, w = tid >> 5;
    const int warp_m = w & 3, warp_n = w >> 2;
    const long r0 = (long)blockIdx.x * 128;

    {
        const u16* X = cat + r0*128;
        for (int l = tid; l < 128*16; l += 256) {
            int row = l >> 4, c = l & 15;
            *(uint4*)(Xs + row*SX1 + c*16) = *(const uint4*)(X + (long)row*128 + c*8);
        }
        for (int l = tid; l < 64*16; l += 256) {
            int row = l >> 4, c = l & 15;
            *(uint4*)(W1 + row*SX1 + c*16) = *(const uint4*)(w1 + (long)row*128 + c*8);
        }
        for (int l = tid; l < 64*8; l += 256) {
            int row = l >> 3, c = l & 7;
            *(uint4*)(W2 + row*SX2 + c*16) = *(const uint4*)(w2 + (long)row*64 + c*8);
        }
    }
    __syncthreads();

    float acc[8][4];
#pragma unroll
    for (int i = 0; i < 8; i++)
#pragma unroll
        for (int j = 0; j < 4; j++) acc[i][j] = 0.f;
    const uint32_t sb = smem_u32(smem);
    mma_stage<64, 128, SX1, SX1>(sb, sb + 128u*SX1, lane, warp_m, warp_n, acc);

    const int group = lane >> 2, tig = lane & 3;
    const uint32_t asb = sb + 128u*SX1 + 64u*SX1;
#pragma unroll
    for (int mt = 0; mt < 2; mt++) {
        int rl = warp_m*32 + mt*16 + group;
#pragma unroll
        for (int nf = 0; nf < 4; nf++) {
            int col = warp_n*32 + nf*8 + tig*2;
            float b0 = b1[col], bb1 = b1[col+1];
            __nv_bfloat162 h0 = __floats2bfloat162_rn(acc[mt*4+nf][0]+b0, acc[mt*4+nf][1]+bb1);
            __nv_bfloat162 h1 = __floats2bfloat162_rn(acc[mt*4+nf][2]+b0, acc[mt*4+nf][3]+bb1);
            *(uint32_t*)(As + rl*SX2 + col*2)       = *(uint32_t*)&h0;
            *(uint32_t*)(As + (rl+8)*SX2 + col*2)   = *(uint32_t*)&h1;
            *(uint32_t*)(att0 + (r0+rl)*64 + col)   = *(uint32_t*)&h0;
            *(uint32_t*)(att0 + (r0+rl+8)*64 + col) = *(uint32_t*)&h1;
        }
    }
    __syncthreads();

    float acc2[8][4];
#pragma unroll
    for (int i = 0; i < 8; i++)
#pragma unroll
        for (int j = 0; j < 4; j++) acc2[i][j] = 0.f;
    mma_stage<64, 64, SX2, SX2>(asb, asb + 128u*SX2, lane, warp_m, warp_n, acc2);

#pragma unroll
    for (int mt = 0; mt < 2; mt++) {
        long r = r0 + warp_m*32 + mt*16 + group;
#pragma unroll
        for (int nf = 0; nf < 4; nf++) {
            int col = warp_n*32 + nf*8 + tig*2;
            float b0 = b2[col], bb1 = b2[col+1];
            __nv_bfloat162 h0 = __floats2bfloat162_rn(acc2[mt*4+nf][0]+b0, acc2[mt*4+nf][1]+bb1);
            __nv_bfloat162 h1 = __floats2bfloat162_rn(acc2[mt*4+nf][2]+b0, acc2[mt*4+nf][3]+bb1);
            *(uint32_t*)(p1 + r*64 + col)     = *(uint32_t*)&h0;
            *(uint32_t*)(p1 + (r+8)*64 + col) = *(uint32_t*)&h1;
        }
    }
}

// ================ fused out-proj1 + x_glo + LN1 ================
__global__ __launch_bounds__(256)
void fused_out_ln(const u16* __restrict__ cat, const u16* __restrict__ w1,
                  const float* __restrict__ b1, const float* __restrict__ x,
                  const u16* __restrict__ att0, const u16* __restrict__ p0,
                  const u16* __restrict__ p1, const float* __restrict__ g,
                  const float* __restrict__ be, float* __restrict__ y)
{
    constexpr int SX1 = 272;
    constexpr int SX2 = 144;
    extern __shared__ __align__(16) char smem[];
    char* Xs = smem;
    char* W1 = Xs + 128*SX1;
    char* As = W1 + 64*SX1;      // att1 tile 128x144
    const int tid = threadIdx.x, lane = tid & 31, w = tid >> 5;
    const int warp_m = w & 3, warp_n = w >> 2;
    const long r0 = (long)blockIdx.x * 128;

    {
        const u16* X = cat + r0*128;
        for (int l = tid; l < 128*16; l += 256) {
            int row = l >> 4, c = l & 15;
            *(uint4*)(Xs + row*SX1 + c*16) = *(const uint4*)(X + (long)row*128 + c*8);
        }
        for (int l = tid; l < 64*16; l += 256) {
            int row = l >> 4, c = l & 15;
            *(uint4*)(W1 + row*SX1 + c*16) = *(const uint4*)(w1 + (long)row*128 + c*8);
        }
    }
    __syncthreads();

    float acc[8][4];
#pragma unroll
    for (int i = 0; i < 8; i++)
#pragma unroll
        for (int j = 0; j < 4; j++) acc[i][j] = 0.f;
    const uint32_t sb = smem_u32(smem);
    mma_stage<64, 128, SX1, SX1>(sb, sb + 128u*SX1, lane, warp_m, warp_n, acc);

    const int group = lane >> 2, tig = lane & 3;
#pragma unroll
    for (int mt = 0; mt < 2; mt++) {
        int rl = warp_m*32 + mt*16 + group;
#pragma unroll
        for (int nf = 0; nf < 4; nf++) {
            int col = warp_n*32 + nf*8 + tig*2;
            float b0 = b1[col], bb1 = b1[col+1];
            __nv_bfloat162 h0 = __floats2bfloat162_rn(acc[mt*4+nf][0]+b0, acc[mt*4+nf][1]+bb1);
            __nv_bfloat162 h1 = __floats2bfloat162_rn(acc[mt*4+nf][2]+b0, acc[mt*4+nf][3]+bb1);
            *(uint32_t*)(As + rl*SX2 + col*2)     = *(uint32_t*)&h0;
            *(uint32_t*)(As + (rl+8)*SX2 + col*2) = *(uint32_t*)&h1;
        }
    }
    __syncthreads();

    // LN phase: warp per row, 16 rows per warp, 2 cols per lane
    const int c = 2 * lane;
    for (int i = 0; i < 16; i++) {
        int rl = w*16 + i;
        long base = (r0 + rl) * 64;
        float2 xv  = *(const float2*)(x + base + c);
        float2 a0v = __bfloat1622float2(*(const __nv_bfloat162*)(att0 + base + c));
        float2 p0v = __bfloat1622float2(*(const __nv_bfloat162*)(p0 + base + c));
        float2 p1v = __bfloat1622float2(*(const __nv_bfloat162*)(p1 + base + c));
        float2 a1v = __bfloat1622float2(*(const __nv_bfloat162*)(As + rl*SX2 + c*2));
        float v0 = 2.f * (xv.x + a0v.x*p0v.x + a1v.x*p1v.x*0.01f);
        float v1 = 2.f * (xv.y + a0v.y*p0v.y + a1v.y*p1v.y*0.01f);
        float s = v0 + v1;
#pragma unroll
        for (int o = 16; o; o >>= 1) s += __shfl_xor_sync(0xffffffffu, s, o);
        float mean = s * (1.f / 64.f);
        float d0 = v0 - mean, d1 = v1 - mean;
        float vs = d0 * d0 + d1 * d1;
#pragma unroll
        for (int o = 16; o; o >>= 1) vs += __shfl_xor_sync(0xffffffffu, vs, o);
        float r = rsqrtf(vs * (1.f / 64.f) + 1e-5f);
        *(float2*)(y + base + c) = make_float2(d0*r*g[c] + be[c], d1*r*g[c+1] + be[c+1]);
    }
}

// ================ fused fc1 + relu + fc2 + residual + LN2 ================
__global__ __launch_bounds__(256)
void fused_mlp_ln(const float* __restrict__ y, const u16* __restrict__ w1,
                  const float* __restrict__ b1, const u16* __restrict__ w2,
                  const float* __restrict__ b2, const float* __restrict__ g,
                  const float* __restrict__ be, float* __restrict__ out)
{
    constexpr int SXY = 144;   // y bf16 row (64) + pad ; reused for h2
    constexpr int SXH = 272;   // hid row (128 bf16) + pad
    extern __shared__ __align__(16) char smem[];
    char* Ys = smem;                  // 128*144 = 18432
    char* W1 = Ys + 128*SXY;          // 128*144 = 18432
    char* Hs = W1 + 128*SXY;          // 128*272 = 34816
    char* W2 = Hs + 128*SXH;          // 64*272 = 17408
    const int tid = threadIdx.x, lane = tid & 31, w = tid >> 5;
    const int warp_m = w & 3, warp_n = w >> 2;
    const long r0 = (long)blockIdx.x * 128;

    {
        const float* Y = y + r0*64;
        for (int l = tid; l < 128*8; l += 256) {
            int row = l >> 3, c = l & 7;
            float4 f0 = *(const float4*)(Y + (long)row*64 + c*8);
            float4 f1 = *(const float4*)(Y + (long)row*64 + c*8 + 4);
            __nv_bfloat162 h[4];
            h[0] = __floats2bfloat162_rn(f0.x, f0.y);
            h[1] = __floats2bfloat162_rn(f0.z, f0.w);
            h[2] = __floats2bfloat162_rn(f1.x, f1.y);
            h[3] = __floats2bfloat162_rn(f1.z, f1.w);
            *(uint4*)(Ys + row*SXY + c*16) = *(uint4*)h;
        }
        for (int l = tid; l < 128*8; l += 256) {
            int row = l >> 3, c = l & 7;
            *(uint4*)(W1 + row*SXY + c*16) = *(const uint4*)(w1 + (long)row*64 + c*8);
        }
        for (int l = tid; l < 64*16; l += 256) {
            int row = l >> 4, c = l & 15;
            *(uint4*)(W2 + row*SXH + c*16) = *(const uint4*)(w2 + (long)row*128 + c*8);
        }
    }
    __syncthreads();

    // stage 1: hid = relu(y @ fc1^T + b1), NT=128
    float acc[16][4];
#pragma unroll
    for (int i = 0; i < 16; i++)
#pragma unroll
        for (int j = 0; j < 4; j++) acc[i][j] = 0.f;
    const uint32_t sb = smem_u32(smem);
    mma_stage<128, 64, SXY, SXY>(sb, sb + 128u*SXY, lane, warp_m, warp_n, acc);

    const int group = lane >> 2, tig = lane & 3;
#pragma unroll
    for (int mt = 0; mt < 2; mt++) {
        int rl = warp_m*32 + mt*16 + group;
#pragma unroll
        for (int nf = 0; nf < 8; nf++) {
            int col = warp_n*64 + nf*8 + tig*2;
            float b0 = b1[col], bb1 = b1[col+1];
            float v00 = fmaxf(acc[mt*8+nf][0]+b0, 0.f), v01 = fmaxf(acc[mt*8+nf][1]+bb1, 0.f);
            float v10 = fmaxf(acc[mt*8+nf][2]+b0, 0.f), v11 = fmaxf(acc[mt*8+nf][3]+bb1, 0.f);
            __nv_bfloat162 h0 = __floats2bfloat162_rn(v00, v01);
            __nv_bfloat162 h1 = __floats2bfloat162_rn(v10, v11);
            *(uint32_t*)(Hs + rl*SXH + col*2)     = *(uint32_t*)&h0;
            *(uint32_t*)(Hs + (rl+8)*SXH + col*2) = *(uint32_t*)&h1;
        }
    }
    __syncthreads();

    // stage 2: h2 = hid @ fc2^T + b2, NT=64 -> store into Ys region (reuse)
    float acc2[8][4];
#pragma unroll
    for (int i = 0; i < 8; i++)
#pragma unroll
        for (int j = 0; j < 4; j++) acc2[i][j] = 0.f;
    const uint32_t hsb = sb + 128u*SXY + 128u*SXY;
    mma_stage<64, 128, SXH, SXH>(hsb, hsb + 128u*SXH, lane, warp_m, warp_n, acc2);

#pragma unroll
    for (int mt = 0; mt < 2; mt++) {
        int rl = warp_m*32 + mt*16 + group;
#pragma unroll
        for (int nf = 0; nf < 4; nf++) {
            int col = warp_n*32 + nf*8 + tig*2;
            float b0 = b2[col], bb1 = b2[col+1];
            __nv_bfloat162 h0 = __floats2bfloat162_rn(acc2[mt*4+nf][0]+b0, acc2[mt*4+nf][1]+bb1);
            __nv_bfloat162 h1 = __floats2bfloat162_rn(acc2[mt*4+nf][2]+b0, acc2[mt*4+nf][3]+bb1);
            *(uint32_t*)(Ys + rl*SXY + col*2)     = *(uint32_t*)&h0;
            *(uint32_t*)(Ys + (rl+8)*SXY + col*2) = *(uint32_t*)&h1;
        }
    }
    __syncthreads();

    // LN2: warp per row, read y fp32 global + h2 from smem
    const int c = 2 * lane;
    for (int i = 0; i < 16; i++) {
        int rl = w*16 + i;
        long base = (r0 + rl) * 64;
        float2 yv = *(const float2*)(y + base + c);
        float2 hv = __bfloat1622float2(*(const __nv_bfloat162*)(Ys + rl*SXY + c*2));
        float v0 = yv.x + hv.x;
        float v1 = yv.y + hv.y;
        float s = v0 + v1;
#pragma unroll
        for (int o = 16; o; o >>= 1) s += __shfl_xor_sync(0xffffffffu, s, o);
        float mean = s * (1.f / 64.f);
        float d0 = v0 - mean, d1 = v1 - mean;
        float vs = d0 * d0 + d1 * d1;
#pragma unroll
        for (int o = 16; o; o >>= 1) vs += __shfl_xor_sync(0xffffffffu, vs, o);
        float r = rsqrtf(vs * (1.f / 64.f) + 1e-5f);
        *(float2*)(out + base + c) = make_float2(d0*r*g[c] + be[c], d1*r*g[c+1] + be[c+1]);
    }
}

// ================ prep kernels ================
__global__ void prep_phi(const float* __restrict__ phi, const float* __restrict__ dw,
                         u16* __restrict__ A2)
{
    long idx4 = (long)blockIdx.x * blockDim.x + threadIdx.x;
    long total4 = (long)SWAV * NNODES * NNODES / 4;
    if (idx4 >= total4) return;
    long idx = idx4 * 4;
    int s = (int)(idx >> 22);
    int i = (int)((idx >> 11) & 2047);
    int j0 = (int)(idx & 2047);
    float4 p = *(const float4*)(phi + idx);
    float4 d = *(const float4*)(dw + (long)s * NNODES + j0);
    u16 res[4];
    res[0] = f2bf(p.x * d.x); res[1] = f2bf(p.y * d.y);
    res[2] = f2bf(p.z * d.z); res[3] = f2bf(p.w * d.w);
    *(uint2*)(A2 + (long)i * KBIG + (long)s * NNODES + j0) = *(uint2*)res;
}

__global__ void prep_phinv(const float* __restrict__ pin, u16* __restrict__ B2)
{
    __shared__ float t[32][33];
    int s = blockIdx.z;
    int j0 = blockIdx.y * 32, n0 = blockIdx.x * 32;
    int tx = threadIdx.x, ty = threadIdx.y;
#pragma unroll
    for (int r = 0; r < 4; r++)
        t[ty + r*8][tx] = pin[((long)s << 22) + (long)(j0 + ty + r*8) * NNODES + n0 + tx];
    __syncthreads();
#pragma unroll
    for (int r = 0; r < 4; r++)
        B2[(long)(n0 + ty + r*8) * KBIG + (long)s * NNODES + j0 + tx] = f2bf(t[tx][ty + r*8]);
}

__global__ void prep_x(const float* __restrict__ x, u16* __restrict__ XT)
{
    __shared__ float t[32][33];
    int bt = blockIdx.z;
    int j0 = blockIdx.x * 32, c0 = blockIdx.y * 32;
    int tx = threadIdx.x, ty = threadIdx.y;
#pragma unroll
    for (int r = 0; r < 4; r++)
        t[ty + r*8][tx] = x[((long)bt * NNODES + j0 + ty + r*8) * CDIM + c0 + tx];
    __syncthreads();
#pragma unroll
    for (int r = 0; r < 4; r++)
        XT[(long)(bt * 64 + c0 + ty + r*8) * NNODES + j0 + tx] = f2bf(t[tx][ty + r*8]);
}

__global__ void conv_bf(const float* __restrict__ src, u16* __restrict__ dst, long n4)
{
    long i = (long)blockIdx.x * blockDim.x + threadIdx.x;
    if (i >= n4) return;
    float4 f = *(const float4*)(src + i*4);
    u16 r[4];
    r[0] = f2bf(f.x); r[1] = f2bf(f.y); r[2] = f2bf(f.z); r[3] = f2bf(f.w);
    *(uint2*)(dst + i*4) = *(uint2*)r;
}

// ---------------- linear attention, spatial ----------------
__global__ __launch_bounds__(256)
void attn_spatial(const u16* __restrict__ qkv, u16* __restrict__ cat)
{
    const int bt = blockIdx.x;
    const int h  = blockIdx.y;
    const int tid = threadIdx.x;
    const int lane = tid & 31;
    const int warp = tid >> 5;
    const u16* base = qkv + (long)bt * NNODES * 192;

    float kvs[HDIM][HDIM];
    float ksum[HDIM];
#pragma unroll
    for (int m = 0; m < HDIM; m++) {
        ksum[m] = 0.f;
#pragma unroll
        for (int d = 0; d < HDIM; d++) kvs[m][d] = 0.f;
    }

    for (int n = tid; n < NNODES; n += 256) {
        float kk[HDIM], vv[HDIM];
        ld8bf(kk, base + (long)n * 192 + 64 + h * 8);
        ld8bf(vv, base + (long)n * 192 + 128 + h * 8);
        float s = 0.f;
#pragma unroll
        for (int m = 0; m < HDIM; m++) s += kk[m] * kk[m];
        float inv = 1.f / fmaxf(sqrtf(s), 1e-12f);
#pragma unroll
        for (int m = 0; m < HDIM; m++) {
            float km = kk[m] * inv;
            ksum[m] += km;
#pragma unroll
            for (int d = 0; d < HDIM; d++) kvs[m][d] = fmaf(km, vv[d], kvs[m][d]);
        }
    }

    __shared__ float red[8][72];
    __shared__ float fin[72];
#pragma unroll
    for (int m = 0; m < HDIM; m++) {
#pragma unroll
        for (int d = 0; d < HDIM; d++) {
            float v = kvs[m][d];
#pragma unroll
            for (int o = 16; o; o >>= 1) v += __shfl_down_sync(0xffffffffu, v, o);
            if (lane == 0) red[warp][m * 8 + d] = v;
        }
        float v = ksum[m];
#pragma unroll
        for (int o = 16; o; o >>= 1) v += __shfl_down_sync(0xffffffffu, v, o);
        if (lane == 0) red[warp][64 + m] = v;
    }
    __syncthreads();
    if (tid < 72) {
        float s = 0.f;
#pragma unroll
        for (int w = 0; w < 8; w++) s += red[w][tid];
        fin[tid] = s;
    }
    __syncthreads();

    float fkvs[HDIM][HDIM], fksum[HDIM];
#pragma unroll
    for (int m = 0; m < HDIM; m++) {
        fksum[m] = fin[64 + m];
#pragma unroll
        for (int d = 0; d < HDIM; d++) fkvs[m][d] = fin[m * 8 + d];
    }

    for (int n = tid; n < NNODES; n += 256) {
        float qq[HDIM], vv[HDIM];
        ld8bf(qq, base + (long)n * 192 + h * 8);
        ld8bf(vv, base + (long)n * 192 + 128 + h * 8);
        float s = 0.f;
#pragma unroll
        for (int m = 0; m < HDIM; m++) s += qq[m] * qq[m];
        float inv = 1.f / fmaxf(sqrtf(s), 1e-12f);
        float den = (float)NNODES;
#pragma unroll
        for (int m = 0; m < HDIM; m++) { qq[m] *= inv; den = fmaf(qq[m], fksum[m], den); }
        float invden = 1.f / fmaxf(den, 1e-5f);
        float o[HDIM];
#pragma unroll
        for (int d = 0; d < HDIM; d++) {
            float num = (float)NNODES * vv[d];
#pragma unroll
            for (int m = 0; m < HDIM; m++) num = fmaf(qq[m], fkvs[m][d], num);
            o[d] = num * invden;
        }
        st8bf(cat + ((long)bt * NNODES + n) * 128 + h * 8, o);
    }
}

// ---------------- linear attention, temporal ----------------
__global__ __launch_bounds__(256)
void attn_temporal(const u16* __restrict__ qkv, u16* __restrict__ cat)
{
    int t = blockIdx.x * blockDim.x + threadIdx.x;
    if (t >= BB * NNODES * HH) return;
    const int h = t & 7;
    const int n = (t >> 3) & (NNODES - 1);
    const int b = t >> 14;

    float kvs[HDIM][HDIM];
    float ksum[HDIM];
#pragma unroll
    for (int m = 0; m < HDIM; m++) {
        ksum[m] = 0.f;
#pragma unroll
        for (int d = 0; d < HDIM; d++) kvs[m][d] = 0.f;
    }

    for (int l = 0; l < TT; l++) {
        const u16* p = qkv + (((long)(b * TT + l)) * NNODES + n) * 192;
        float kk[HDIM], vv[HDIM];
        ld8bf(kk, p + 64 + h * 8);
        ld8bf(vv, p + 128 + h * 8);
        float s = 0.f;
#pragma unroll
        for (int m = 0; m < HDIM; m++) s += kk[m] * kk[m];
        float inv = 1.f / fmaxf(sqrtf(s), 1e-12f);
#pragma unroll
        for (int m = 0; m < HDIM; m++) {
            float km = kk[m] * inv;
            ksum[m] += km;
#pragma unroll
            for (int d = 0; d < HDIM; d++) kvs[m][d] = fmaf(km, vv[d], kvs[m][d]);
        }
    }

    for (int l = 0; l < TT; l++) {
        const u16* p = qkv + (((long)(b * TT + l)) * NNODES + n) * 192;
        float qq[HDIM], vv[HDIM];
        ld8bf(qq, p + h * 8);
        ld8bf(vv, p + 128 + h * 8);
        float s = 0.f;
#pragma unroll
        for (int m = 0; m < HDIM; m++) s += qq[m] * qq[m];
        float inv = 1.f / fmaxf(sqrtf(s), 1e-12f);
        float den = (float)TT;
#pragma unroll
        for (int m = 0; m < HDIM; m++) { qq[m] *= inv; den = fmaf(qq[m], ksum[m], den); }
        float invden = 1.f / fmaxf(den, 1e-5f);
        float o[HDIM];
#pragma unroll
        for (int d = 0; d < HDIM; d++) {
            float num = (float)TT * vv[d];
#pragma unroll
            for (int m = 0; m < HDIM; m++) num = fmaf(qq[m], kvs[m][d], num);
            o[d] = num * invden;
        }
        st8bf(cat + (((long)(b * TT + l)) * NNODES + n) * 128 + 64 + h * 8, o);
    }
}

// ---------------- host launcher ----------------
extern "C" void kernel_launch(void* const* d_in, const int* in_sizes, int n_in,
                              void* d_out, int out_size)
{
    const float* x     = (const float*)d_in[0];
    const float* phi   = (const float*)d_in[1];
    const float* phinv = (const float*)d_in[2];
    const float* diagw = (const float*)d_in[3];
    const float* qkv0w = (const float*)d_in[4];
    const float* out0w = (const float*)d_in[5];
    const float* out0b = (const float*)d_in[6];
    const float* qkv1w = (const float*)d_in[7];
    const float* out1w = (const float*)d_in[8];
    const float* out1b = (const float*)d_in[9];
    const float* pw0w  = (const float*)d_in[10];
    const float* pw0b  = (const float*)d_in[11];
    const float* pw1w  = (const float*)d_in[12];
    const float* pw1b  = (const float*)d_in[13];
    const float* fc1w  = (const float*)d_in[14];
    const float* fc1b  = (const float*)d_in[15];
    const float* fc2w  = (const float*)d_in[16];
    const float* fc2b  = (const float*)d_in[17];
    const float* ln1g  = (const float*)d_in[18];
    const float* ln1b  = (const float*)d_in[19];
    const float* ln2g  = (const float*)d_in[20];
    const float* ln2b  = (const float*)d_in[21];

    u16 *a2, *b2, *msumbf, *xt, *xb, *xk, *qkvb, *catb, *att0, *p0, *p1;
    u16 *wqkv0, *wout0, *wqkv1, *wout1, *wpw0, *wpw1, *wfc1, *wfc2;
    float *yb;
    cudaGetSymbolAddress((void**)&a2,     g_a2);
    cudaGetSymbolAddress((void**)&b2,     g_b2);
    cudaGetSymbolAddress((void**)&msumbf, g_msumbf);
    cudaGetSymbolAddress((void**)&xt,     g_xt);
    cudaGetSymbolAddress((void**)&xb,     g_xb);
    cudaGetSymbolAddress((void**)&xk,     g_xk);
    cudaGetSymbolAddress((void**)&qkvb,   g_qkv);
    cudaGetSymbolAddress((void**)&catb,   g_cat);
    cudaGetSymbolAddress((void**)&att0,   g_att0);
    cudaGetSymbolAddress((void**)&p0,     g_p0);
    cudaGetSymbolAddress((void**)&p1,     g_p1);
    cudaGetSymbolAddress((void**)&yb,     g_y);
    cudaGetSymbolAddress((void**)&wqkv0,  g_wqkv0);
    cudaGetSymbolAddress((void**)&wout0,  g_wout0);
    cudaGetSymbolAddress((void**)&wqkv1,  g_wqkv1);
    cudaGetSymbolAddress((void**)&wout1,  g_wout1);
    cudaGetSymbolAddress((void**)&wpw0,   g_wpw0);
    cudaGetSymbolAddress((void**)&wpw1,   g_wpw1);
    cudaGetSymbolAddress((void**)&wfc1,   g_wfc1);
    cudaGetSymbolAddress((void**)&wfc2,   g_wfc2);

    auto rg_qkv = rowgemm<192, 64, false, true, false>;
    auto rg_pw  = rowgemm<64,  64, false, true, false>;
    const int SM_QKV = (128+192)*(64*2+16);           // 46080
    const int SM_PW  = (128+64)*(64*2+16);            // 27648
    const int SM_OPW = 128*272 + 64*272 + 128*144 + 64*144;  // 79872
    const int SM_OLN = 128*272 + 64*272 + 128*144;           // 70656
    const int SM_MLP = 128*144 + 128*144 + 128*272 + 64*272; // 89088
    cudaFuncSetAttribute(rg_qkv,       cudaFuncAttributeMaxDynamicSharedMemorySize, SM_QKV);
    cudaFuncSetAttribute(rg_pw,        cudaFuncAttributeMaxDynamicSharedMemorySize, SM_PW);
    cudaFuncSetAttribute(fused_out_pw, cudaFuncAttributeMaxDynamicSharedMemorySize, SM_OPW);
    cudaFuncSetAttribute(fused_out_ln, cudaFuncAttributeMaxDynamicSharedMemorySize, SM_OLN);
    cudaFuncSetAttribute(fused_mlp_ln, cudaFuncAttributeMaxDynamicSharedMemorySize, SM_MLP);

    const unsigned RB = (unsigned)(ROWS / 128);  // 3072

    // prep
    conv_bf<<<(unsigned)((ROWS*64/4 + 255)/256), 256>>>(x, xb, ROWS*64/4);
    conv_bf<<<12, 256>>>(qkv0w, wqkv0, 12288/4);
    conv_bf<<<8,  256>>>(out0w, wout0, 8192/4);
    conv_bf<<<12, 256>>>(qkv1w, wqkv1, 12288/4);
    conv_bf<<<8,  256>>>(out1w, wout1, 8192/4);
    conv_bf<<<4,  256>>>(pw0w,  wpw0,  4096/4);
    conv_bf<<<4,  256>>>(pw1w,  wpw1,  4096/4);
    conv_bf<<<8,  256>>>(fc1w,  wfc1,  8192/4);
    conv_bf<<<8,  256>>>(fc2w,  wfc2,  8192/4);
    {
        long total4 = (long)SWAV * NNODES * NNODES / 4;
        prep_phi<<<(unsigned)((total4 + 255) / 256), 256>>>(phi, diagw, a2);
    }
    prep_phinv<<<dim3(NNODES/32, NNODES/32, SWAV), dim3(32, 8)>>>(phinv, b2);
    prep_x<<<dim3(NNODES/32, CDIM/32, BT), dim3(32, 8)>>>(x, xt);

    // big GEMMs
    mma_gemm<0><<<dim3(16, 16), 256>>>(a2, b2, KBIG, KBIG, KBIG, msumbf);
    mma_gemm<1><<<dim3(NXK/128, 16), 256>>>(msumbf, xt, NNODES, NNODES, NNODES, xk);

    // layer 0
    rg_qkv<<<RB, 256, SM_QKV>>>(xb, wqkv0, nullptr, qkvb);
    attn_spatial<<<dim3(BT, HH), 256>>>(qkvb, catb);
    attn_temporal<<<(BB * NNODES * HH + 255) / 256, 256>>>(qkvb, catb);
    rg_pw<<<RB, 256, SM_PW>>>(xb, wpw0, pw0b, p0);
    fused_out_pw<<<RB, 256, SM_OPW>>>(catb, wout0, out0b, wpw1, pw1b, att0, p1);

    // layer 1
    rg_qkv<<<RB, 256, SM_QKV>>>(xk, wqkv1, nullptr, qkvb);
    attn_spatial<<<dim3(BT, HH), 256>>>(qkvb, catb);
    attn_temporal<<<(BB * NNODES * HH + 255) / 256, 256>>>(qkvb, catb);
    fused_out_ln<<<RB, 256, SM_OLN>>>(catb, wout1, out1b, x, att0, p0, p1, ln1g, ln1b, yb);

    // MLP + LN2
    fused_mlp_ln<<<RB, 256, SM_MLP>>>(yb, wfc1, fc1b, wfc2, fc2b, ln2g, ln2b, (float*)d_out);
}

// round 8
// speedup vs baseline: 4.1661x; 1.2004x over previous
#include <cuda_runtime.h>
#include <cuda_bf16.h>
#include <math.h>
#include <stdint.h>

#define BB 8
#define TT 24
#define NNODES 2048
#define CDIM 64
#define HH 8
#define HDIM 8
#define SWAV 4
#define BT (BB*TT)              // 192
#define ROWS ((long)BT*NNODES)  // 393216
#define KBIG (SWAV*NNODES)      // 8192
#define NXK (BT*CDIM)           // 12288

typedef unsigned short u16;

// ---------------- scratch ----------------
__device__ u16 g_a2[(long)NNODES*KBIG];
__device__ u16 g_b2[(long)NNODES*KBIG];
__device__ u16 g_msumbf[(long)NNODES*NNODES];
__device__ u16 g_xt[(long)NXK*NNODES];
__device__ u16 g_xk  [ROWS*CDIM];
__device__ u16 g_qkv [ROWS*3*CDIM];
__device__ u16 g_cat [ROWS*2*CDIM];
__device__ u16 g_att0[ROWS*CDIM];
__device__ u16 g_p0  [ROWS*CDIM];
__device__ u16 g_p1  [ROWS*CDIM];
__device__ float g_y [ROWS*CDIM];
__device__ u16 g_wqkv0[3*CDIM*CDIM];
__device__ u16 g_wout0[CDIM*2*CDIM];
__device__ u16 g_wqkv1[3*CDIM*CDIM];
__device__ u16 g_wout1[CDIM*2*CDIM];
__device__ u16 g_wpw0 [CDIM*CDIM];
__device__ u16 g_wpw1 [CDIM*CDIM];
__device__ u16 g_wfc1 [2*CDIM*CDIM];
__device__ u16 g_wfc2 [CDIM*2*CDIM];

__device__ __forceinline__ uint32_t smem_u32(const void* p){
    uint32_t a;
    asm("{ .reg .u64 t; cvta.to.shared.u64 t, %1; cvt.u32.u64 %0, t; }" : "=r"(a) : "l"(p));
    return a;
}
__device__ __forceinline__ u16 f2bf(float v){
    __nv_bfloat16 h = __float2bfloat16(v);
    return *(u16*)&h;
}
__device__ __forceinline__ void ld8bf(float* f, const u16* p){
    uint4 u = *(const uint4*)p;
    const __nv_bfloat162* h = (const __nv_bfloat162*)&u;
#pragma unroll
    for (int i = 0; i < 4; i++) { float2 t = __bfloat1622float2(h[i]); f[2*i] = t.x; f[2*i+1] = t.y; }
}
__device__ __forceinline__ void st8bf(u16* p, const float* f){
    __nv_bfloat162 h[4];
#pragma unroll
    for (int i = 0; i < 4; i++) h[i] = __floats2bfloat162_rn(f[2*i], f[2*i+1]);
    *(uint4*)p = *(uint4*)h;
}

#define LDSM4(r, addr) \
    asm volatile("ldmatrix.sync.aligned.m8n8.x4.shared.b16 {%0,%1,%2,%3}, [%4];" \
        : "=r"((r)[0]), "=r"((r)[1]), "=r"((r)[2]), "=r"((r)[3]) : "r"(addr))

#define MMA16816(c, a, b0, b1) \
    asm volatile("mma.sync.aligned.m16n8k16.row.col.f32.bf16.bf16.f32 " \
        "{%0,%1,%2,%3}, {%4,%5,%6,%7}, {%8,%9}, {%0,%1,%2,%3};" \
        : "+f"((c)[0]), "+f"((c)[1]), "+f"((c)[2]), "+f"((c)[3]) \
        : "r"((a)[0]), "r"((a)[1]), "r"((a)[2]), "r"((a)[3]), "r"(b0), "r"(b1))

#define CP16(s, g) \
    asm volatile("cp.async.cg.shared.global [%0], [%1], 16;" :: "r"(s), "l"(g))
#define CPCOMMIT() asm volatile("cp.async.commit_group;" ::: "memory")
#define CPWAIT1()  asm volatile("cp.async.wait_group 1;" ::: "memory")

// generic smem-resident MMA stage
template<int NT, int KT, int SXA, int SXB>
__device__ __forceinline__ void mma_stage(uint32_t sa, uint32_t sbm, int lane,
                                          int warp_m, int warp_n, float (*acc)[4])
{
    constexpr int NF = NT/16;
    const uint32_t aoff = sa + (uint32_t)(warp_m*32 + (lane & 15))*SXA + (uint32_t)(lane >> 4)*16;
    const uint32_t boff = sbm + (uint32_t)(warp_n*(NT/2) + ((lane >> 4) << 3) + (lane & 7))*SXB
                        + (uint32_t)((lane >> 3) & 1)*16;
#pragma unroll
    for (int k16 = 0; k16 < KT/16; k16++) {
        uint32_t a[2][4], b[NF/2][4];
#pragma unroll
        for (int mt = 0; mt < 2; mt++)
            LDSM4(a[mt], aoff + mt*16*SXA + k16*32);
#pragma unroll
        for (int nf2 = 0; nf2 < NF/2; nf2++)
            LDSM4(b[nf2], boff + nf2*16*SXB + k16*32);
#pragma unroll
        for (int mt = 0; mt < 2; mt++)
#pragma unroll
            for (int nf = 0; nf < NF; nf++) {
                const int nf2 = nf >> 1, hi = (nf & 1) * 2;
                MMA16816(acc[mt*NF+nf], a[mt], b[nf2][hi], b[nf2][hi+1]);
            }
    }
}

// ================ big mma GEMM with 3-stage cp.async pipeline ================
// D[m,n] = sum_k A[m,k]*B[n,k]. Tile 128x128, K-tile 32. stage = 20480B, 3 stages.
template<int EPI>
__global__ __launch_bounds__(256)
void mma_gemm(const u16* __restrict__ A, const u16* __restrict__ B,
              int K, int ldA, int ldB, void* __restrict__ Cout)
{
    extern __shared__ __align__(16) char smem[];
    const int tid  = threadIdx.x;
    const int lane = tid & 31;
    const int w    = tid >> 5;
    const int warp_m = w & 3;
    const int warp_n = w >> 2;
    const long m0 = (long)blockIdx.y * 128;
    const long n0 = (long)blockIdx.x * 128;
    const u16* Ab = A + m0 * ldA;
    const u16* Bb = B + n0 * ldB;

    const uint32_t sbase = smem_u32(smem);
    const int r0w = tid >> 2;   // 0..63
    const int kc  = tid & 3;

    const uint32_t aoff = (uint32_t)(warp_m*32 + (lane & 15))*80 + (uint32_t)(lane >> 4)*16;
    const uint32_t boff = (uint32_t)(warp_n*64 + ((lane >> 4) << 3) + (lane & 7))*80
                        + (uint32_t)((lane >> 3) & 1)*16 + 10240;

    float acc[2][8][4];
#pragma unroll
    for (int mt = 0; mt < 2; mt++)
#pragma unroll
        for (int nt = 0; nt < 8; nt++)
#pragma unroll
            for (int i = 0; i < 4; i++) acc[mt][nt][i] = 0.f;

    const int T = K >> 5;
    // prologue: stages 0,1
#pragma unroll
    for (int s = 0; s < 2; s++) {
        const int kt = s << 5;
#pragma unroll
        for (int i = 0; i < 2; i++) {
            int row = r0w + i*64;
            uint32_t sA = sbase + (uint32_t)s*20480 + row*80 + kc*16;
            CP16(sA,         Ab + (long)row*ldA + kt + kc*8);
            CP16(sA + 10240, Bb + (long)row*ldB + kt + kc*8);
        }
        CPCOMMIT();
    }

    for (int t = 0; t < T; t++) {
        CPWAIT1();
        __syncthreads();
        if (t + 2 < T) {
            const int kt = (t + 2) << 5;
            const int buf = (t + 2) % 3;
#pragma unroll
            for (int i = 0; i < 2; i++) {
                int row = r0w + i*64;
                uint32_t sA = sbase + (uint32_t)buf*20480 + row*80 + kc*16;
                CP16(sA,         Ab + (long)row*ldA + kt + kc*8);
                CP16(sA + 10240, Bb + (long)row*ldB + kt + kc*8);
            }
        }
        CPCOMMIT();
        const uint32_t sA = sbase + (uint32_t)(t % 3)*20480;
#pragma unroll
        for (int k16 = 0; k16 < 2; k16++) {
            uint32_t a[2][4], b[4][4];
#pragma unroll
            for (int mt = 0; mt < 2; mt++)
                LDSM4(a[mt], sA + aoff + mt*1280 + k16*32);
#pragma unroll
            for (int nt2 = 0; nt2 < 4; nt2++)
                LDSM4(b[nt2], sA + boff + nt2*1280 + k16*32);
#pragma unroll
            for (int mt = 0; mt < 2; mt++)
#pragma unroll
                for (int nt = 0; nt < 8; nt++) {
                    const int nt2 = nt >> 1, hi = (nt & 1) * 2;
                    MMA16816(acc[mt][nt], a[mt], b[nt2][hi], b[nt2][hi+1]);
                }
        }
    }

    const int group = lane >> 2, tig = lane & 3;
    if (EPI == 0) {
        u16* C = (u16*)Cout;
#pragma unroll
        for (int mt = 0; mt < 2; mt++) {
            long rbase = m0 + warp_m*32 + mt*16;
#pragma unroll
            for (int nt = 0; nt < 8; nt++) {
                long col = n0 + warp_n*64 + nt*8 + tig*2;
                __nv_bfloat162 h0 = __floats2bfloat162_rn(acc[mt][nt][0], acc[mt][nt][1]);
                __nv_bfloat162 h1 = __floats2bfloat162_rn(acc[mt][nt][2], acc[mt][nt][3]);
                *(uint32_t*)(C + (rbase + group)*2048 + col)     = *(uint32_t*)&h0;
                *(uint32_t*)(C + (rbase + 8 + group)*2048 + col) = *(uint32_t*)&h1;
            }
        }
    } else {
        u16* Xk = (u16*)Cout;
        const long bt = (n0 + warp_n*64) >> 6;
        u16* obase = Xk + bt * (long)NNODES * 64;
#pragma unroll
        for (int mt = 0; mt < 2; mt++) {
            long r = m0 + warp_m*32 + mt*16 + group;
#pragma unroll
            for (int nt = 0; nt < 8; nt++) {
                int cin = nt*8 + tig*2;
                __nv_bfloat162 h0 = __floats2bfloat162_rn(acc[mt][nt][0], acc[mt][nt][1]);
                __nv_bfloat162 h1 = __floats2bfloat162_rn(acc[mt][nt][2], acc[mt][nt][3]);
                *(uint32_t*)(obase + r*64 + cin)       = *(uint32_t*)&h0;
                *(uint32_t*)(obase + (r + 8)*64 + cin) = *(uint32_t*)&h1;
            }
        }
    }
}

// ================ rowgemm (qkv / pw0) ================
template<int NT, int KT, bool RELU, bool OUTBF, bool INF32>
__global__ __launch_bounds__(256)
void rowgemm(const void* __restrict__ Xin, const u16* __restrict__ Wb,
             const float* __restrict__ bias, void* __restrict__ Out)
{
    constexpr int SX  = KT*2 + 16;
    constexpr int CPR = (KT*2)/16;
    constexpr int NF  = NT/16;
    extern __shared__ __align__(16) char smem[];
    const int tid = threadIdx.x, lane = tid & 31, w = tid >> 5;
    const int warp_m = w & 3, warp_n = w >> 2;
    const long r0 = (long)blockIdx.x * 128;

    if (!INF32) {
        const u16* X = (const u16*)Xin + r0*KT;
        for (int l = tid; l < 128*CPR; l += 256) {
            int row = l / CPR, c = l % CPR;
            *(uint4*)(smem + row*SX + c*16) = *(const uint4*)(X + (long)row*KT + c*8);
        }
    } else {
        const float* X = (const float*)Xin + r0*KT;
        for (int l = tid; l < 128*CPR; l += 256) {
            int row = l / CPR, c = l % CPR;
            float4 f0 = *(const float4*)(X + (long)row*KT + c*8);
            float4 f1 = *(const float4*)(X + (long)row*KT + c*8 + 4);
            __nv_bfloat162 h[4];
            h[0] = __floats2bfloat162_rn(f0.x, f0.y);
            h[1] = __floats2bfloat162_rn(f0.z, f0.w);
            h[2] = __floats2bfloat162_rn(f1.x, f1.y);
            h[3] = __floats2bfloat162_rn(f1.z, f1.w);
            *(uint4*)(smem + row*SX + c*16) = *(uint4*)h;
        }
    }
    char* wsm = smem + 128*SX;
    for (int l = tid; l < NT*CPR; l += 256) {
        int row = l / CPR, c = l % CPR;
        *(uint4*)(wsm + row*SX + c*16) = *(const uint4*)(Wb + (long)row*KT + c*8);
    }
    __syncthreads();

    float acc[2*NF][4];
#pragma unroll
    for (int i = 0; i < 2*NF; i++)
#pragma unroll
        for (int j = 0; j < 4; j++) acc[i][j] = 0.f;

    const uint32_t sb = smem_u32(smem);
    mma_stage<NT, KT, SX, SX>(sb, sb + 128u*SX, lane, warp_m, warp_n, acc);

    const int group = lane >> 2, tig = lane & 3;
#pragma unroll
    for (int mt = 0; mt < 2; mt++) {
        long r = r0 + warp_m*32 + mt*16 + group;
#pragma unroll
        for (int nf = 0; nf < NF; nf++) {
            int col = warp_n*(NT/2) + nf*8 + tig*2;
            float b0 = 0.f, b1 = 0.f;
            if (bias) { b0 = bias[col]; b1 = bias[col+1]; }
            float v00 = acc[mt*NF+nf][0] + b0, v01 = acc[mt*NF+nf][1] + b1;
            float v10 = acc[mt*NF+nf][2] + b0, v11 = acc[mt*NF+nf][3] + b1;
            if (RELU) {
                v00 = fmaxf(v00, 0.f); v01 = fmaxf(v01, 0.f);
                v10 = fmaxf(v10, 0.f); v11 = fmaxf(v11, 0.f);
            }
            u16* O = (u16*)Out;
            __nv_bfloat162 h0 = __floats2bfloat162_rn(v00, v01);
            __nv_bfloat162 h1 = __floats2bfloat162_rn(v10, v11);
            *(uint32_t*)(O + r*NT + col)       = *(uint32_t*)&h0;
            *(uint32_t*)(O + (r + 8)*NT + col) = *(uint32_t*)&h1;
        }
    }
}

// ================ fused out-proj0 + pw1 ================
__global__ __launch_bounds__(256)
void fused_out_pw(const u16* __restrict__ cat, const u16* __restrict__ w1,
                  const float* __restrict__ b1, const u16* __restrict__ w2,
                  const float* __restrict__ b2, u16* __restrict__ att0,
                  u16* __restrict__ p1)
{
    constexpr int SX1 = 272;
    constexpr int SX2 = 144;
    extern __shared__ __align__(16) char smem[];
    char* Xs = smem;
    char* W1 = Xs + 128*SX1;
    char* As = W1 + 64*SX1;
    char* W2 = As + 128*SX2;
    const int tid = threadIdx.x, lane = tid & 31, w = tid >> 5;
    const int warp_m = w & 3, warp_n = w >> 2;
    const long r0 = (long)blockIdx.x * 128;

    {
        const u16* X = cat + r0*128;
        for (int l = tid; l < 128*16; l += 256) {
            int row = l >> 4, c = l & 15;
            *(uint4*)(Xs + row*SX1 + c*16) = *(const uint4*)(X + (long)row*128 + c*8);
        }
        for (int l = tid; l < 64*16; l += 256) {
            int row = l >> 4, c = l & 15;
            *(uint4*)(W1 + row*SX1 + c*16) = *(const uint4*)(w1 + (long)row*128 + c*8);
        }
        for (int l = tid; l < 64*8; l += 256) {
            int row = l >> 3, c = l & 7;
            *(uint4*)(W2 + row*SX2 + c*16) = *(const uint4*)(w2 + (long)row*64 + c*8);
        }
    }
    __syncthreads();

    float acc[8][4];
#pragma unroll
    for (int i = 0; i < 8; i++)
#pragma unroll
        for (int j = 0; j < 4; j++) acc[i][j] = 0.f;
    const uint32_t sb = smem_u32(smem);
    mma_stage<64, 128, SX1, SX1>(sb, sb + 128u*SX1, lane, warp_m, warp_n, acc);

    const int group = lane >> 2, tig = lane & 3;
    const uint32_t asb = sb + 128u*SX1 + 64u*SX1;
#pragma unroll
    for (int mt = 0; mt < 2; mt++) {
        int rl = warp_m*32 + mt*16 + group;
#pragma unroll
        for (int nf = 0; nf < 4; nf++) {
            int col = warp_n*32 + nf*8 + tig*2;
            float b0 = b1[col], bb1 = b1[col+1];
            __nv_bfloat162 h0 = __floats2bfloat162_rn(acc[mt*4+nf][0]+b0, acc[mt*4+nf][1]+bb1);
            __nv_bfloat162 h1 = __floats2bfloat162_rn(acc[mt*4+nf][2]+b0, acc[mt*4+nf][3]+bb1);
            *(uint32_t*)(As + rl*SX2 + col*2)       = *(uint32_t*)&h0;
            *(uint32_t*)(As + (rl+8)*SX2 + col*2)   = *(uint32_t*)&h1;
            *(uint32_t*)(att0 + (r0+rl)*64 + col)   = *(uint32_t*)&h0;
            *(uint32_t*)(att0 + (r0+rl+8)*64 + col) = *(uint32_t*)&h1;
        }
    }
    __syncthreads();

    float acc2[8][4];
#pragma unroll
    for (int i = 0; i < 8; i++)
#pragma unroll
        for (int j = 0; j < 4; j++) acc2[i][j] = 0.f;
    mma_stage<64, 64, SX2, SX2>(asb, asb + 128u*SX2, lane, warp_m, warp_n, acc2);

#pragma unroll
    for (int mt = 0; mt < 2; mt++) {
        long r = r0 + warp_m*32 + mt*16 + group;
#pragma unroll
        for (int nf = 0; nf < 4; nf++) {
            int col = warp_n*32 + nf*8 + tig*2;
            float b0 = b2[col], bb1 = b2[col+1];
            __nv_bfloat162 h0 = __floats2bfloat162_rn(acc2[mt*4+nf][0]+b0, acc2[mt*4+nf][1]+bb1);
            __nv_bfloat162 h1 = __floats2bfloat162_rn(acc2[mt*4+nf][2]+b0, acc2[mt*4+nf][3]+bb1);
            *(uint32_t*)(p1 + r*64 + col)     = *(uint32_t*)&h0;
            *(uint32_t*)(p1 + (r+8)*64 + col) = *(uint32_t*)&h1;
        }
    }
}

// ================ fused out-proj1 + x_glo + LN1 ================
__global__ __launch_bounds__(256)
void fused_out_ln(const u16* __restrict__ cat, const u16* __restrict__ w1,
                  const float* __restrict__ b1, const float* __restrict__ x,
                  const u16* __restrict__ att0, const u16* __restrict__ p0,
                  const u16* __restrict__ p1, const float* __restrict__ g,
                  const float* __restrict__ be, float* __restrict__ y)
{
    constexpr int SX1 = 272;
    constexpr int SX2 = 144;
    extern __shared__ __align__(16) char smem[];
    char* Xs = smem;
    char* W1 = Xs + 128*SX1;
    char* As = W1 + 64*SX1;
    const int tid = threadIdx.x, lane = tid & 31, w = tid >> 5;
    const int warp_m = w & 3, warp_n = w >> 2;
    const long r0 = (long)blockIdx.x * 128;

    {
        const u16* X = cat + r0*128;
        for (int l = tid; l < 128*16; l += 256) {
            int row = l >> 4, c = l & 15;
            *(uint4*)(Xs + row*SX1 + c*16) = *(const uint4*)(X + (long)row*128 + c*8);
        }
        for (int l = tid; l < 64*16; l += 256) {
            int row = l >> 4, c = l & 15;
            *(uint4*)(W1 + row*SX1 + c*16) = *(const uint4*)(w1 + (long)row*128 + c*8);
        }
    }
    __syncthreads();

    float acc[8][4];
#pragma unroll
    for (int i = 0; i < 8; i++)
#pragma unroll
        for (int j = 0; j < 4; j++) acc[i][j] = 0.f;
    const uint32_t sb = smem_u32(smem);
    mma_stage<64, 128, SX1, SX1>(sb, sb + 128u*SX1, lane, warp_m, warp_n, acc);

    const int group = lane >> 2, tig = lane & 3;
#pragma unroll
    for (int mt = 0; mt < 2; mt++) {
        int rl = warp_m*32 + mt*16 + group;
#pragma unroll
        for (int nf = 0; nf < 4; nf++) {
            int col = warp_n*32 + nf*8 + tig*2;
            float b0 = b1[col], bb1 = b1[col+1];
            __nv_bfloat162 h0 = __floats2bfloat162_rn(acc[mt*4+nf][0]+b0, acc[mt*4+nf][1]+bb1);
            __nv_bfloat162 h1 = __floats2bfloat162_rn(acc[mt*4+nf][2]+b0, acc[mt*4+nf][3]+bb1);
            *(uint32_t*)(As + rl*SX2 + col*2)     = *(uint32_t*)&h0;
            *(uint32_t*)(As + (rl+8)*SX2 + col*2) = *(uint32_t*)&h1;
        }
    }
    __syncthreads();

    const int c = 2 * lane;
    for (int i = 0; i < 16; i++) {
        int rl = w*16 + i;
        long base = (r0 + rl) * 64;
        float2 xv  = *(const float2*)(x + base + c);
        float2 a0v = __bfloat1622float2(*(const __nv_bfloat162*)(att0 + base + c));
        float2 p0v = __bfloat1622float2(*(const __nv_bfloat162*)(p0 + base + c));
        float2 p1v = __bfloat1622float2(*(const __nv_bfloat162*)(p1 + base + c));
        float2 a1v = __bfloat1622float2(*(const __nv_bfloat162*)(As + rl*SX2 + c*2));
        float v0 = 2.f * (xv.x + a0v.x*p0v.x + a1v.x*p1v.x*0.01f);
        float v1 = 2.f * (xv.y + a0v.y*p0v.y + a1v.y*p1v.y*0.01f);
        float s = v0 + v1;
#pragma unroll
        for (int o = 16; o; o >>= 1) s += __shfl_xor_sync(0xffffffffu, s, o);
        float mean = s * (1.f / 64.f);
        float d0 = v0 - mean, d1 = v1 - mean;
        float vs = d0 * d0 + d1 * d1;
#pragma unroll
        for (int o = 16; o; o >>= 1) vs += __shfl_xor_sync(0xffffffffu, vs, o);
        float r = rsqrtf(vs * (1.f / 64.f) + 1e-5f);
        *(float2*)(y + base + c) = make_float2(d0*r*g[c] + be[c], d1*r*g[c+1] + be[c+1]);
    }
}

// ================ fused fc1 + relu + fc2 + residual + LN2 ================
__global__ __launch_bounds__(256)
void fused_mlp_ln(const float* __restrict__ y, const u16* __restrict__ w1,
                  const float* __restrict__ b1, const u16* __restrict__ w2,
                  const float* __restrict__ b2, const float* __restrict__ g,
                  const float* __restrict__ be, float* __restrict__ out)
{
    constexpr int SXY = 144;
    constexpr int SXH = 272;
    extern __shared__ __align__(16) char smem[];
    char* Ys = smem;
    char* W1 = Ys + 128*SXY;
    char* Hs = W1 + 128*SXY;
    char* W2 = Hs + 128*SXH;
    const int tid = threadIdx.x, lane = tid & 31, w = tid >> 5;
    const int warp_m = w & 3, warp_n = w >> 2;
    const long r0 = (long)blockIdx.x * 128;

    {
        const float* Y = y + r0*64;
        for (int l = tid; l < 128*8; l += 256) {
            int row = l >> 3, c = l & 7;
            float4 f0 = *(const float4*)(Y + (long)row*64 + c*8);
            float4 f1 = *(const float4*)(Y + (long)row*64 + c*8 + 4);
            __nv_bfloat162 h[4];
            h[0] = __floats2bfloat162_rn(f0.x, f0.y);
            h[1] = __floats2bfloat162_rn(f0.z, f0.w);
            h[2] = __floats2bfloat162_rn(f1.x, f1.y);
            h[3] = __floats2bfloat162_rn(f1.z, f1.w);
            *(uint4*)(Ys + row*SXY + c*16) = *(uint4*)h;
        }
        for (int l = tid; l < 128*8; l += 256) {
            int row = l >> 3, c = l & 7;
            *(uint4*)(W1 + row*SXY + c*16) = *(const uint4*)(w1 + (long)row*64 + c*8);
        }
        for (int l = tid; l < 64*16; l += 256) {
            int row = l >> 4, c = l & 15;
            *(uint4*)(W2 + row*SXH + c*16) = *(const uint4*)(w2 + (long)row*128 + c*8);
        }
    }
    __syncthreads();

    float acc[16][4];
#pragma unroll
    for (int i = 0; i < 16; i++)
#pragma unroll
        for (int j = 0; j < 4; j++) acc[i][j] = 0.f;
    const uint32_t sb = smem_u32(smem);
    mma_stage<128, 64, SXY, SXY>(sb, sb + 128u*SXY, lane, warp_m, warp_n, acc);

    const int group = lane >> 2, tig = lane & 3;
#pragma unroll
    for (int mt = 0; mt < 2; mt++) {
        int rl = warp_m*32 + mt*16 + group;
#pragma unroll
        for (int nf = 0; nf < 8; nf++) {
            int col = warp_n*64 + nf*8 + tig*2;
            float b0 = b1[col], bb1 = b1[col+1];
            float v00 = fmaxf(acc[mt*8+nf][0]+b0, 0.f), v01 = fmaxf(acc[mt*8+nf][1]+bb1, 0.f);
            float v10 = fmaxf(acc[mt*8+nf][2]+b0, 0.f), v11 = fmaxf(acc[mt*8+nf][3]+bb1, 0.f);
            __nv_bfloat162 h0 = __floats2bfloat162_rn(v00, v01);
            __nv_bfloat162 h1 = __floats2bfloat162_rn(v10, v11);
            *(uint32_t*)(Hs + rl*SXH + col*2)     = *(uint32_t*)&h0;
            *(uint32_t*)(Hs + (rl+8)*SXH + col*2) = *(uint32_t*)&h1;
        }
    }
    __syncthreads();

    float acc2[8][4];
#pragma unroll
    for (int i = 0; i < 8; i++)
#pragma unroll
        for (int j = 0; j < 4; j++) acc2[i][j] = 0.f;
    const uint32_t hsb = sb + 128u*SXY + 128u*SXY;
    mma_stage<64, 128, SXH, SXH>(hsb, hsb + 128u*SXH, lane, warp_m, warp_n, acc2);

#pragma unroll
    for (int mt = 0; mt < 2; mt++) {
        int rl = warp_m*32 + mt*16 + group;
#pragma unroll
        for (int nf = 0; nf < 4; nf++) {
            int col = warp_n*32 + nf*8 + tig*2;
            float b0 = b2[col], bb1 = b2[col+1];
            __nv_bfloat162 h0 = __floats2bfloat162_rn(acc2[mt*4+nf][0]+b0, acc2[mt*4+nf][1]+bb1);
            __nv_bfloat162 h1 = __floats2bfloat162_rn(acc2[mt*4+nf][2]+b0, acc2[mt*4+nf][3]+bb1);
            *(uint32_t*)(Ys + rl*SXY + col*2)     = *(uint32_t*)&h0;
            *(uint32_t*)(Ys + (rl+8)*SXY + col*2) = *(uint32_t*)&h1;
        }
    }
    __syncthreads();

    const int c = 2 * lane;
    for (int i = 0; i < 16; i++) {
        int rl = w*16 + i;
        long base = (r0 + rl) * 64;
        float2 yv = *(const float2*)(y + base + c);
        float2 hv = __bfloat1622float2(*(const __nv_bfloat162*)(Ys + rl*SXY + c*2));
        float v0 = yv.x + hv.x;
        float v1 = yv.y + hv.y;
        float s = v0 + v1;
#pragma unroll
        for (int o = 16; o; o >>= 1) s += __shfl_xor_sync(0xffffffffu, s, o);
        float mean = s * (1.f / 64.f);
        float d0 = v0 - mean, d1 = v1 - mean;
        float vs = d0 * d0 + d1 * d1;
#pragma unroll
        for (int o = 16; o; o >>= 1) vs += __shfl_xor_sync(0xffffffffu, vs, o);
        float r = rsqrtf(vs * (1.f / 64.f) + 1e-5f);
        *(float2*)(out + base + c) = make_float2(d0*r*g[c] + be[c], d1*r*g[c+1] + be[c+1]);
    }
}

// ================ prep kernels ================
__global__ void prep_phi(const float* __restrict__ phi, const float* __restrict__ dw,
                         u16* __restrict__ A2)
{
    long idx4 = (long)blockIdx.x * blockDim.x + threadIdx.x;
    long total4 = (long)SWAV * NNODES * NNODES / 4;
    if (idx4 >= total4) return;
    long idx = idx4 * 4;
    int s = (int)(idx >> 22);
    int i = (int)((idx >> 11) & 2047);
    int j0 = (int)(idx & 2047);
    float4 p = *(const float4*)(phi + idx);
    float4 d = *(const float4*)(dw + (long)s * NNODES + j0);
    u16 res[4];
    res[0] = f2bf(p.x * d.x); res[1] = f2bf(p.y * d.y);
    res[2] = f2bf(p.z * d.z); res[3] = f2bf(p.w * d.w);
    *(uint2*)(A2 + (long)i * KBIG + (long)s * NNODES + j0) = *(uint2*)res;
}

__global__ void prep_phinv(const float* __restrict__ pin, u16* __restrict__ B2)
{
    __shared__ float t[32][33];
    int s = blockIdx.z;
    int j0 = blockIdx.y * 32, n0 = blockIdx.x * 32;
    int tx = threadIdx.x, ty = threadIdx.y;
#pragma unroll
    for (int r = 0; r < 4; r++)
        t[ty + r*8][tx] = pin[((long)s << 22) + (long)(j0 + ty + r*8) * NNODES + n0 + tx];
    __syncthreads();
#pragma unroll
    for (int r = 0; r < 4; r++)
        B2[(long)(n0 + ty + r*8) * KBIG + (long)s * NNODES + j0 + tx] = f2bf(t[tx][ty + r*8]);
}

__global__ void prep_x(const float* __restrict__ x, u16* __restrict__ XT)
{
    __shared__ float t[32][33];
    int bt = blockIdx.z;
    int j0 = blockIdx.x * 32, c0 = blockIdx.y * 32;
    int tx = threadIdx.x, ty = threadIdx.y;
#pragma unroll
    for (int r = 0; r < 4; r++)
        t[ty + r*8][tx] = x[((long)bt * NNODES + j0 + ty + r*8) * CDIM + c0 + tx];
    __syncthreads();
#pragma unroll
    for (int r = 0; r < 4; r++)
        XT[(long)(bt * 64 + c0 + ty + r*8) * NNODES + j0 + tx] = f2bf(t[tx][ty + r*8]);
}

__global__ void conv_bf(const float* __restrict__ src, u16* __restrict__ dst, long n4)
{
    long i = (long)blockIdx.x * blockDim.x + threadIdx.x;
    if (i >= n4) return;
    float4 f = *(const float4*)(src + i*4);
    u16 r[4];
    r[0] = f2bf(f.x); r[1] = f2bf(f.y); r[2] = f2bf(f.z); r[3] = f2bf(f.w);
    *(uint2*)(dst + i*4) = *(uint2*)r;
}

// ================ fused attention: spatial (blocks 0..767) + temporal (768..1279) =========
__global__ __launch_bounds__(256)
void attn_fused(const u16* __restrict__ qkv, u16* __restrict__ cat)
{
    const int bid = blockIdx.x;
    const int tid = threadIdx.x;

    if (bid < 768) {
        // ---- spatial: block = (bt, head-pair); thread = (node, head-in-pair) ----
        const int bt = bid >> 2;
        const int h  = (bid & 3) * 2 + (tid & 1);
        const int lane = tid & 31, warp = tid >> 5;
        const u16* base = qkv + (long)bt * NNODES * 192;

        float kvs[HDIM][HDIM], ksum[HDIM];
#pragma unroll
        for (int m = 0; m < HDIM; m++) {
            ksum[m] = 0.f;
#pragma unroll
            for (int d = 0; d < HDIM; d++) kvs[m][d] = 0.f;
        }

        for (int n = tid >> 1; n < NNODES; n += 128) {
            float kk[HDIM], vv[HDIM];
            ld8bf(kk, base + (long)n * 192 + 64 + h * 8);
            ld8bf(vv, base + (long)n * 192 + 128 + h * 8);
            float s = 0.f;
#pragma unroll
            for (int m = 0; m < HDIM; m++) s += kk[m] * kk[m];
            float inv = 1.f / fmaxf(sqrtf(s), 1e-12f);
#pragma unroll
            for (int m = 0; m < HDIM; m++) {
                float km = kk[m] * inv;
                ksum[m] += km;
#pragma unroll
                for (int d = 0; d < HDIM; d++) kvs[m][d] = fmaf(km, vv[d], kvs[m][d]);
            }
        }

        __shared__ float red[8][2][72];
        __shared__ float fin[2][72];
#pragma unroll
        for (int m = 0; m < HDIM; m++) {
#pragma unroll
            for (int d = 0; d < HDIM; d++) {
                float v = kvs[m][d];
#pragma unroll
                for (int o = 2; o <= 16; o <<= 1) v += __shfl_xor_sync(0xffffffffu, v, o);
                if (lane < 2) red[warp][lane][m * 8 + d] = v;
            }
            float v = ksum[m];
#pragma unroll
            for (int o = 2; o <= 16; o <<= 1) v += __shfl_xor_sync(0xffffffffu, v, o);
            if (lane < 2) red[warp][lane][64 + m] = v;
        }
        __syncthreads();
        if (tid < 144) {
            int p = tid & 1, e = tid >> 1;
            float s = 0.f;
#pragma unroll
            for (int ww = 0; ww < 8; ww++) s += red[ww][p][e];
            fin[p][e] = s;
        }
        __syncthreads();

        float fkvs[HDIM][HDIM], fksum[HDIM];
        const int pp = tid & 1;
#pragma unroll
        for (int m = 0; m < HDIM; m++) {
            fksum[m] = fin[pp][64 + m];
#pragma unroll
            for (int d = 0; d < HDIM; d++) fkvs[m][d] = fin[pp][m * 8 + d];
        }

        for (int n = tid >> 1; n < NNODES; n += 128) {
            float qq[HDIM], vv[HDIM];
            ld8bf(qq, base + (long)n * 192 + h * 8);
            ld8bf(vv, base + (long)n * 192 + 128 + h * 8);
            float s = 0.f;
#pragma unroll
            for (int m = 0; m < HDIM; m++) s += qq[m] * qq[m];
            float inv = 1.f / fmaxf(sqrtf(s), 1e-12f);
            float den = (float)NNODES;
#pragma unroll
            for (int m = 0; m < HDIM; m++) { qq[m] *= inv; den = fmaf(qq[m], fksum[m], den); }
            float invden = 1.f / fmaxf(den, 1e-5f);
            float o[HDIM];
#pragma unroll
            for (int d = 0; d < HDIM; d++) {
                float num = (float)NNODES * vv[d];
#pragma unroll
                for (int m = 0; m < HDIM; m++) num = fmaf(qq[m], fkvs[m][d], num);
                o[d] = num * invden;
            }
            st8bf(cat + ((long)bt * NNODES + n) * 128 + h * 8, o);
        }
    } else {
        // ---- temporal: thread = (b, n, h) ----
        int t = (bid - 768) * 256 + tid;
        if (t >= BB * NNODES * HH) return;
        const int h = t & 7;
        const int n = (t >> 3) & (NNODES - 1);
        const int b = t >> 14;

        float kvs[HDIM][HDIM], ksum[HDIM];
#pragma unroll
        for (int m = 0; m < HDIM; m++) {
            ksum[m] = 0.f;
#pragma unroll
            for (int d = 0; d < HDIM; d++) kvs[m][d] = 0.f;
        }

        for (int l = 0; l < TT; l++) {
            const u16* p = qkv + (((long)(b * TT + l)) * NNODES + n) * 192;
            float kk[HDIM], vv[HDIM];
            ld8bf(kk, p + 64 + h * 8);
            ld8bf(vv, p + 128 + h * 8);
            float s = 0.f;
#pragma unroll
            for (int m = 0; m < HDIM; m++) s += kk[m] * kk[m];
            float inv = 1.f / fmaxf(sqrtf(s), 1e-12f);
#pragma unroll
            for (int m = 0; m < HDIM; m++) {
                float km = kk[m] * inv;
                ksum[m] += km;
#pragma unroll
                for (int d = 0; d < HDIM; d++) kvs[m][d] = fmaf(km, vv[d], kvs[m][d]);
            }
        }

        for (int l = 0; l < TT; l++) {
            const u16* p = qkv + (((long)(b * TT + l)) * NNODES + n) * 192;
            float qq[HDIM], vv[HDIM];
            ld8bf(qq, p + h * 8);
            ld8bf(vv, p + 128 + h * 8);
            float s = 0.f;
#pragma unroll
            for (int m = 0; m < HDIM; m++) s += qq[m] * qq[m];
            float inv = 1.f / fmaxf(sqrtf(s), 1e-12f);
            float den = (float)TT;
#pragma unroll
            for (int m = 0; m < HDIM; m++) { qq[m] *= inv; den = fmaf(qq[m], ksum[m], den); }
            float invden = 1.f / fmaxf(den, 1e-5f);
            float o[HDIM];
#pragma unroll
            for (int d = 0; d < HDIM; d++) {
                float num = (float)TT * vv[d];
#pragma unroll
                for (int m = 0; m < HDIM; m++) num = fmaf(qq[m], kvs[m][d], num);
                o[d] = num * invden;
            }
            st8bf(cat + (((long)(b * TT + l)) * NNODES + n) * 128 + 64 + h * 8, o);
        }
    }
}

// ---------------- host launcher ----------------
extern "C" void kernel_launch(void* const* d_in, const int* in_sizes, int n_in,
                              void* d_out, int out_size)
{
    const float* x     = (const float*)d_in[0];
    const float* phi   = (const float*)d_in[1];
    const float* phinv = (const float*)d_in[2];
    const float* diagw = (const float*)d_in[3];
    const float* qkv0w = (const float*)d_in[4];
    const float* out0w = (const float*)d_in[5];
    const float* out0b = (const float*)d_in[6];
    const float* qkv1w = (const float*)d_in[7];
    const float* out1w = (const float*)d_in[8];
    const float* out1b = (const float*)d_in[9];
    const float* pw0w  = (const float*)d_in[10];
    const float* pw0b  = (const float*)d_in[11];
    const float* pw1w  = (const float*)d_in[12];
    const float* pw1b  = (const float*)d_in[13];
    const float* fc1w  = (const float*)d_in[14];
    const float* fc1b  = (const float*)d_in[15];
    const float* fc2w  = (const float*)d_in[16];
    const float* fc2b  = (const float*)d_in[17];
    const float* ln1g  = (const float*)d_in[18];
    const float* ln1b  = (const float*)d_in[19];
    const float* ln2g  = (const float*)d_in[20];
    const float* ln2b  = (const float*)d_in[21];

    u16 *a2, *b2, *msumbf, *xt, *xk, *qkvb, *catb, *att0, *p0, *p1;
    u16 *wqkv0, *wout0, *wqkv1, *wout1, *wpw0, *wpw1, *wfc1, *wfc2;
    float *yb;
    cudaGetSymbolAddress((void**)&a2,     g_a2);
    cudaGetSymbolAddress((void**)&b2,     g_b2);
    cudaGetSymbolAddress((void**)&msumbf, g_msumbf);
    cudaGetSymbolAddress((void**)&xt,     g_xt);
    cudaGetSymbolAddress((void**)&xk,     g_xk);
    cudaGetSymbolAddress((void**)&qkvb,   g_qkv);
    cudaGetSymbolAddress((void**)&catb,   g_cat);
    cudaGetSymbolAddress((void**)&att0,   g_att0);
    cudaGetSymbolAddress((void**)&p0,     g_p0);
    cudaGetSymbolAddress((void**)&p1,     g_p1);
    cudaGetSymbolAddress((void**)&yb,     g_y);
    cudaGetSymbolAddress((void**)&wqkv0,  g_wqkv0);
    cudaGetSymbolAddress((void**)&wout0,  g_wout0);
    cudaGetSymbolAddress((void**)&wqkv1,  g_wqkv1);
    cudaGetSymbolAddress((void**)&wout1,  g_wout1);
    cudaGetSymbolAddress((void**)&wpw0,   g_wpw0);
    cudaGetSymbolAddress((void**)&wpw1,   g_wpw1);
    cudaGetSymbolAddress((void**)&wfc1,   g_wfc1);
    cudaGetSymbolAddress((void**)&wfc2,   g_wfc2);

    auto rg_qkv_f32 = rowgemm<192, 64, false, true, true >;  // layer0: fp32 x
    auto rg_qkv_bf  = rowgemm<192, 64, false, true, false>;  // layer1: bf16 xk
    auto rg_pw_f32  = rowgemm<64,  64, false, true, true >;  // p0 from fp32 x
    const int SM_QKV = (128+192)*(64*2+16);                   // 46080
    const int SM_PW  = (128+64)*(64*2+16);                    // 27648
    const int SM_OPW = 128*272 + 64*272 + 128*144 + 64*144;   // 79872
    const int SM_OLN = 128*272 + 64*272 + 128*144;            // 70656
    const int SM_MLP = 128*144 + 128*144 + 128*272 + 64*272;  // 89088
    const int SM_MMA = 3 * 20480;                             // 61440
    cudaFuncSetAttribute(rg_qkv_f32,   cudaFuncAttributeMaxDynamicSharedMemorySize, SM_QKV);
    cudaFuncSetAttribute(rg_qkv_bf,    cudaFuncAttributeMaxDynamicSharedMemorySize, SM_QKV);
    cudaFuncSetAttribute(rg_pw_f32,    cudaFuncAttributeMaxDynamicSharedMemorySize, SM_PW);
    cudaFuncSetAttribute(fused_out_pw, cudaFuncAttributeMaxDynamicSharedMemorySize, SM_OPW);
    cudaFuncSetAttribute(fused_out_ln, cudaFuncAttributeMaxDynamicSharedMemorySize, SM_OLN);
    cudaFuncSetAttribute(fused_mlp_ln, cudaFuncAttributeMaxDynamicSharedMemorySize, SM_MLP);
    cudaFuncSetAttribute(mma_gemm<0>,  cudaFuncAttributeMaxDynamicSharedMemorySize, SM_MMA);
    cudaFuncSetAttribute(mma_gemm<1>,  cudaFuncAttributeMaxDynamicSharedMemorySize, SM_MMA);

    const unsigned RB = (unsigned)(ROWS / 128);  // 3072

    // prep (weights -> bf16; phi/phinv/x layouts)
    conv_bf<<<12, 256>>>(qkv0w, wqkv0, 12288/4);
    conv_bf<<<8,  256>>>(out0w, wout0, 8192/4);
    conv_bf<<<12, 256>>>(qkv1w, wqkv1, 12288/4);
    conv_bf<<<8,  256>>>(out1w, wout1, 8192/4);
    conv_bf<<<4,  256>>>(pw0w,  wpw0,  4096/4);
    conv_bf<<<4,  256>>>(pw1w,  wpw1,  4096/4);
    conv_bf<<<8,  256>>>(fc1w,  wfc1,  8192/4);
    conv_bf<<<8,  256>>>(fc2w,  wfc2,  8192/4);
    {
        long total4 = (long)SWAV * NNODES * NNODES / 4;
        prep_phi<<<(unsigned)((total4 + 255) / 256), 256>>>(phi, diagw, a2);
    }
    prep_phinv<<<dim3(NNODES/32, NNODES/32, SWAV), dim3(32, 8)>>>(phinv, b2);
    prep_x<<<dim3(NNODES/32, CDIM/32, BT), dim3(32, 8)>>>(x, xt);

    // big GEMMs (cp.async pipelined)
    mma_gemm<0><<<dim3(16, 16), 256, SM_MMA>>>(a2, b2, KBIG, KBIG, KBIG, msumbf);
    mma_gemm<1><<<dim3(NXK/128, 16), 256, SM_MMA>>>(msumbf, xt, NNODES, NNODES, NNODES, xk);

    // layer 0
    rg_qkv_f32<<<RB, 256, SM_QKV>>>(x, wqkv0, nullptr, qkvb);
    attn_fused<<<1280, 256>>>(qkvb, catb);
    rg_pw_f32<<<RB, 256, SM_PW>>>(x, wpw0, pw0b, p0);
    fused_out_pw<<<RB, 256, SM_OPW>>>(catb, wout0, out0b, wpw1, pw1b, att0, p1);

    // layer 1
    rg_qkv_bf<<<RB, 256, SM_QKV>>>(xk, wqkv1, nullptr, qkvb);
    attn_fused<<<1280, 256>>>(qkvb, catb);
    fused_out_ln<<<RB, 256, SM_OLN>>>(catb, wout1, out1b, x, att0, p0, p1, ln1g, ln1b, yb);

    // MLP + LN2
    fused_mlp_ln<<<RB, 256, SM_MLP>>>(yb, wfc1, fc1b, wfc2, fc2b, ln2g, ln2b, (float*)d_out);
}

// round 9
// speedup vs baseline: 4.6586x; 1.1182x over previous
#include <cuda_runtime.h>
#include <cuda_bf16.h>
#include <math.h>
#include <stdint.h>

#define BB 8
#define TT 24
#define NNODES 2048
#define CDIM 64
#define HH 8
#define HDIM 8
#define SWAV 4
#define BT (BB*TT)              // 192
#define ROWS ((long)BT*NNODES)  // 393216
#define KBIG (SWAV*NNODES)      // 8192
#define NXK (BT*CDIM)           // 12288

typedef unsigned short u16;

// ---------------- scratch ----------------
__device__ u16 g_a2[(long)NNODES*KBIG];
__device__ u16 g_b2[(long)NNODES*KBIG];
__device__ u16 g_msumbf[(long)NNODES*NNODES];
__device__ u16 g_xt[(long)NXK*NNODES];
__device__ u16 g_qkv [ROWS*3*CDIM];
__device__ u16 g_cat [ROWS*2*CDIM];
__device__ u16 g_att0[ROWS*CDIM];
__device__ u16 g_p0  [ROWS*CDIM];
__device__ u16 g_p1  [ROWS*CDIM];
__device__ float g_y [ROWS*CDIM];
__device__ u16 g_wqkv0[3*CDIM*CDIM];
__device__ u16 g_wout0[CDIM*2*CDIM];
__device__ u16 g_wqkv1[3*CDIM*CDIM];
__device__ u16 g_wout1[CDIM*2*CDIM];
__device__ u16 g_wpw0 [CDIM*CDIM];
__device__ u16 g_wpw1 [CDIM*CDIM];
__device__ u16 g_wfc1 [2*CDIM*CDIM];
__device__ u16 g_wfc2 [CDIM*2*CDIM];

__device__ __forceinline__ uint32_t smem_u32(const void* p){
    uint32_t a;
    asm("{ .reg .u64 t; cvta.to.shared.u64 t, %1; cvt.u32.u64 %0, t; }" : "=r"(a) : "l"(p));
    return a;
}
__device__ __forceinline__ u16 f2bf(float v){
    __nv_bfloat16 h = __float2bfloat16(v);
    return *(u16*)&h;
}
__device__ __forceinline__ void ld8bf(float* f, const u16* p){
    uint4 u = *(const uint4*)p;
    const __nv_bfloat162* h = (const __nv_bfloat162*)&u;
#pragma unroll
    for (int i = 0; i < 4; i++) { float2 t = __bfloat1622float2(h[i]); f[2*i] = t.x; f[2*i+1] = t.y; }
}
__device__ __forceinline__ void st8bf(u16* p, const float* f){
    __nv_bfloat162 h[4];
#pragma unroll
    for (int i = 0; i < 4; i++) h[i] = __floats2bfloat162_rn(f[2*i], f[2*i+1]);
    *(uint4*)p = *(uint4*)h;
}

#define LDSM4(r, addr) \
    asm volatile("ldmatrix.sync.aligned.m8n8.x4.shared.b16 {%0,%1,%2,%3}, [%4];" \
        : "=r"((r)[0]), "=r"((r)[1]), "=r"((r)[2]), "=r"((r)[3]) : "r"(addr))

#define MMA16816(c, a, b0, b1) \
    asm volatile("mma.sync.aligned.m16n8k16.row.col.f32.bf16.bf16.f32 " \
        "{%0,%1,%2,%3}, {%4,%5,%6,%7}, {%8,%9}, {%0,%1,%2,%3};" \
        : "+f"((c)[0]), "+f"((c)[1]), "+f"((c)[2]), "+f"((c)[3]) \
        : "r"((a)[0]), "r"((a)[1]), "r"((a)[2]), "r"((a)[3]), "r"(b0), "r"(b1))

#define CP16(s, g) \
    asm volatile("cp.async.cg.shared.global [%0], [%1], 16;" :: "r"(s), "l"(g))
#define CPCOMMIT() asm volatile("cp.async.commit_group;" ::: "memory")
#define CPWAIT1()  asm volatile("cp.async.wait_group 1;" ::: "memory")
#define CPWAIT0()  asm volatile("cp.async.wait_group 0;" ::: "memory")

// generic smem-resident MMA stage: acc[mt*NF+nf] += Atile(128xKT) * Btile(NTxKT)^T
template<int NT, int KT, int SXA, int SXB>
__device__ __forceinline__ void mma_stage(uint32_t sa, uint32_t sbm, int lane,
                                          int warp_m, int warp_n, float (*acc)[4])
{
    constexpr int NF = NT/16;
    const uint32_t aoff = sa + (uint32_t)(warp_m*32 + (lane & 15))*SXA + (uint32_t)(lane >> 4)*16;
    const uint32_t boff = sbm + (uint32_t)(warp_n*(NT/2) + ((lane >> 4) << 3) + (lane & 7))*SXB
                        + (uint32_t)((lane >> 3) & 1)*16;
#pragma unroll
    for (int k16 = 0; k16 < KT/16; k16++) {
        uint32_t a[2][4], b[NF/2][4];
#pragma unroll
        for (int mt = 0; mt < 2; mt++)
            LDSM4(a[mt], aoff + mt*16*SXA + k16*32);
#pragma unroll
        for (int nf2 = 0; nf2 < NF/2; nf2++)
            LDSM4(b[nf2], boff + nf2*16*SXB + k16*32);
#pragma unroll
        for (int mt = 0; mt < 2; mt++)
#pragma unroll
            for (int nf = 0; nf < NF; nf++) {
                const int nf2 = nf >> 1, hi = (nf & 1) * 2;
                MMA16816(acc[mt*NF+nf], a[mt], b[nf2][hi], b[nf2][hi+1]);
            }
    }
}

// ================ big mma GEMM with 3-stage cp.async pipeline ================
// D[m,n] = sum_k A[m,k]*B[n,k]. Tile 128x128, K-tile 32.
// EPI 0: bf16 out row-major ld 2048 [Msum]
// EPI 1: fused qkv1 epilogue: the 128x128 tile = 2 full (bt,node) row panels of
//        64 channels; store tile bf16 to smem, GEMM with wqkv1 (192x64), write qkv.
template<int EPI>
__global__ __launch_bounds__(256, 2)
void mma_gemm(const u16* __restrict__ A, const u16* __restrict__ B,
              int K, int ldA, int ldB, void* __restrict__ Cout,
              const u16* __restrict__ wq, u16* __restrict__ qkvout)
{
    extern __shared__ __align__(16) char smem[];
    const int tid  = threadIdx.x;
    const int lane = tid & 31;
    const int w    = tid >> 5;
    const int warp_m = w & 3;
    const int warp_n = w >> 2;
    const long m0 = (long)blockIdx.y * 128;
    const long n0 = (long)blockIdx.x * 128;
    const u16* Ab = A + m0 * ldA;
    const u16* Bb = B + n0 * ldB;

    const uint32_t sbase = smem_u32(smem);
    const int r0w = tid >> 2;   // 0..63
    const int kc  = tid & 3;

    const uint32_t aoff = (uint32_t)(warp_m*32 + (lane & 15))*80 + (uint32_t)(lane >> 4)*16;
    const uint32_t boff = (uint32_t)(warp_n*64 + ((lane >> 4) << 3) + (lane & 7))*80
                        + (uint32_t)((lane >> 3) & 1)*16 + 10240;

    float acc[2][8][4];
#pragma unroll
    for (int mt = 0; mt < 2; mt++)
#pragma unroll
        for (int nt = 0; nt < 8; nt++)
#pragma unroll
            for (int i = 0; i < 4; i++) acc[mt][nt][i] = 0.f;

    const int T = K >> 5;
#pragma unroll
    for (int s = 0; s < 2; s++) {
        const int kt = s << 5;
#pragma unroll
        for (int i = 0; i < 2; i++) {
            int row = r0w + i*64;
            uint32_t sA = sbase + (uint32_t)s*20480 + row*80 + kc*16;
            CP16(sA,         Ab + (long)row*ldA + kt + kc*8);
            CP16(sA + 10240, Bb + (long)row*ldB + kt + kc*8);
        }
        CPCOMMIT();
    }

    for (int t = 0; t < T; t++) {
        CPWAIT1();
        __syncthreads();
        if (t + 2 < T) {
            const int kt = (t + 2) << 5;
            const int buf = (t + 2) % 3;
#pragma unroll
            for (int i = 0; i < 2; i++) {
                int row = r0w + i*64;
                uint32_t sA = sbase + (uint32_t)buf*20480 + row*80 + kc*16;
                CP16(sA,         Ab + (long)row*ldA + kt + kc*8);
                CP16(sA + 10240, Bb + (long)row*ldB + kt + kc*8);
            }
        }
        CPCOMMIT();
        const uint32_t sA = sbase + (uint32_t)(t % 3)*20480;
#pragma unroll
        for (int k16 = 0; k16 < 2; k16++) {
            uint32_t a[2][4], b[4][4];
#pragma unroll
            for (int mt = 0; mt < 2; mt++)
                LDSM4(a[mt], sA + aoff + mt*1280 + k16*32);
#pragma unroll
            for (int nt2 = 0; nt2 < 4; nt2++)
                LDSM4(b[nt2], sA + boff + nt2*1280 + k16*32);
#pragma unroll
            for (int mt = 0; mt < 2; mt++)
#pragma unroll
                for (int nt = 0; nt < 8; nt++) {
                    const int nt2 = nt >> 1, hi = (nt & 1) * 2;
                    MMA16816(acc[mt][nt], a[mt], b[nt2][hi], b[nt2][hi+1]);
                }
        }
    }

    const int group = lane >> 2, tig = lane & 3;
    if (EPI == 0) {
        u16* C = (u16*)Cout;
#pragma unroll
        for (int mt = 0; mt < 2; mt++) {
            long rbase = m0 + warp_m*32 + mt*16;
#pragma unroll
            for (int nt = 0; nt < 8; nt++) {
                long col = n0 + warp_n*64 + nt*8 + tig*2;
                __nv_bfloat162 h0 = __floats2bfloat162_rn(acc[mt][nt][0], acc[mt][nt][1]);
                __nv_bfloat162 h1 = __floats2bfloat162_rn(acc[mt][nt][2], acc[mt][nt][3]);
                *(uint32_t*)(C + (rbase + group)*2048 + col)     = *(uint32_t*)&h0;
                *(uint32_t*)(C + (rbase + 8 + group)*2048 + col) = *(uint32_t*)&h1;
            }
        }
    } else {
        // ---- fused qkv1 epilogue ----
        CPWAIT0();
        __syncthreads();   // all warps done with pipeline smem
        char* As = smem;            // x_k tile: 256 rows (2 bt x 128 nodes) x 144B
        char* Wq = smem + 256*144;  // 192 x 144B
        // store acc -> As (bf16), same rounding as old global xk path
#pragma unroll
        for (int mt = 0; mt < 2; mt++) {
            int rl = warp_m*32 + mt*16 + group;
            int arow = warp_n*128 + rl;   // warp_n == bt_local
#pragma unroll
            for (int nt = 0; nt < 8; nt++) {
                int cin = nt*8 + tig*2;
                __nv_bfloat162 h0 = __floats2bfloat162_rn(acc[mt][nt][0], acc[mt][nt][1]);
                __nv_bfloat162 h1 = __floats2bfloat162_rn(acc[mt][nt][2], acc[mt][nt][3]);
                *(uint32_t*)(As + arow*144 + cin*2)     = *(uint32_t*)&h0;
                *(uint32_t*)(As + (arow+8)*144 + cin*2) = *(uint32_t*)&h1;
            }
        }
        // load wqkv1 (192 rows x 64 bf16)
        for (int l = tid; l < 192*8; l += 256) {
            int row = l >> 3, c = l & 7;
            *(uint4*)(Wq + row*144 + c*16) = *(const uint4*)(wq + (long)row*64 + c*8);
        }
        __syncthreads();

        const uint32_t wsb = sbase + 256u*144u;
#pragma unroll
        for (int h = 0; h < 2; h++) {
            float acc2[24][4];
#pragma unroll
            for (int i = 0; i < 24; i++)
#pragma unroll
                for (int j = 0; j < 4; j++) acc2[i][j] = 0.f;
            mma_stage<192, 64, 144, 144>(sbase + (uint32_t)h*128u*144u, wsb,
                                         lane, warp_m, warp_n, acc2);
            const long bt = (n0 >> 6) + h;
            u16* Q = qkvout + bt * (long)NNODES * 192;
#pragma unroll
            for (int mt = 0; mt < 2; mt++) {
                long r = m0 + warp_m*32 + mt*16 + group;
#pragma unroll
                for (int nf = 0; nf < 12; nf++) {
                    int col = warp_n*96 + nf*8 + tig*2;
                    __nv_bfloat162 h0 = __floats2bfloat162_rn(acc2[mt*12+nf][0], acc2[mt*12+nf][1]);
                    __nv_bfloat162 h1 = __floats2bfloat162_rn(acc2[mt*12+nf][2], acc2[mt*12+nf][3]);
                    *(uint32_t*)(Q + r*192 + col)       = *(uint32_t*)&h0;
                    *(uint32_t*)(Q + (r + 8)*192 + col) = *(uint32_t*)&h1;
                }
            }
            __syncthreads();
        }
    }
}

// ================ fused qkv0 + pw0 from fp32 x (x loaded once) ================
__global__ __launch_bounds__(256)
void rg_qkv_pw(const float* __restrict__ x, const u16* __restrict__ wq,
               const u16* __restrict__ wp, const float* __restrict__ pb,
               u16* __restrict__ qkv, u16* __restrict__ p0)
{
    extern __shared__ __align__(16) char smem[];
    char* Xs = smem;             // 128 x 144
    char* Wq = smem + 128*144;   // 192 x 144
    char* Wp = Wq + 192*144;     // 64 x 144
    const int tid = threadIdx.x, lane = tid & 31, w = tid >> 5;
    const int warp_m = w & 3, warp_n = w >> 2;
    const long r0 = (long)blockIdx.x * 128;

    {
        const float* X = x + r0*64;
        for (int l = tid; l < 128*8; l += 256) {
            int row = l >> 3, c = l & 7;
            float4 f0 = *(const float4*)(X + (long)row*64 + c*8);
            float4 f1 = *(const float4*)(X + (long)row*64 + c*8 + 4);
            __nv_bfloat162 h[4];
            h[0] = __floats2bfloat162_rn(f0.x, f0.y);
            h[1] = __floats2bfloat162_rn(f0.z, f0.w);
            h[2] = __floats2bfloat162_rn(f1.x, f1.y);
            h[3] = __floats2bfloat162_rn(f1.z, f1.w);
            *(uint4*)(Xs + row*144 + c*16) = *(uint4*)h;
        }
        for (int l = tid; l < 192*8; l += 256) {
            int row = l >> 3, c = l & 7;
            *(uint4*)(Wq + row*144 + c*16) = *(const uint4*)(wq + (long)row*64 + c*8);
        }
        for (int l = tid; l < 64*8; l += 256) {
            int row = l >> 3, c = l & 7;
            *(uint4*)(Wp + row*144 + c*16) = *(const uint4*)(wp + (long)row*64 + c*8);
        }
    }
    __syncthreads();

    const uint32_t sb = smem_u32(smem);
    const int group = lane >> 2, tig = lane & 3;

    // stage 1: qkv (NT=192, no bias)
    {
        float acc[24][4];
#pragma unroll
        for (int i = 0; i < 24; i++)
#pragma unroll
            for (int j = 0; j < 4; j++) acc[i][j] = 0.f;
        mma_stage<192, 64, 144, 144>(sb, sb + 128u*144u, lane, warp_m, warp_n, acc);
#pragma unroll
        for (int mt = 0; mt < 2; mt++) {
            long r = r0 + warp_m*32 + mt*16 + group;
#pragma unroll
            for (int nf = 0; nf < 12; nf++) {
                int col = warp_n*96 + nf*8 + tig*2;
                __nv_bfloat162 h0 = __floats2bfloat162_rn(acc[mt*12+nf][0], acc[mt*12+nf][1]);
                __nv_bfloat162 h1 = __floats2bfloat162_rn(acc[mt*12+nf][2], acc[mt*12+nf][3]);
                *(uint32_t*)(qkv + r*192 + col)       = *(uint32_t*)&h0;
                *(uint32_t*)(qkv + (r + 8)*192 + col) = *(uint32_t*)&h1;
            }
        }
    }
    // stage 2: p0 (NT=64, bias)
    {
        float acc[8][4];
#pragma unroll
        for (int i = 0; i < 8; i++)
#pragma unroll
            for (int j = 0; j < 4; j++) acc[i][j] = 0.f;
        mma_stage<64, 64, 144, 144>(sb, sb + (128u+192u)*144u, lane, warp_m, warp_n, acc);
#pragma unroll
        for (int mt = 0; mt < 2; mt++) {
            long r = r0 + warp_m*32 + mt*16 + group;
#pragma unroll
            for (int nf = 0; nf < 4; nf++) {
                int col = warp_n*32 + nf*8 + tig*2;
                float b0 = pb[col], b1 = pb[col+1];
                __nv_bfloat162 h0 = __floats2bfloat162_rn(acc[mt*4+nf][0]+b0, acc[mt*4+nf][1]+b1);
                __nv_bfloat162 h1 = __floats2bfloat162_rn(acc[mt*4+nf][2]+b0, acc[mt*4+nf][3]+b1);
                *(uint32_t*)(p0 + r*64 + col)       = *(uint32_t*)&h0;
                *(uint32_t*)(p0 + (r + 8)*64 + col) = *(uint32_t*)&h1;
            }
        }
    }
}

// ================ fused out-proj0 + pw1 ================
__global__ __launch_bounds__(256)
void fused_out_pw(const u16* __restrict__ cat, const u16* __restrict__ w1,
                  const float* __restrict__ b1, const u16* __restrict__ w2,
                  const float* __restrict__ b2, u16* __restrict__ att0,
                  u16* __restrict__ p1)
{
    constexpr int SX1 = 272;
    constexpr int SX2 = 144;
    extern __shared__ __align__(16) char smem[];
    char* Xs = smem;
    char* W1 = Xs + 128*SX1;
    char* As = W1 + 64*SX1;
    char* W2 = As + 128*SX2;
    const int tid = threadIdx.x, lane = tid & 31, w = tid >> 5;
    const int warp_m = w & 3, warp_n = w >> 2;
    const long r0 = (long)blockIdx.x * 128;

    {
        const u16* X = cat + r0*128;
        for (int l = tid; l < 128*16; l += 256) {
            int row = l >> 4, c = l & 15;
            *(uint4*)(Xs + row*SX1 + c*16) = *(const uint4*)(X + (long)row*128 + c*8);
        }
        for (int l = tid; l < 64*16; l += 256) {
            int row = l >> 4, c = l & 15;
            *(uint4*)(W1 + row*SX1 + c*16) = *(const uint4*)(w1 + (long)row*128 + c*8);
        }
        for (int l = tid; l < 64*8; l += 256) {
            int row = l >> 3, c = l & 7;
            *(uint4*)(W2 + row*SX2 + c*16) = *(const uint4*)(w2 + (long)row*64 + c*8);
        }
    }
    __syncthreads();

    float acc[8][4];
#pragma unroll
    for (int i = 0; i < 8; i++)
#pragma unroll
        for (int j = 0; j < 4; j++) acc[i][j] = 0.f;
    const uint32_t sb = smem_u32(smem);
    mma_stage<64, 128, SX1, SX1>(sb, sb + 128u*SX1, lane, warp_m, warp_n, acc);

    const int group = lane >> 2, tig = lane & 3;
    const uint32_t asb = sb + 128u*SX1 + 64u*SX1;
#pragma unroll
    for (int mt = 0; mt < 2; mt++) {
        int rl = warp_m*32 + mt*16 + group;
#pragma unroll
        for (int nf = 0; nf < 4; nf++) {
            int col = warp_n*32 + nf*8 + tig*2;
            float b0 = b1[col], bb1 = b1[col+1];
            __nv_bfloat162 h0 = __floats2bfloat162_rn(acc[mt*4+nf][0]+b0, acc[mt*4+nf][1]+bb1);
            __nv_bfloat162 h1 = __floats2bfloat162_rn(acc[mt*4+nf][2]+b0, acc[mt*4+nf][3]+bb1);
            *(uint32_t*)(As + rl*SX2 + col*2)       = *(uint32_t*)&h0;
            *(uint32_t*)(As + (rl+8)*SX2 + col*2)   = *(uint32_t*)&h1;
            *(uint32_t*)(att0 + (r0+rl)*64 + col)   = *(uint32_t*)&h0;
            *(uint32_t*)(att0 + (r0+rl+8)*64 + col) = *(uint32_t*)&h1;
        }
    }
    __syncthreads();

    float acc2[8][4];
#pragma unroll
    for (int i = 0; i < 8; i++)
#pragma unroll
        for (int j = 0; j < 4; j++) acc2[i][j] = 0.f;
    mma_stage<64, 64, SX2, SX2>(asb, asb + 128u*SX2, lane, warp_m, warp_n, acc2);

#pragma unroll
    for (int mt = 0; mt < 2; mt++) {
        long r = r0 + warp_m*32 + mt*16 + group;
#pragma unroll
        for (int nf = 0; nf < 4; nf++) {
            int col = warp_n*32 + nf*8 + tig*2;
            float b0 = b2[col], bb1 = b2[col+1];
            __nv_bfloat162 h0 = __floats2bfloat162_rn(acc2[mt*4+nf][0]+b0, acc2[mt*4+nf][1]+bb1);
            __nv_bfloat162 h1 = __floats2bfloat162_rn(acc2[mt*4+nf][2]+b0, acc2[mt*4+nf][3]+bb1);
            *(uint32_t*)(p1 + r*64 + col)     = *(uint32_t*)&h0;
            *(uint32_t*)(p1 + (r+8)*64 + col) = *(uint32_t*)&h1;
        }
    }
}

// ================ fused out-proj1 + x_glo + LN1 ================
__global__ __launch_bounds__(256)
void fused_out_ln(const u16* __restrict__ cat, const u16* __restrict__ w1,
                  const float* __restrict__ b1, const float* __restrict__ x,
                  const u16* __restrict__ att0, const u16* __restrict__ p0,
                  const u16* __restrict__ p1, const float* __restrict__ g,
                  const float* __restrict__ be, float* __restrict__ y)
{
    constexpr int SX1 = 272;
    constexpr int SX2 = 144;
    extern __shared__ __align__(16) char smem[];
    char* Xs = smem;
    char* W1 = Xs + 128*SX1;
    char* As = W1 + 64*SX1;
    const int tid = threadIdx.x, lane = tid & 31, w = tid >> 5;
    const int warp_m = w & 3, warp_n = w >> 2;
    const long r0 = (long)blockIdx.x * 128;

    {
        const u16* X = cat + r0*128;
        for (int l = tid; l < 128*16; l += 256) {
            int row = l >> 4, c = l & 15;
            *(uint4*)(Xs + row*SX1 + c*16) = *(const uint4*)(X + (long)row*128 + c*8);
        }
        for (int l = tid; l < 64*16; l += 256) {
            int row = l >> 4, c = l & 15;
            *(uint4*)(W1 + row*SX1 + c*16) = *(const uint4*)(w1 + (long)row*128 + c*8);
        }
    }
    __syncthreads();

    float acc[8][4];
#pragma unroll
    for (int i = 0; i < 8; i++)
#pragma unroll
        for (int j = 0; j < 4; j++) acc[i][j] = 0.f;
    const uint32_t sb = smem_u32(smem);
    mma_stage<64, 128, SX1, SX1>(sb, sb + 128u*SX1, lane, warp_m, warp_n, acc);

    const int group = lane >> 2, tig = lane & 3;
#pragma unroll
    for (int mt = 0; mt < 2; mt++) {
        int rl = warp_m*32 + mt*16 + group;
#pragma unroll
        for (int nf = 0; nf < 4; nf++) {
            int col = warp_n*32 + nf*8 + tig*2;
            float b0 = b1[col], bb1 = b1[col+1];
            __nv_bfloat162 h0 = __floats2bfloat162_rn(acc[mt*4+nf][0]+b0, acc[mt*4+nf][1]+bb1);
            __nv_bfloat162 h1 = __floats2bfloat162_rn(acc[mt*4+nf][2]+b0, acc[mt*4+nf][3]+bb1);
            *(uint32_t*)(As + rl*SX2 + col*2)     = *(uint32_t*)&h0;
            *(uint32_t*)(As + (rl+8)*SX2 + col*2) = *(uint32_t*)&h1;
        }
    }
    __syncthreads();

    const int c = 2 * lane;
    for (int i = 0; i < 16; i++) {
        int rl = w*16 + i;
        long base = (r0 + rl) * 64;
        float2 xv  = *(const float2*)(x + base + c);
        float2 a0v = __bfloat1622float2(*(const __nv_bfloat162*)(att0 + base + c));
        float2 p0v = __bfloat1622float2(*(const __nv_bfloat162*)(p0 + base + c));
        float2 p1v = __bfloat1622float2(*(const __nv_bfloat162*)(p1 + base + c));
        float2 a1v = __bfloat1622float2(*(const __nv_bfloat162*)(As + rl*SX2 + c*2));
        float v0 = 2.f * (xv.x + a0v.x*p0v.x + a1v.x*p1v.x*0.01f);
        float v1 = 2.f * (xv.y + a0v.y*p0v.y + a1v.y*p1v.y*0.01f);
        float s = v0 + v1;
#pragma unroll
        for (int o = 16; o; o >>= 1) s += __shfl_xor_sync(0xffffffffu, s, o);
        float mean = s * (1.f / 64.f);
        float d0 = v0 - mean, d1 = v1 - mean;
        float vs = d0 * d0 + d1 * d1;
#pragma unroll
        for (int o = 16; o; o >>= 1) vs += __shfl_xor_sync(0xffffffffu, vs, o);
        float r = rsqrtf(vs * (1.f / 64.f) + 1e-5f);
        *(float2*)(y + base + c) = make_float2(d0*r*g[c] + be[c], d1*r*g[c+1] + be[c+1]);
    }
}

// ================ fused fc1 + relu + fc2 + residual + LN2 ================
__global__ __launch_bounds__(256)
void fused_mlp_ln(const float* __restrict__ y, const u16* __restrict__ w1,
                  const float* __restrict__ b1, const u16* __restrict__ w2,
                  const float* __restrict__ b2, const float* __restrict__ g,
                  const float* __restrict__ be, float* __restrict__ out)
{
    constexpr int SXY = 144;
    constexpr int SXH = 272;
    extern __shared__ __align__(16) char smem[];
    char* Ys = smem;
    char* W1 = Ys + 128*SXY;
    char* Hs = W1 + 128*SXY;
    char* W2 = Hs + 128*SXH;
    const int tid = threadIdx.x, lane = tid & 31, w = tid >> 5;
    const int warp_m = w & 3, warp_n = w >> 2;
    const long r0 = (long)blockIdx.x * 128;

    {
        const float* Y = y + r0*64;
        for (int l = tid; l < 128*8; l += 256) {
            int row = l >> 3, c = l & 7;
            float4 f0 = *(const float4*)(Y + (long)row*64 + c*8);
            float4 f1 = *(const float4*)(Y + (long)row*64 + c*8 + 4);
            __nv_bfloat162 h[4];
            h[0] = __floats2bfloat162_rn(f0.x, f0.y);
            h[1] = __floats2bfloat162_rn(f0.z, f0.w);
            h[2] = __floats2bfloat162_rn(f1.x, f1.y);
            h[3] = __floats2bfloat162_rn(f1.z, f1.w);
            *(uint4*)(Ys + row*SXY + c*16) = *(uint4*)h;
        }
        for (int l = tid; l < 128*8; l += 256) {
            int row = l >> 3, c = l & 7;
            *(uint4*)(W1 + row*SXY + c*16) = *(const uint4*)(w1 + (long)row*64 + c*8);
        }
        for (int l = tid; l < 64*16; l += 256) {
            int row = l >> 4, c = l & 15;
            *(uint4*)(W2 + row*SXH + c*16) = *(const uint4*)(w2 + (long)row*128 + c*8);
        }
    }
    __syncthreads();

    float acc[16][4];
#pragma unroll
    for (int i = 0; i < 16; i++)
#pragma unroll
        for (int j = 0; j < 4; j++) acc[i][j] = 0.f;
    const uint32_t sb = smem_u32(smem);
    mma_stage<128, 64, SXY, SXY>(sb, sb + 128u*SXY, lane, warp_m, warp_n, acc);

    const int group = lane >> 2, tig = lane & 3;
#pragma unroll
    for (int mt = 0; mt < 2; mt++) {
        int rl = warp_m*32 + mt*16 + group;
#pragma unroll
        for (int nf = 0; nf < 8; nf++) {
            int col = warp_n*64 + nf*8 + tig*2;
            float b0 = b1[col], bb1 = b1[col+1];
            float v00 = fmaxf(acc[mt*8+nf][0]+b0, 0.f), v01 = fmaxf(acc[mt*8+nf][1]+bb1, 0.f);
            float v10 = fmaxf(acc[mt*8+nf][2]+b0, 0.f), v11 = fmaxf(acc[mt*8+nf][3]+bb1, 0.f);
            __nv_bfloat162 h0 = __floats2bfloat162_rn(v00, v01);
            __nv_bfloat162 h1 = __floats2bfloat162_rn(v10, v11);
            *(uint32_t*)(Hs + rl*SXH + col*2)     = *(uint32_t*)&h0;
            *(uint32_t*)(Hs + (rl+8)*SXH + col*2) = *(uint32_t*)&h1;
        }
    }
    __syncthreads();

    float acc2[8][4];
#pragma unroll
    for (int i = 0; i < 8; i++)
#pragma unroll
        for (int j = 0; j < 4; j++) acc2[i][j] = 0.f;
    const uint32_t hsb = sb + 128u*SXY + 128u*SXY;
    mma_stage<64, 128, SXH, SXH>(hsb, hsb + 128u*SXH, lane, warp_m, warp_n, acc2);

#pragma unroll
    for (int mt = 0; mt < 2; mt++) {
        int rl = warp_m*32 + mt*16 + group;
#pragma unroll
        for (int nf = 0; nf < 4; nf++) {
            int col = warp_n*32 + nf*8 + tig*2;
            float b0 = b2[col], bb1 = b2[col+1];
            __nv_bfloat162 h0 = __floats2bfloat162_rn(acc2[mt*4+nf][0]+b0, acc2[mt*4+nf][1]+bb1);
            __nv_bfloat162 h1 = __floats2bfloat162_rn(acc2[mt*4+nf][2]+b0, acc2[mt*4+nf][3]+bb1);
            *(uint32_t*)(Ys + rl*SXY + col*2)     = *(uint32_t*)&h0;
            *(uint32_t*)(Ys + (rl+8)*SXY + col*2) = *(uint32_t*)&h1;
        }
    }
    __syncthreads();

    const int c = 2 * lane;
    for (int i = 0; i < 16; i++) {
        int rl = w*16 + i;
        long base = (r0 + rl) * 64;
        float2 yv = *(const float2*)(y + base + c);
        float2 hv = __bfloat1622float2(*(const __nv_bfloat162*)(Ys + rl*SXY + c*2));
        float v0 = yv.x + hv.x;
        float v1 = yv.y + hv.y;
        float s = v0 + v1;
#pragma unroll
        for (int o = 16; o; o >>= 1) s += __shfl_xor_sync(0xffffffffu, s, o);
        float mean = s * (1.f / 64.f);
        float d0 = v0 - mean, d1 = v1 - mean;
        float vs = d0 * d0 + d1 * d1;
#pragma unroll
        for (int o = 16; o; o >>= 1) vs += __shfl_xor_sync(0xffffffffu, vs, o);
        float r = rsqrtf(vs * (1.f / 64.f) + 1e-5f);
        *(float2*)(out + base + c) = make_float2(d0*r*g[c] + be[c], d1*r*g[c+1] + be[c+1]);
    }
}

// ================ prep kernels ================
__global__ void prep_phi(const float* __restrict__ phi, const float* __restrict__ dw,
                         u16* __restrict__ A2)
{
    long idx4 = (long)blockIdx.x * blockDim.x + threadIdx.x;
    long total4 = (long)SWAV * NNODES * NNODES / 4;
    if (idx4 >= total4) return;
    long idx = idx4 * 4;
    int s = (int)(idx >> 22);
    int i = (int)((idx >> 11) & 2047);
    int j0 = (int)(idx & 2047);
    float4 p = *(const float4*)(phi + idx);
    float4 d = *(const float4*)(dw + (long)s * NNODES + j0);
    u16 res[4];
    res[0] = f2bf(p.x * d.x); res[1] = f2bf(p.y * d.y);
    res[2] = f2bf(p.z * d.z); res[3] = f2bf(p.w * d.w);
    *(uint2*)(A2 + (long)i * KBIG + (long)s * NNODES + j0) = *(uint2*)res;
}

__global__ void prep_phinv(const float* __restrict__ pin, u16* __restrict__ B2)
{
    __shared__ float t[32][33];
    int s = blockIdx.z;
    int j0 = blockIdx.y * 32, n0 = blockIdx.x * 32;
    int tx = threadIdx.x, ty = threadIdx.y;
#pragma unroll
    for (int r = 0; r < 4; r++)
        t[ty + r*8][tx] = pin[((long)s << 22) + (long)(j0 + ty + r*8) * NNODES + n0 + tx];
    __syncthreads();
#pragma unroll
    for (int r = 0; r < 4; r++)
        B2[(long)(n0 + ty + r*8) * KBIG + (long)s * NNODES + j0 + tx] = f2bf(t[tx][ty + r*8]);
}

__global__ void prep_x(const float* __restrict__ x, u16* __restrict__ XT)
{
    __shared__ float t[32][33];
    int bt = blockIdx.z;
    int j0 = blockIdx.x * 32, c0 = blockIdx.y * 32;
    int tx = threadIdx.x, ty = threadIdx.y;
#pragma unroll
    for (int r = 0; r < 4; r++)
        t[ty + r*8][tx] = x[((long)bt * NNODES + j0 + ty + r*8) * CDIM + c0 + tx];
    __syncthreads();
#pragma unroll
    for (int r = 0; r < 4; r++)
        XT[(long)(bt * 64 + c0 + ty + r*8) * NNODES + j0 + tx] = f2bf(t[tx][ty + r*8]);
}

// all 8 weight tensors -> bf16, one launch. segments in quads (float4 units).
struct ConvArgs { const float* src[8]; u16* dst[8]; };
__global__ void conv_all(ConvArgs a)
{
    int q = blockIdx.x * 256 + threadIdx.x;   // 0..16383
    const int off[9] = {0, 3072, 5120, 8192, 10240, 11264, 12288, 14336, 16384};
    if (q >= 16384) return;
    int s = 0;
#pragma unroll
    for (int i = 1; i < 8; i++) if (q >= off[i]) s = i;
    long j = (long)(q - off[s]) * 4;
    float4 f = *(const float4*)(a.src[s] + j);
    u16 r[4];
    r[0] = f2bf(f.x); r[1] = f2bf(f.y); r[2] = f2bf(f.z); r[3] = f2bf(f.w);
    *(uint2*)(a.dst[s] + j) = *(uint2*)r;
}

// ================ fused attention: spatial (0..767) + temporal (768..1279) ========
__global__ __launch_bounds__(256)
void attn_fused(const u16* __restrict__ qkv, u16* __restrict__ cat)
{
    const int bid = blockIdx.x;
    const int tid = threadIdx.x;

    if (bid < 768) {
        const int bt = bid >> 2;
        const int h  = (bid & 3) * 2 + (tid & 1);
        const int lane = tid & 31, warp = tid >> 5;
        const u16* base = qkv + (long)bt * NNODES * 192;

        float kvs[HDIM][HDIM], ksum[HDIM];
#pragma unroll
        for (int m = 0; m < HDIM; m++) {
            ksum[m] = 0.f;
#pragma unroll
            for (int d = 0; d < HDIM; d++) kvs[m][d] = 0.f;
        }

        for (int n = tid >> 1; n < NNODES; n += 128) {
            float kk[HDIM], vv[HDIM];
            ld8bf(kk, base + (long)n * 192 + 64 + h * 8);
            ld8bf(vv, base + (long)n * 192 + 128 + h * 8);
            float s = 0.f;
#pragma unroll
            for (int m = 0; m < HDIM; m++) s += kk[m] * kk[m];
            float inv = 1.f / fmaxf(sqrtf(s), 1e-12f);
#pragma unroll
            for (int m = 0; m < HDIM; m++) {
                float km = kk[m] * inv;
                ksum[m] += km;
#pragma unroll
                for (int d = 0; d < HDIM; d++) kvs[m][d] = fmaf(km, vv[d], kvs[m][d]);
            }
        }

        __shared__ float red[8][2][72];
        __shared__ float fin[2][72];
#pragma unroll
        for (int m = 0; m < HDIM; m++) {
#pragma unroll
            for (int d = 0; d < HDIM; d++) {
                float v = kvs[m][d];
#pragma unroll
                for (int o = 2; o <= 16; o <<= 1) v += __shfl_xor_sync(0xffffffffu, v, o);
                if (lane < 2) red[warp][lane][m * 8 + d] = v;
            }
            float v = ksum[m];
#pragma unroll
            for (int o = 2; o <= 16; o <<= 1) v += __shfl_xor_sync(0xffffffffu, v, o);
            if (lane < 2) red[warp][lane][64 + m] = v;
        }
        __syncthreads();
        if (tid < 144) {
            int p = tid & 1, e = tid >> 1;
            float s = 0.f;
#pragma unroll
            for (int ww = 0; ww < 8; ww++) s += red[ww][p][e];
            fin[p][e] = s;
        }
        __syncthreads();

        float fkvs[HDIM][HDIM], fksum[HDIM];
        const int pp = tid & 1;
#pragma unroll
        for (int m = 0; m < HDIM; m++) {
            fksum[m] = fin[pp][64 + m];
#pragma unroll
            for (int d = 0; d < HDIM; d++) fkvs[m][d] = fin[pp][m * 8 + d];
        }

        for (int n = tid >> 1; n < NNODES; n += 128) {
            float qq[HDIM], vv[HDIM];
            ld8bf(qq, base + (long)n * 192 + h * 8);
            ld8bf(vv, base + (long)n * 192 + 128 + h * 8);
            float s = 0.f;
#pragma unroll
            for (int m = 0; m < HDIM; m++) s += qq[m] * qq[m];
            float inv = 1.f / fmaxf(sqrtf(s), 1e-12f);
            float den = (float)NNODES;
#pragma unroll
            for (int m = 0; m < HDIM; m++) { qq[m] *= inv; den = fmaf(qq[m], fksum[m], den); }
            float invden = 1.f / fmaxf(den, 1e-5f);
            float o[HDIM];
#pragma unroll
            for (int d = 0; d < HDIM; d++) {
                float num = (float)NNODES * vv[d];
#pragma unroll
                for (int m = 0; m < HDIM; m++) num = fmaf(qq[m], fkvs[m][d], num);
                o[d] = num * invden;
            }
            st8bf(cat + ((long)bt * NNODES + n) * 128 + h * 8, o);
        }
    } else {
        int t = (bid - 768) * 256 + tid;
        if (t >= BB * NNODES * HH) return;
        const int h = t & 7;
        const int n = (t >> 3) & (NNODES - 1);
        const int b = t >> 14;

        float kvs[HDIM][HDIM], ksum[HDIM];
#pragma unroll
        for (int m = 0; m < HDIM; m++) {
            ksum[m] = 0.f;
#pragma unroll
            for (int d = 0; d < HDIM; d++) kvs[m][d] = 0.f;
        }

        for (int l = 0; l < TT; l++) {
            const u16* p = qkv + (((long)(b * TT + l)) * NNODES + n) * 192;
            float kk[HDIM], vv[HDIM];
            ld8bf(kk, p + 64 + h * 8);
            ld8bf(vv, p + 128 + h * 8);
            float s = 0.f;
#pragma unroll
            for (int m = 0; m < HDIM; m++) s += kk[m] * kk[m];
            float inv = 1.f / fmaxf(sqrtf(s), 1e-12f);
#pragma unroll
            for (int m = 0; m < HDIM; m++) {
                float km = kk[m] * inv;
                ksum[m] += km;
#pragma unroll
                for (int d = 0; d < HDIM; d++) kvs[m][d] = fmaf(km, vv[d], kvs[m][d]);
            }
        }

        for (int l = 0; l < TT; l++) {
            const u16* p = qkv + (((long)(b * TT + l)) * NNODES + n) * 192;
            float qq[HDIM], vv[HDIM];
            ld8bf(qq, p + h * 8);
            ld8bf(vv, p + 128 + h * 8);
            float s = 0.f;
#pragma unroll
            for (int m = 0; m < HDIM; m++) s += qq[m] * qq[m];
            float inv = 1.f / fmaxf(sqrtf(s), 1e-12f);
            float den = (float)TT;
#pragma unroll
            for (int m = 0; m < HDIM; m++) { qq[m] *= inv; den = fmaf(qq[m], ksum[m], den); }
            float invden = 1.f / fmaxf(den, 1e-5f);
            float o[HDIM];
#pragma unroll
            for (int d = 0; d < HDIM; d++) {
                float num = (float)TT * vv[d];
#pragma unroll
                for (int m = 0; m < HDIM; m++) num = fmaf(qq[m], kvs[m][d], num);
                o[d] = num * invden;
            }
            st8bf(cat + (((long)(b * TT + l)) * NNODES + n) * 128 + 64 + h * 8, o);
        }
    }
}

// ---------------- host launcher ----------------
extern "C" void kernel_launch(void* const* d_in, const int* in_sizes, int n_in,
                              void* d_out, int out_size)
{
    const float* x     = (const float*)d_in[0];
    const float* phi   = (const float*)d_in[1];
    const float* phinv = (const float*)d_in[2];
    const float* diagw = (const float*)d_in[3];
    const float* qkv0w = (const float*)d_in[4];
    const float* out0w = (const float*)d_in[5];
    const float* out0b = (const float*)d_in[6];
    const float* qkv1w = (const float*)d_in[7];
    const float* out1w = (const float*)d_in[8];
    const float* out1b = (const float*)d_in[9];
    const float* pw0w  = (const float*)d_in[10];
    const float* pw0b  = (const float*)d_in[11];
    const float* pw1w  = (const float*)d_in[12];
    const float* pw1b  = (const float*)d_in[13];
    const float* fc1w  = (const float*)d_in[14];
    const float* fc1b  = (const float*)d_in[15];
    const float* fc2w  = (const float*)d_in[16];
    const float* fc2b  = (const float*)d_in[17];
    const float* ln1g  = (const float*)d_in[18];
    const float* ln1b  = (const float*)d_in[19];
    const float* ln2g  = (const float*)d_in[20];
    const float* ln2b  = (const float*)d_in[21];

    u16 *a2, *b2, *msumbf, *xt, *qkvb, *catb, *att0, *p0, *p1;
    u16 *wqkv0, *wout0, *wqkv1, *wout1, *wpw0, *wpw1, *wfc1, *wfc2;
    float *yb;
    cudaGetSymbolAddress((void**)&a2,     g_a2);
    cudaGetSymbolAddress((void**)&b2,     g_b2);
    cudaGetSymbolAddress((void**)&msumbf, g_msumbf);
    cudaGetSymbolAddress((void**)&xt,     g_xt);
    cudaGetSymbolAddress((void**)&qkvb,   g_qkv);
    cudaGetSymbolAddress((void**)&catb,   g_cat);
    cudaGetSymbolAddress((void**)&att0,   g_att0);
    cudaGetSymbolAddress((void**)&p0,     g_p0);
    cudaGetSymbolAddress((void**)&p1,     g_p1);
    cudaGetSymbolAddress((void**)&yb,     g_y);
    cudaGetSymbolAddress((void**)&wqkv0,  g_wqkv0);
    cudaGetSymbolAddress((void**)&wout0,  g_wout0);
    cudaGetSymbolAddress((void**)&wqkv1,  g_wqkv1);
    cudaGetSymbolAddress((void**)&wout1,  g_wout1);
    cudaGetSymbolAddress((void**)&wpw0,   g_wpw0);
    cudaGetSymbolAddress((void**)&wpw1,   g_wpw1);
    cudaGetSymbolAddress((void**)&wfc1,   g_wfc1);
    cudaGetSymbolAddress((void**)&wfc2,   g_wfc2);

    const int SM_QKVPW = 128*144 + 192*144 + 64*144;          // 55296
    const int SM_OPW  = 128*272 + 64*272 + 128*144 + 64*144;  // 79872
    const int SM_OLN  = 128*272 + 64*272 + 128*144;           // 70656
    const int SM_MLP  = 128*144 + 128*144 + 128*272 + 64*272; // 89088
    const int SM_MMA0 = 3 * 20480;                            // 61440
    const int SM_MMA1 = 256*144 + 192*144;                    // 64512 (>= 61440)
    cudaFuncSetAttribute(rg_qkv_pw,    cudaFuncAttributeMaxDynamicSharedMemorySize, SM_QKVPW);
    cudaFuncSetAttribute(fused_out_pw, cudaFuncAttributeMaxDynamicSharedMemorySize, SM_OPW);
    cudaFuncSetAttribute(fused_out_ln, cudaFuncAttributeMaxDynamicSharedMemorySize, SM_OLN);
    cudaFuncSetAttribute(fused_mlp_ln, cudaFuncAttributeMaxDynamicSharedMemorySize, SM_MLP);
    cudaFuncSetAttribute(mma_gemm<0>,  cudaFuncAttributeMaxDynamicSharedMemorySize, SM_MMA0);
    cudaFuncSetAttribute(mma_gemm<1>,  cudaFuncAttributeMaxDynamicSharedMemorySize, SM_MMA1);

    const unsigned RB = (unsigned)(ROWS / 128);  // 3072

    // prep: all weights in one launch + bf16 layouts
    ConvArgs ca;
    ca.src[0] = qkv0w; ca.dst[0] = wqkv0;
    ca.src[1] = out0w; ca.dst[1] = wout0;
    ca.src[2] = qkv1w; ca.dst[2] = wqkv1;
    ca.src[3] = out1w; ca.dst[3] = wout1;
    ca.src[4] = pw0w;  ca.dst[4] = wpw0;
    ca.src[5] = pw1w;  ca.dst[5] = wpw1;
    ca.src[6] = fc1w;  ca.dst[6] = wfc1;
    ca.src[7] = fc2w;  ca.dst[7] = wfc2;
    conv_all<<<64, 256>>>(ca);
    {
        long total4 = (long)SWAV * NNODES * NNODES / 4;
        prep_phi<<<(unsigned)((total4 + 255) / 256), 256>>>(phi, diagw, a2);
    }
    prep_phinv<<<dim3(NNODES/32, NNODES/32, SWAV), dim3(32, 8)>>>(phinv, b2);
    prep_x<<<dim3(NNODES/32, CDIM/32, BT), dim3(32, 8)>>>(x, xt);

    // Msum (2048x2048x8192)
    mma_gemm<0><<<dim3(16, 16), 256, SM_MMA0>>>(a2, b2, KBIG, KBIG, KBIG, msumbf,
                                                nullptr, nullptr);

    // layer 0: qkv0 + p0 fused; attention; out-proj0 + pw1 fused
    rg_qkv_pw<<<RB, 256, SM_QKVPW>>>(x, wqkv0, wpw0, pw0b, qkvb, p0);
    attn_fused<<<1280, 256>>>(qkvb, catb);
    fused_out_pw<<<RB, 256, SM_OPW>>>(catb, wout0, out0b, wpw1, pw1b, att0, p1);

    // x_k GEMM with fused qkv1 epilogue (writes qkvb directly; no xk buffer)
    mma_gemm<1><<<dim3(NXK/128, 16), 256, SM_MMA1>>>(msumbf, xt, NNODES, NNODES, NNODES,
                                                     nullptr, wqkv1, qkvb);

    // layer 1: attention; out-proj1 + x_glo + LN1
    attn_fused<<<1280, 256>>>(qkvb, catb);
    fused_out_ln<<<RB, 256, SM_OLN>>>(catb, wout1, out1b, x, att0, p0, p1, ln1g, ln1b, yb);

    // MLP + LN2
    fused_mlp_ln<<<RB, 256, SM_MLP>>>(yb, wfc1, fc1b, wfc2, fc2b, ln2g, ln2b, (float*)d_out);
}

// round 10
// speedup vs baseline: 4.9200x; 1.0561x over previous
#include <cuda_runtime.h>
#include <cuda_bf16.h>
#include <math.h>
#include <stdint.h>

#define BB 8
#define TT 24
#define NNODES 2048
#define CDIM 64
#define HH 8
#define HDIM 8
#define SWAV 4
#define BT (BB*TT)              // 192
#define ROWS ((long)BT*NNODES)  // 393216
#define KBIG (SWAV*NNODES)      // 8192
#define NXK (BT*CDIM)           // 12288

typedef unsigned short u16;

// ---------------- scratch ----------------
__device__ u16 g_a2[(long)NNODES*KBIG];
__device__ u16 g_b2[(long)NNODES*KBIG];
__device__ u16 g_msumbf[(long)NNODES*NNODES];
__device__ u16 g_xt[(long)NXK*NNODES];
__device__ u16 g_qkv [ROWS*3*CDIM];     // layer0 qkv
__device__ u16 g_qkv2[ROWS*3*CDIM];     // layer1 qkv (stream B)
__device__ u16 g_cat [ROWS*2*CDIM];     // layer0 cat
__device__ u16 g_cat2[ROWS*2*CDIM];     // layer1 cat (stream B)
__device__ u16 g_att0[ROWS*CDIM];
__device__ u16 g_p0  [ROWS*CDIM];
__device__ u16 g_p1  [ROWS*CDIM];
__device__ float g_y [ROWS*CDIM];
__device__ u16 g_wqkv0[3*CDIM*CDIM];
__device__ u16 g_wout0[CDIM*2*CDIM];
__device__ u16 g_wqkv1[3*CDIM*CDIM];
__device__ u16 g_wout1[CDIM*2*CDIM];
__device__ u16 g_wpw0 [CDIM*CDIM];
__device__ u16 g_wpw1 [CDIM*CDIM];
__device__ u16 g_wfc1 [2*CDIM*CDIM];
__device__ u16 g_wfc2 [CDIM*2*CDIM];

// streams/events created once at static-init time (before harness checkpoints;
// no allocation APIs used inside kernel_launch)
struct StreamsInit {
    cudaStream_t sB;
    cudaEvent_t eF, eJ;
    StreamsInit() {
        cudaStreamCreateWithFlags(&sB, cudaStreamNonBlocking);
        cudaEventCreateWithFlags(&eF, cudaEventDisableTiming);
        cudaEventCreateWithFlags(&eJ, cudaEventDisableTiming);
    }
};
static StreamsInit g_si;

__device__ __forceinline__ uint32_t smem_u32(const void* p){
    uint32_t a;
    asm("{ .reg .u64 t; cvta.to.shared.u64 t, %1; cvt.u32.u64 %0, t; }" : "=r"(a) : "l"(p));
    return a;
}
__device__ __forceinline__ u16 f2bf(float v){
    __nv_bfloat16 h = __float2bfloat16(v);
    return *(u16*)&h;
}
__device__ __forceinline__ void ld8bf(float* f, const u16* p){
    uint4 u = *(const uint4*)p;
    const __nv_bfloat162* h = (const __nv_bfloat162*)&u;
#pragma unroll
    for (int i = 0; i < 4; i++) { float2 t = __bfloat1622float2(h[i]); f[2*i] = t.x; f[2*i+1] = t.y; }
}
__device__ __forceinline__ void st8bf(u16* p, const float* f){
    __nv_bfloat162 h[4];
#pragma unroll
    for (int i = 0; i < 4; i++) h[i] = __floats2bfloat162_rn(f[2*i], f[2*i+1]);
    *(uint4*)p = *(uint4*)h;
}

#define LDSM4(r, addr) \
    asm volatile("ldmatrix.sync.aligned.m8n8.x4.shared.b16 {%0,%1,%2,%3}, [%4];" \
        : "=r"((r)[0]), "=r"((r)[1]), "=r"((r)[2]), "=r"((r)[3]) : "r"(addr))

#define MMA16816(c, a, b0, b1) \
    asm volatile("mma.sync.aligned.m16n8k16.row.col.f32.bf16.bf16.f32 " \
        "{%0,%1,%2,%3}, {%4,%5,%6,%7}, {%8,%9}, {%0,%1,%2,%3};" \
        : "+f"((c)[0]), "+f"((c)[1]), "+f"((c)[2]), "+f"((c)[3]) \
        : "r"((a)[0]), "r"((a)[1]), "r"((a)[2]), "r"((a)[3]), "r"(b0), "r"(b1))

#define CP16(s, g) \
    asm volatile("cp.async.cg.shared.global [%0], [%1], 16;" :: "r"(s), "l"(g))
#define CPCOMMIT() asm volatile("cp.async.commit_group;" ::: "memory")
#define CPWAIT1()  asm volatile("cp.async.wait_group 1;" ::: "memory")
#define CPWAIT0()  asm volatile("cp.async.wait_group 0;" ::: "memory")

template<int NT, int KT, int SXA, int SXB>
__device__ __forceinline__ void mma_stage(uint32_t sa, uint32_t sbm, int lane,
                                          int warp_m, int warp_n, float (*acc)[4])
{
    constexpr int NF = NT/16;
    const uint32_t aoff = sa + (uint32_t)(warp_m*32 + (lane & 15))*SXA + (uint32_t)(lane >> 4)*16;
    const uint32_t boff = sbm + (uint32_t)(warp_n*(NT/2) + ((lane >> 4) << 3) + (lane & 7))*SXB
                        + (uint32_t)((lane >> 3) & 1)*16;
#pragma unroll
    for (int k16 = 0; k16 < KT/16; k16++) {
        uint32_t a[2][4], b[NF/2][4];
#pragma unroll
        for (int mt = 0; mt < 2; mt++)
            LDSM4(a[mt], aoff + mt*16*SXA + k16*32);
#pragma unroll
        for (int nf2 = 0; nf2 < NF/2; nf2++)
            LDSM4(b[nf2], boff + nf2*16*SXB + k16*32);
#pragma unroll
        for (int mt = 0; mt < 2; mt++)
#pragma unroll
            for (int nf = 0; nf < NF; nf++) {
                const int nf2 = nf >> 1, hi = (nf & 1) * 2;
                MMA16816(acc[mt*NF+nf], a[mt], b[nf2][hi], b[nf2][hi+1]);
            }
    }
}

// ================ big mma GEMM with 3-stage cp.async pipeline ================
template<int EPI>
__global__ __launch_bounds__(256, 2)
void mma_gemm(const u16* __restrict__ A, const u16* __restrict__ B,
              int K, int ldA, int ldB, void* __restrict__ Cout,
              const u16* __restrict__ wq, u16* __restrict__ qkvout)
{
    extern __shared__ __align__(16) char smem[];
    const int tid  = threadIdx.x;
    const int lane = tid & 31;
    const int w    = tid >> 5;
    const int warp_m = w & 3;
    const int warp_n = w >> 2;
    const long m0 = (long)blockIdx.y * 128;
    const long n0 = (long)blockIdx.x * 128;
    const u16* Ab = A + m0 * ldA;
    const u16* Bb = B + n0 * ldB;

    const uint32_t sbase = smem_u32(smem);
    const int r0w = tid >> 2;
    const int kc  = tid & 3;

    const uint32_t aoff = (uint32_t)(warp_m*32 + (lane & 15))*80 + (uint32_t)(lane >> 4)*16;
    const uint32_t boff = (uint32_t)(warp_n*64 + ((lane >> 4) << 3) + (lane & 7))*80
                        + (uint32_t)((lane >> 3) & 1)*16 + 10240;

    float acc[2][8][4];
#pragma unroll
    for (int mt = 0; mt < 2; mt++)
#pragma unroll
        for (int nt = 0; nt < 8; nt++)
#pragma unroll
            for (int i = 0; i < 4; i++) acc[mt][nt][i] = 0.f;

    const int T = K >> 5;
#pragma unroll
    for (int s = 0; s < 2; s++) {
        const int kt = s << 5;
#pragma unroll
        for (int i = 0; i < 2; i++) {
            int row = r0w + i*64;
            uint32_t sA = sbase + (uint32_t)s*20480 + row*80 + kc*16;
            CP16(sA,         Ab + (long)row*ldA + kt + kc*8);
            CP16(sA + 10240, Bb + (long)row*ldB + kt + kc*8);
        }
        CPCOMMIT();
    }

    for (int t = 0; t < T; t++) {
        CPWAIT1();
        __syncthreads();
        if (t + 2 < T) {
            const int kt = (t + 2) << 5;
            const int buf = (t + 2) % 3;
#pragma unroll
            for (int i = 0; i < 2; i++) {
                int row = r0w + i*64;
                uint32_t sA = sbase + (uint32_t)buf*20480 + row*80 + kc*16;
                CP16(sA,         Ab + (long)row*ldA + kt + kc*8);
                CP16(sA + 10240, Bb + (long)row*ldB + kt + kc*8);
            }
        }
        CPCOMMIT();
        const uint32_t sA = sbase + (uint32_t)(t % 3)*20480;
#pragma unroll
        for (int k16 = 0; k16 < 2; k16++) {
            uint32_t a[2][4], b[4][4];
#pragma unroll
            for (int mt = 0; mt < 2; mt++)
                LDSM4(a[mt], sA + aoff + mt*1280 + k16*32);
#pragma unroll
            for (int nt2 = 0; nt2 < 4; nt2++)
                LDSM4(b[nt2], sA + boff + nt2*1280 + k16*32);
#pragma unroll
            for (int mt = 0; mt < 2; mt++)
#pragma unroll
                for (int nt = 0; nt < 8; nt++) {
                    const int nt2 = nt >> 1, hi = (nt & 1) * 2;
                    MMA16816(acc[mt][nt], a[mt], b[nt2][hi], b[nt2][hi+1]);
                }
        }
    }

    const int group = lane >> 2, tig = lane & 3;
    if (EPI == 0) {
        u16* C = (u16*)Cout;
#pragma unroll
        for (int mt = 0; mt < 2; mt++) {
            long rbase = m0 + warp_m*32 + mt*16;
#pragma unroll
            for (int nt = 0; nt < 8; nt++) {
                long col = n0 + warp_n*64 + nt*8 + tig*2;
                __nv_bfloat162 h0 = __floats2bfloat162_rn(acc[mt][nt][0], acc[mt][nt][1]);
                __nv_bfloat162 h1 = __floats2bfloat162_rn(acc[mt][nt][2], acc[mt][nt][3]);
                *(uint32_t*)(C + (rbase + group)*2048 + col)     = *(uint32_t*)&h0;
                *(uint32_t*)(C + (rbase + 8 + group)*2048 + col) = *(uint32_t*)&h1;
            }
        }
    } else {
        // fused qkv1 epilogue
        CPWAIT0();
        __syncthreads();
        char* As = smem;
        char* Wq = smem + 256*144;
#pragma unroll
        for (int mt = 0; mt < 2; mt++) {
            int rl = warp_m*32 + mt*16 + group;
            int arow = warp_n*128 + rl;
#pragma unroll
            for (int nt = 0; nt < 8; nt++) {
                int cin = nt*8 + tig*2;
                __nv_bfloat162 h0 = __floats2bfloat162_rn(acc[mt][nt][0], acc[mt][nt][1]);
                __nv_bfloat162 h1 = __floats2bfloat162_rn(acc[mt][nt][2], acc[mt][nt][3]);
                *(uint32_t*)(As + arow*144 + cin*2)     = *(uint32_t*)&h0;
                *(uint32_t*)(As + (arow+8)*144 + cin*2) = *(uint32_t*)&h1;
            }
        }
        for (int l = tid; l < 192*8; l += 256) {
            int row = l >> 3, c = l & 7;
            *(uint4*)(Wq + row*144 + c*16) = *(const uint4*)(wq + (long)row*64 + c*8);
        }
        __syncthreads();

        const uint32_t wsb = sbase + 256u*144u;
#pragma unroll
        for (int h = 0; h < 2; h++) {
            float acc2[24][4];
#pragma unroll
            for (int i = 0; i < 24; i++)
#pragma unroll
                for (int j = 0; j < 4; j++) acc2[i][j] = 0.f;
            mma_stage<192, 64, 144, 144>(sbase + (uint32_t)h*128u*144u, wsb,
                                         lane, warp_m, warp_n, acc2);
            const long bt = (n0 >> 6) + h;
            u16* Q = qkvout + bt * (long)NNODES * 192;
#pragma unroll
            for (int mt = 0; mt < 2; mt++) {
                long r = m0 + warp_m*32 + mt*16 + group;
#pragma unroll
                for (int nf = 0; nf < 12; nf++) {
                    int col = warp_n*96 + nf*8 + tig*2;
                    __nv_bfloat162 h0 = __floats2bfloat162_rn(acc2[mt*12+nf][0], acc2[mt*12+nf][1]);
                    __nv_bfloat162 h1 = __floats2bfloat162_rn(acc2[mt*12+nf][2], acc2[mt*12+nf][3]);
                    *(uint32_t*)(Q + r*192 + col)       = *(uint32_t*)&h0;
                    *(uint32_t*)(Q + (r + 8)*192 + col) = *(uint32_t*)&h1;
                }
            }
            __syncthreads();
        }
    }
}

// ================ fused qkv0 + pw0 from fp32 x ================
__global__ __launch_bounds__(256)
void rg_qkv_pw(const float* __restrict__ x, const u16* __restrict__ wq,
               const u16* __restrict__ wp, const float* __restrict__ pb,
               u16* __restrict__ qkv, u16* __restrict__ p0)
{
    extern __shared__ __align__(16) char smem[];
    char* Xs = smem;
    char* Wq = smem + 128*144;
    char* Wp = Wq + 192*144;
    const int tid = threadIdx.x, lane = tid & 31, w = tid >> 5;
    const int warp_m = w & 3, warp_n = w >> 2;
    const long r0 = (long)blockIdx.x * 128;

    {
        const float* X = x + r0*64;
        for (int l = tid; l < 128*8; l += 256) {
            int row = l >> 3, c = l & 7;
            float4 f0 = *(const float4*)(X + (long)row*64 + c*8);
            float4 f1 = *(const float4*)(X + (long)row*64 + c*8 + 4);
            __nv_bfloat162 h[4];
            h[0] = __floats2bfloat162_rn(f0.x, f0.y);
            h[1] = __floats2bfloat162_rn(f0.z, f0.w);
            h[2] = __floats2bfloat162_rn(f1.x, f1.y);
            h[3] = __floats2bfloat162_rn(f1.z, f1.w);
            *(uint4*)(Xs + row*144 + c*16) = *(uint4*)h;
        }
        for (int l = tid; l < 192*8; l += 256) {
            int row = l >> 3, c = l & 7;
            *(uint4*)(Wq + row*144 + c*16) = *(const uint4*)(wq + (long)row*64 + c*8);
        }
        for (int l = tid; l < 64*8; l += 256) {
            int row = l >> 3, c = l & 7;
            *(uint4*)(Wp + row*144 + c*16) = *(const uint4*)(wp + (long)row*64 + c*8);
        }
    }
    __syncthreads();

    const uint32_t sb = smem_u32(smem);
    const int group = lane >> 2, tig = lane & 3;

    {
        float acc[24][4];
#pragma unroll
        for (int i = 0; i < 24; i++)
#pragma unroll
            for (int j = 0; j < 4; j++) acc[i][j] = 0.f;
        mma_stage<192, 64, 144, 144>(sb, sb + 128u*144u, lane, warp_m, warp_n, acc);
#pragma unroll
        for (int mt = 0; mt < 2; mt++) {
            long r = r0 + warp_m*32 + mt*16 + group;
#pragma unroll
            for (int nf = 0; nf < 12; nf++) {
                int col = warp_n*96 + nf*8 + tig*2;
                __nv_bfloat162 h0 = __floats2bfloat162_rn(acc[mt*12+nf][0], acc[mt*12+nf][1]);
                __nv_bfloat162 h1 = __floats2bfloat162_rn(acc[mt*12+nf][2], acc[mt*12+nf][3]);
                *(uint32_t*)(qkv + r*192 + col)       = *(uint32_t*)&h0;
                *(uint32_t*)(qkv + (r + 8)*192 + col) = *(uint32_t*)&h1;
            }
        }
    }
    {
        float acc[8][4];
#pragma unroll
        for (int i = 0; i < 8; i++)
#pragma unroll
            for (int j = 0; j < 4; j++) acc[i][j] = 0.f;
        mma_stage<64, 64, 144, 144>(sb, sb + (128u+192u)*144u, lane, warp_m, warp_n, acc);
#pragma unroll
        for (int mt = 0; mt < 2; mt++) {
            long r = r0 + warp_m*32 + mt*16 + group;
#pragma unroll
            for (int nf = 0; nf < 4; nf++) {
                int col = warp_n*32 + nf*8 + tig*2;
                float b0 = pb[col], b1 = pb[col+1];
                __nv_bfloat162 h0 = __floats2bfloat162_rn(acc[mt*4+nf][0]+b0, acc[mt*4+nf][1]+b1);
                __nv_bfloat162 h1 = __floats2bfloat162_rn(acc[mt*4+nf][2]+b0, acc[mt*4+nf][3]+b1);
                *(uint32_t*)(p0 + r*64 + col)       = *(uint32_t*)&h0;
                *(uint32_t*)(p0 + (r + 8)*64 + col) = *(uint32_t*)&h1;
            }
        }
    }
}

// ================ fused out-proj0 + pw1 ================
__global__ __launch_bounds__(256)
void fused_out_pw(const u16* __restrict__ cat, const u16* __restrict__ w1,
                  const float* __restrict__ b1, const u16* __restrict__ w2,
                  const float* __restrict__ b2, u16* __restrict__ att0,
                  u16* __restrict__ p1)
{
    constexpr int SX1 = 272;
    constexpr int SX2 = 144;
    extern __shared__ __align__(16) char smem[];
    char* Xs = smem;
    char* W1 = Xs + 128*SX1;
    char* As = W1 + 64*SX1;
    char* W2 = As + 128*SX2;
    const int tid = threadIdx.x, lane = tid & 31, w = tid >> 5;
    const int warp_m = w & 3, warp_n = w >> 2;
    const long r0 = (long)blockIdx.x * 128;

    {
        const u16* X = cat + r0*128;
        for (int l = tid; l < 128*16; l += 256) {
            int row = l >> 4, c = l & 15;
            *(uint4*)(Xs + row*SX1 + c*16) = *(const uint4*)(X + (long)row*128 + c*8);
        }
        for (int l = tid; l < 64*16; l += 256) {
            int row = l >> 4, c = l & 15;
            *(uint4*)(W1 + row*SX1 + c*16) = *(const uint4*)(w1 + (long)row*128 + c*8);
        }
        for (int l = tid; l < 64*8; l += 256) {
            int row = l >> 3, c = l & 7;
            *(uint4*)(W2 + row*SX2 + c*16) = *(const uint4*)(w2 + (long)row*64 + c*8);
        }
    }
    __syncthreads();

    float acc[8][4];
#pragma unroll
    for (int i = 0; i < 8; i++)
#pragma unroll
        for (int j = 0; j < 4; j++) acc[i][j] = 0.f;
    const uint32_t sb = smem_u32(smem);
    mma_stage<64, 128, SX1, SX1>(sb, sb + 128u*SX1, lane, warp_m, warp_n, acc);

    const int group = lane >> 2, tig = lane & 3;
    const uint32_t asb = sb + 128u*SX1 + 64u*SX1;
#pragma unroll
    for (int mt = 0; mt < 2; mt++) {
        int rl = warp_m*32 + mt*16 + group;
#pragma unroll
        for (int nf = 0; nf < 4; nf++) {
            int col = warp_n*32 + nf*8 + tig*2;
            float b0 = b1[col], bb1 = b1[col+1];
            __nv_bfloat162 h0 = __floats2bfloat162_rn(acc[mt*4+nf][0]+b0, acc[mt*4+nf][1]+bb1);
            __nv_bfloat162 h1 = __floats2bfloat162_rn(acc[mt*4+nf][2]+b0, acc[mt*4+nf][3]+bb1);
            *(uint32_t*)(As + rl*SX2 + col*2)       = *(uint32_t*)&h0;
            *(uint32_t*)(As + (rl+8)*SX2 + col*2)   = *(uint32_t*)&h1;
            *(uint32_t*)(att0 + (r0+rl)*64 + col)   = *(uint32_t*)&h0;
            *(uint32_t*)(att0 + (r0+rl+8)*64 + col) = *(uint32_t*)&h1;
        }
    }
    __syncthreads();

    float acc2[8][4];
#pragma unroll
    for (int i = 0; i < 8; i++)
#pragma unroll
        for (int j = 0; j < 4; j++) acc2[i][j] = 0.f;
    mma_stage<64, 64, SX2, SX2>(asb, asb + 128u*SX2, lane, warp_m, warp_n, acc2);

#pragma unroll
    for (int mt = 0; mt < 2; mt++) {
        long r = r0 + warp_m*32 + mt*16 + group;
#pragma unroll
        for (int nf = 0; nf < 4; nf++) {
            int col = warp_n*32 + nf*8 + tig*2;
            float b0 = b2[col], bb1 = b2[col+1];
            __nv_bfloat162 h0 = __floats2bfloat162_rn(acc2[mt*4+nf][0]+b0, acc2[mt*4+nf][1]+bb1);
            __nv_bfloat162 h1 = __floats2bfloat162_rn(acc2[mt*4+nf][2]+b0, acc2[mt*4+nf][3]+bb1);
            *(uint32_t*)(p1 + r*64 + col)     = *(uint32_t*)&h0;
            *(uint32_t*)(p1 + (r+8)*64 + col) = *(uint32_t*)&h1;
        }
    }
}

// ================ fused out-proj1 + x_glo + LN1 ================
__global__ __launch_bounds__(256)
void fused_out_ln(const u16* __restrict__ cat, const u16* __restrict__ w1,
                  const float* __restrict__ b1, const float* __restrict__ x,
                  const u16* __restrict__ att0, const u16* __restrict__ p0,
                  const u16* __restrict__ p1, const float* __restrict__ g,
                  const float* __restrict__ be, float* __restrict__ y)
{
    constexpr int SX1 = 272;
    constexpr int SX2 = 144;
    extern __shared__ __align__(16) char smem[];
    char* Xs = smem;
    char* W1 = Xs + 128*SX1;
    char* As = W1 + 64*SX1;
    const int tid = threadIdx.x, lane = tid & 31, w = tid >> 5;
    const int warp_m = w & 3, warp_n = w >> 2;
    const long r0 = (long)blockIdx.x * 128;

    {
        const u16* X = cat + r0*128;
        for (int l = tid; l < 128*16; l += 256) {
            int row = l >> 4, c = l & 15;
            *(uint4*)(Xs + row*SX1 + c*16) = *(const uint4*)(X + (long)row*128 + c*8);
        }
        for (int l = tid; l < 64*16; l += 256) {
            int row = l >> 4, c = l & 15;
            *(uint4*)(W1 + row*SX1 + c*16) = *(const uint4*)(w1 + (long)row*128 + c*8);
        }
    }
    __syncthreads();

    float acc[8][4];
#pragma unroll
    for (int i = 0; i < 8; i++)
#pragma unroll
        for (int j = 0; j < 4; j++) acc[i][j] = 0.f;
    const uint32_t sb = smem_u32(smem);
    mma_stage<64, 128, SX1, SX1>(sb, sb + 128u*SX1, lane, warp_m, warp_n, acc);

    const int group = lane >> 2, tig = lane & 3;
#pragma unroll
    for (int mt = 0; mt < 2; mt++) {
        int rl = warp_m*32 + mt*16 + group;
#pragma unroll
        for (int nf = 0; nf < 4; nf++) {
            int col = warp_n*32 + nf*8 + tig*2;
            float b0 = b1[col], bb1 = b1[col+1];
            __nv_bfloat162 h0 = __floats2bfloat162_rn(acc[mt*4+nf][0]+b0, acc[mt*4+nf][1]+bb1);
            __nv_bfloat162 h1 = __floats2bfloat162_rn(acc[mt*4+nf][2]+b0, acc[mt*4+nf][3]+bb1);
            *(uint32_t*)(As + rl*SX2 + col*2)     = *(uint32_t*)&h0;
            *(uint32_t*)(As + (rl+8)*SX2 + col*2) = *(uint32_t*)&h1;
        }
    }
    __syncthreads();

    const int c = 2 * lane;
    for (int i = 0; i < 16; i++) {
        int rl = w*16 + i;
        long base = (r0 + rl) * 64;
        float2 xv  = *(const float2*)(x + base + c);
        float2 a0v = __bfloat1622float2(*(const __nv_bfloat162*)(att0 + base + c));
        float2 p0v = __bfloat1622float2(*(const __nv_bfloat162*)(p0 + base + c));
        float2 p1v = __bfloat1622float2(*(const __nv_bfloat162*)(p1 + base + c));
        float2 a1v = __bfloat1622float2(*(const __nv_bfloat162*)(As + rl*SX2 + c*2));
        float v0 = 2.f * (xv.x + a0v.x*p0v.x + a1v.x*p1v.x*0.01f);
        float v1 = 2.f * (xv.y + a0v.y*p0v.y + a1v.y*p1v.y*0.01f);
        float s = v0 + v1;
#pragma unroll
        for (int o = 16; o; o >>= 1) s += __shfl_xor_sync(0xffffffffu, s, o);
        float mean = s * (1.f / 64.f);
        float d0 = v0 - mean, d1 = v1 - mean;
        float vs = d0 * d0 + d1 * d1;
#pragma unroll
        for (int o = 16; o; o >>= 1) vs += __shfl_xor_sync(0xffffffffu, vs, o);
        float r = rsqrtf(vs * (1.f / 64.f) + 1e-5f);
        *(float2*)(y + base + c) = make_float2(d0*r*g[c] + be[c], d1*r*g[c+1] + be[c+1]);
    }
}

// ================ fused fc1 + relu + fc2 + residual + LN2 ================
__global__ __launch_bounds__(256)
void fused_mlp_ln(const float* __restrict__ y, const u16* __restrict__ w1,
                  const float* __restrict__ b1, const u16* __restrict__ w2,
                  const float* __restrict__ b2, const float* __restrict__ g,
                  const float* __restrict__ be, float* __restrict__ out)
{
    constexpr int SXY = 144;
    constexpr int SXH = 272;
    extern __shared__ __align__(16) char smem[];
    char* Ys = smem;
    char* W1 = Ys + 128*SXY;
    char* Hs = W1 + 128*SXY;
    char* W2 = Hs + 128*SXH;
    const int tid = threadIdx.x, lane = tid & 31, w = tid >> 5;
    const int warp_m = w & 3, warp_n = w >> 2;
    const long r0 = (long)blockIdx.x * 128;

    {
        const float* Y = y + r0*64;
        for (int l = tid; l < 128*8; l += 256) {
            int row = l >> 3, c = l & 7;
            float4 f0 = *(const float4*)(Y + (long)row*64 + c*8);
            float4 f1 = *(const float4*)(Y + (long)row*64 + c*8 + 4);
            __nv_bfloat162 h[4];
            h[0] = __floats2bfloat162_rn(f0.x, f0.y);
            h[1] = __floats2bfloat162_rn(f0.z, f0.w);
            h[2] = __floats2bfloat162_rn(f1.x, f1.y);
            h[3] = __floats2bfloat162_rn(f1.z, f1.w);
            *(uint4*)(Ys + row*SXY + c*16) = *(uint4*)h;
        }
        for (int l = tid; l < 128*8; l += 256) {
            int row = l >> 3, c = l & 7;
            *(uint4*)(W1 + row*SXY + c*16) = *(const uint4*)(w1 + (long)row*64 + c*8);
        }
        for (int l = tid; l < 64*16; l += 256) {
            int row = l >> 4, c = l & 15;
            *(uint4*)(W2 + row*SXH + c*16) = *(const uint4*)(w2 + (long)row*128 + c*8);
        }
    }
    __syncthreads();

    float acc[16][4];
#pragma unroll
    for (int i = 0; i < 16; i++)
#pragma unroll
        for (int j = 0; j < 4; j++) acc[i][j] = 0.f;
    const uint32_t sb = smem_u32(smem);
    mma_stage<128, 64, SXY, SXY>(sb, sb + 128u*SXY, lane, warp_m, warp_n, acc);

    const int group = lane >> 2, tig = lane & 3;
#pragma unroll
    for (int mt = 0; mt < 2; mt++) {
        int rl = warp_m*32 + mt*16 + group;
#pragma unroll
        for (int nf = 0; nf < 8; nf++) {
            int col = warp_n*64 + nf*8 + tig*2;
            float b0 = b1[col], bb1 = b1[col+1];
            float v00 = fmaxf(acc[mt*8+nf][0]+b0, 0.f), v01 = fmaxf(acc[mt*8+nf][1]+bb1, 0.f);
            float v10 = fmaxf(acc[mt*8+nf][2]+b0, 0.f), v11 = fmaxf(acc[mt*8+nf][3]+bb1, 0.f);
            __nv_bfloat162 h0 = __floats2bfloat162_rn(v00, v01);
            __nv_bfloat162 h1 = __floats2bfloat162_rn(v10, v11);
            *(uint32_t*)(Hs + rl*SXH + col*2)     = *(uint32_t*)&h0;
            *(uint32_t*)(Hs + (rl+8)*SXH + col*2) = *(uint32_t*)&h1;
        }
    }
    __syncthreads();

    float acc2[8][4];
#pragma unroll
    for (int i = 0; i < 8; i++)
#pragma unroll
        for (int j = 0; j < 4; j++) acc2[i][j] = 0.f;
    const uint32_t hsb = sb + 128u*SXY + 128u*SXY;
    mma_stage<64, 128, SXH, SXH>(hsb, hsb + 128u*SXH, lane, warp_m, warp_n, acc2);

#pragma unroll
    for (int mt = 0; mt < 2; mt++) {
        int rl = warp_m*32 + mt*16 + group;
#pragma unroll
        for (int nf = 0; nf < 4; nf++) {
            int col = warp_n*32 + nf*8 + tig*2;
            float b0 = b2[col], bb1 = b2[col+1];
            __nv_bfloat162 h0 = __floats2bfloat162_rn(acc2[mt*4+nf][0]+b0, acc2[mt*4+nf][1]+bb1);
            __nv_bfloat162 h1 = __floats2bfloat162_rn(acc2[mt*4+nf][2]+b0, acc2[mt*4+nf][3]+bb1);
            *(uint32_t*)(Ys + rl*SXY + col*2)     = *(uint32_t*)&h0;
            *(uint32_t*)(Ys + (rl+8)*SXY + col*2) = *(uint32_t*)&h1;
        }
    }
    __syncthreads();

    const int c = 2 * lane;
    for (int i = 0; i < 16; i++) {
        int rl = w*16 + i;
        long base = (r0 + rl) * 64;
        float2 yv = *(const float2*)(y + base + c);
        float2 hv = __bfloat1622float2(*(const __nv_bfloat162*)(Ys + rl*SXY + c*2));
        float v0 = yv.x + hv.x;
        float v1 = yv.y + hv.y;
        float s = v0 + v1;
#pragma unroll
        for (int o = 16; o; o >>= 1) s += __shfl_xor_sync(0xffffffffu, s, o);
        float mean = s * (1.f / 64.f);
        float d0 = v0 - mean, d1 = v1 - mean;
        float vs = d0 * d0 + d1 * d1;
#pragma unroll
        for (int o = 16; o; o >>= 1) vs += __shfl_xor_sync(0xffffffffu, vs, o);
        float r = rsqrtf(vs * (1.f / 64.f) + 1e-5f);
        *(float2*)(out + base + c) = make_float2(d0*r*g[c] + be[c], d1*r*g[c+1] + be[c+1]);
    }
}

// ================ prep kernels ================
__global__ void prep_phi(const float* __restrict__ phi, const float* __restrict__ dw,
                         u16* __restrict__ A2)
{
    long idx4 = (long)blockIdx.x * blockDim.x + threadIdx.x;
    long total4 = (long)SWAV * NNODES * NNODES / 4;
    if (idx4 >= total4) return;
    long idx = idx4 * 4;
    int s = (int)(idx >> 22);
    int i = (int)((idx >> 11) & 2047);
    int j0 = (int)(idx & 2047);
    float4 p = *(const float4*)(phi + idx);
    float4 d = *(const float4*)(dw + (long)s * NNODES + j0);
    u16 res[4];
    res[0] = f2bf(p.x * d.x); res[1] = f2bf(p.y * d.y);
    res[2] = f2bf(p.z * d.z); res[3] = f2bf(p.w * d.w);
    *(uint2*)(A2 + (long)i * KBIG + (long)s * NNODES + j0) = *(uint2*)res;
}

__global__ void prep_phinv(const float* __restrict__ pin, u16* __restrict__ B2)
{
    __shared__ float t[32][33];
    int s = blockIdx.z;
    int j0 = blockIdx.y * 32, n0 = blockIdx.x * 32;
    int tx = threadIdx.x, ty = threadIdx.y;
#pragma unroll
    for (int r = 0; r < 4; r++)
        t[ty + r*8][tx] = pin[((long)s << 22) + (long)(j0 + ty + r*8) * NNODES + n0 + tx];
    __syncthreads();
#pragma unroll
    for (int r = 0; r < 4; r++)
        B2[(long)(n0 + ty + r*8) * KBIG + (long)s * NNODES + j0 + tx] = f2bf(t[tx][ty + r*8]);
}

__global__ void prep_x(const float* __restrict__ x, u16* __restrict__ XT)
{
    __shared__ float t[32][33];
    int bt = blockIdx.z;
    int j0 = blockIdx.x * 32, c0 = blockIdx.y * 32;
    int tx = threadIdx.x, ty = threadIdx.y;
#pragma unroll
    for (int r = 0; r < 4; r++)
        t[ty + r*8][tx] = x[((long)bt * NNODES + j0 + ty + r*8) * CDIM + c0 + tx];
    __syncthreads();
#pragma unroll
    for (int r = 0; r < 4; r++)
        XT[(long)(bt * 64 + c0 + ty + r*8) * NNODES + j0 + tx] = f2bf(t[tx][ty + r*8]);
}

struct ConvArgs { const float* src[8]; u16* dst[8]; };
__global__ void conv_all(ConvArgs a)
{
    int q = blockIdx.x * 256 + threadIdx.x;
    const int off[9] = {0, 3072, 5120, 8192, 10240, 11264, 12288, 14336, 16384};
    if (q >= 16384) return;
    int s = 0;
#pragma unroll
    for (int i = 1; i < 8; i++) if (q >= off[i]) s = i;
    long j = (long)(q - off[s]) * 4;
    float4 f = *(const float4*)(a.src[s] + j);
    u16 r[4];
    r[0] = f2bf(f.x); r[1] = f2bf(f.y); r[2] = f2bf(f.z); r[3] = f2bf(f.w);
    *(uint2*)(a.dst[s] + j) = *(uint2*)r;
}

// ================ fused attention: spatial (0..767) + temporal (768..1279) ========
__global__ __launch_bounds__(256)
void attn_fused(const u16* __restrict__ qkv, u16* __restrict__ cat)
{
    const int bid = blockIdx.x;
    const int tid = threadIdx.x;

    if (bid < 768) {
        const int bt = bid >> 2;
        const int h  = (bid & 3) * 2 + (tid & 1);
        const int lane = tid & 31, warp = tid >> 5;
        const u16* base = qkv + (long)bt * NNODES * 192;

        float kvs[HDIM][HDIM], ksum[HDIM];
#pragma unroll
        for (int m = 0; m < HDIM; m++) {
            ksum[m] = 0.f;
#pragma unroll
            for (int d = 0; d < HDIM; d++) kvs[m][d] = 0.f;
        }

        for (int n = tid >> 1; n < NNODES; n += 128) {
            float kk[HDIM], vv[HDIM];
            ld8bf(kk, base + (long)n * 192 + 64 + h * 8);
            ld8bf(vv, base + (long)n * 192 + 128 + h * 8);
            float s = 0.f;
#pragma unroll
            for (int m = 0; m < HDIM; m++) s += kk[m] * kk[m];
            float inv = 1.f / fmaxf(sqrtf(s), 1e-12f);
#pragma unroll
            for (int m = 0; m < HDIM; m++) {
                float km = kk[m] * inv;
                ksum[m] += km;
#pragma unroll
                for (int d = 0; d < HDIM; d++) kvs[m][d] = fmaf(km, vv[d], kvs[m][d]);
            }
        }

        __shared__ float red[8][2][72];
        __shared__ float fin[2][72];
#pragma unroll
        for (int m = 0; m < HDIM; m++) {
#pragma unroll
            for (int d = 0; d < HDIM; d++) {
                float v = kvs[m][d];
#pragma unroll
                for (int o = 2; o <= 16; o <<= 1) v += __shfl_xor_sync(0xffffffffu, v, o);
                if (lane < 2) red[warp][lane][m * 8 + d] = v;
            }
            float v = ksum[m];
#pragma unroll
            for (int o = 2; o <= 16; o <<= 1) v += __shfl_xor_sync(0xffffffffu, v, o);
            if (lane < 2) red[warp][lane][64 + m] = v;
        }
        __syncthreads();
        if (tid < 144) {
            int p = tid & 1, e = tid >> 1;
            float s = 0.f;
#pragma unroll
            for (int ww = 0; ww < 8; ww++) s += red[ww][p][e];
            fin[p][e] = s;
        }
        __syncthreads();

        float fkvs[HDIM][HDIM], fksum[HDIM];
        const int pp = tid & 1;
#pragma unroll
        for (int m = 0; m < HDIM; m++) {
            fksum[m] = fin[pp][64 + m];
#pragma unroll
            for (int d = 0; d < HDIM; d++) fkvs[m][d] = fin[pp][m * 8 + d];
        }

        for (int n = tid >> 1; n < NNODES; n += 128) {
            float qq[HDIM], vv[HDIM];
            ld8bf(qq, base + (long)n * 192 + h * 8);
            ld8bf(vv, base + (long)n * 192 + 128 + h * 8);
            float s = 0.f;
#pragma unroll
            for (int m = 0; m < HDIM; m++) s += qq[m] * qq[m];
            float inv = 1.f / fmaxf(sqrtf(s), 1e-12f);
            float den = (float)NNODES;
#pragma unroll
            for (int m = 0; m < HDIM; m++) { qq[m] *= inv; den = fmaf(qq[m], fksum[m], den); }
            float invden = 1.f / fmaxf(den, 1e-5f);
            float o[HDIM];
#pragma unroll
            for (int d = 0; d < HDIM; d++) {
                float num = (float)NNODES * vv[d];
#pragma unroll
                for (int m = 0; m < HDIM; m++) num = fmaf(qq[m], fkvs[m][d], num);
                o[d] = num * invden;
            }
            st8bf(cat + ((long)bt * NNODES + n) * 128 + h * 8, o);
        }
    } else {
        int t = (bid - 768) * 256 + tid;
        if (t >= BB * NNODES * HH) return;
        const int h = t & 7;
        const int n = (t >> 3) & (NNODES - 1);
        const int b = t >> 14;

        float kvs[HDIM][HDIM], ksum[HDIM];
#pragma unroll
        for (int m = 0; m < HDIM; m++) {
            ksum[m] = 0.f;
#pragma unroll
            for (int d = 0; d < HDIM; d++) kvs[m][d] = 0.f;
        }

        for (int l = 0; l < TT; l++) {
            const u16* p = qkv + (((long)(b * TT + l)) * NNODES + n) * 192;
            float kk[HDIM], vv[HDIM];
            ld8bf(kk, p + 64 + h * 8);
            ld8bf(vv, p + 128 + h * 8);
            float s = 0.f;
#pragma unroll
            for (int m = 0; m < HDIM; m++) s += kk[m] * kk[m];
            float inv = 1.f / fmaxf(sqrtf(s), 1e-12f);
#pragma unroll
            for (int m = 0; m < HDIM; m++) {
                float km = kk[m] * inv;
                ksum[m] += km;
#pragma unroll
                for (int d = 0; d < HDIM; d++) kvs[m][d] = fmaf(km, vv[d], kvs[m][d]);
            }
        }

        for (int l = 0; l < TT; l++) {
            const u16* p = qkv + (((long)(b * TT + l)) * NNODES + n) * 192;
            float qq[HDIM], vv[HDIM];
            ld8bf(qq, p + h * 8);
            ld8bf(vv, p + 128 + h * 8);
            float s = 0.f;
#pragma unroll
            for (int m = 0; m < HDIM; m++) s += qq[m] * qq[m];
            float inv = 1.f / fmaxf(sqrtf(s), 1e-12f);
            float den = (float)TT;
#pragma unroll
            for (int m = 0; m < HDIM; m++) { qq[m] *= inv; den = fmaf(qq[m], ksum[m], den); }
            float invden = 1.f / fmaxf(den, 1e-5f);
            float o[HDIM];
#pragma unroll
            for (int d = 0; d < HDIM; d++) {
                float num = (float)TT * vv[d];
#pragma unroll
                for (int m = 0; m < HDIM; m++) num = fmaf(qq[m], kvs[m][d], num);
                o[d] = num * invden;
            }
            st8bf(cat + (((long)(b * TT + l)) * NNODES + n) * 128 + 64 + h * 8, o);
        }
    }
}

// ---------------- host launcher ----------------
extern "C" void kernel_launch(void* const* d_in, const int* in_sizes, int n_in,
                              void* d_out, int out_size)
{
    const float* x     = (const float*)d_in[0];
    const float* phi   = (const float*)d_in[1];
    const float* phinv = (const float*)d_in[2];
    const float* diagw = (const float*)d_in[3];
    const float* qkv0w = (const float*)d_in[4];
    const float* out0w = (const float*)d_in[5];
    const float* out0b = (const float*)d_in[6];
    const float* qkv1w = (const float*)d_in[7];
    const float* out1w = (const float*)d_in[8];
    const float* out1b = (const float*)d_in[9];
    const float* pw0w  = (const float*)d_in[10];
    const float* pw0b  = (const float*)d_in[11];
    const float* pw1w  = (const float*)d_in[12];
    const float* pw1b  = (const float*)d_in[13];
    const float* fc1w  = (const float*)d_in[14];
    const float* fc1b  = (const float*)d_in[15];
    const float* fc2w  = (const float*)d_in[16];
    const float* fc2b  = (const float*)d_in[17];
    const float* ln1g  = (const float*)d_in[18];
    const float* ln1b  = (const float*)d_in[19];
    const float* ln2g  = (const float*)d_in[20];
    const float* ln2b  = (const float*)d_in[21];

    u16 *a2, *b2, *msumbf, *xt, *qkvb, *qkvb2, *catb, *catb2, *att0, *p0, *p1;
    u16 *wqkv0, *wout0, *wqkv1, *wout1, *wpw0, *wpw1, *wfc1, *wfc2;
    float *yb;
    cudaGetSymbolAddress((void**)&a2,     g_a2);
    cudaGetSymbolAddress((void**)&b2,     g_b2);
    cudaGetSymbolAddress((void**)&msumbf, g_msumbf);
    cudaGetSymbolAddress((void**)&xt,     g_xt);
    cudaGetSymbolAddress((void**)&qkvb,   g_qkv);
    cudaGetSymbolAddress((void**)&qkvb2,  g_qkv2);
    cudaGetSymbolAddress((void**)&catb,   g_cat);
    cudaGetSymbolAddress((void**)&catb2,  g_cat2);
    cudaGetSymbolAddress((void**)&att0,   g_att0);
    cudaGetSymbolAddress((void**)&p0,     g_p0);
    cudaGetSymbolAddress((void**)&p1,     g_p1);
    cudaGetSymbolAddress((void**)&yb,     g_y);
    cudaGetSymbolAddress((void**)&wqkv0,  g_wqkv0);
    cudaGetSymbolAddress((void**)&wout0,  g_wout0);
    cudaGetSymbolAddress((void**)&wqkv1,  g_wqkv1);
    cudaGetSymbolAddress((void**)&wout1,  g_wout1);
    cudaGetSymbolAddress((void**)&wpw0,   g_wpw0);
    cudaGetSymbolAddress((void**)&wpw1,   g_wpw1);
    cudaGetSymbolAddress((void**)&wfc1,   g_wfc1);
    cudaGetSymbolAddress((void**)&wfc2,   g_wfc2);

    const int SM_QKVPW = 128*144 + 192*144 + 64*144;          // 55296
    const int SM_OPW  = 128*272 + 64*272 + 128*144 + 64*144;  // 79872
    const int SM_OLN  = 128*272 + 64*272 + 128*144;           // 70656
    const int SM_MLP  = 128*144 + 128*144 + 128*272 + 64*272; // 89088
    const int SM_MMA0 = 3 * 20480;                            // 61440
    const int SM_MMA1 = 256*144 + 192*144;                    // 64512
    cudaFuncSetAttribute(rg_qkv_pw,    cudaFuncAttributeMaxDynamicSharedMemorySize, SM_QKVPW);
    cudaFuncSetAttribute(fused_out_pw, cudaFuncAttributeMaxDynamicSharedMemorySize, SM_OPW);
    cudaFuncSetAttribute(fused_out_ln, cudaFuncAttributeMaxDynamicSharedMemorySize, SM_OLN);
    cudaFuncSetAttribute(fused_mlp_ln, cudaFuncAttributeMaxDynamicSharedMemorySize, SM_MLP);
    cudaFuncSetAttribute(mma_gemm<0>,  cudaFuncAttributeMaxDynamicSharedMemorySize, SM_MMA0);
    cudaFuncSetAttribute(mma_gemm<1>,  cudaFuncAttributeMaxDynamicSharedMemorySize, SM_MMA1);

    const unsigned RB = (unsigned)(ROWS / 128);  // 3072
    cudaStream_t sB = g_si.sB;

    // ---- pre-fork (default stream): tiny weight conversion ----
    ConvArgs ca;
    ca.src[0] = qkv0w; ca.dst[0] = wqkv0;
    ca.src[1] = out0w; ca.dst[1] = wout0;
    ca.src[2] = qkv1w; ca.dst[2] = wqkv1;
    ca.src[3] = out1w; ca.dst[3] = wout1;
    ca.src[4] = pw0w;  ca.dst[4] = wpw0;
    ca.src[5] = pw1w;  ca.dst[5] = wpw1;
    ca.src[6] = fc1w;  ca.dst[6] = wfc1;
    ca.src[7] = fc2w;  ca.dst[7] = wfc2;
    conv_all<<<64, 256>>>(ca);

    // ---- fork ----
    cudaEventRecord(g_si.eF, 0);
    cudaStreamWaitEvent(sB, g_si.eF, 0);

    // ---- stream B: wavelet chain ----
    {
        long total4 = (long)SWAV * NNODES * NNODES / 4;
        prep_phi<<<(unsigned)((total4 + 255) / 256), 256, 0, sB>>>(phi, diagw, a2);
    }
    prep_phinv<<<dim3(NNODES/32, NNODES/32, SWAV), dim3(32, 8), 0, sB>>>(phinv, b2);
    prep_x<<<dim3(NNODES/32, CDIM/32, BT), dim3(32, 8), 0, sB>>>(x, xt);
    mma_gemm<0><<<dim3(16, 16), 256, SM_MMA0, sB>>>(a2, b2, KBIG, KBIG, KBIG, msumbf,
                                                    nullptr, nullptr);
    mma_gemm<1><<<dim3(NXK/128, 16), 256, SM_MMA1, sB>>>(msumbf, xt, NNODES, NNODES, NNODES,
                                                         nullptr, wqkv1, qkvb2);
    attn_fused<<<1280, 256, 0, sB>>>(qkvb2, catb2);
    cudaEventRecord(g_si.eJ, sB);

    // ---- default stream: layer-0 chain (overlaps with stream B) ----
    rg_qkv_pw<<<RB, 256, SM_QKVPW>>>(x, wqkv0, wpw0, pw0b, qkvb, p0);
    attn_fused<<<1280, 256>>>(qkvb, catb);
    fused_out_pw<<<RB, 256, SM_OPW>>>(catb, wout0, out0b, wpw1, pw1b, att0, p1);

    // ---- join ----
    cudaStreamWaitEvent(0, g_si.eJ, 0);

    // out-proj1 + x_glo + LN1 ; then MLP + LN2
    fused_out_ln<<<RB, 256, SM_OLN>>>(catb2, wout1, out1b, x, att0, p0, p1, ln1g, ln1b, yb);
    fused_mlp_ln<<<RB, 256, SM_MLP>>>(yb, wfc1, fc1b, wfc2, fc2b, ln2g, ln2b, (float*)d_out);
}